// round 2
// baseline (speedup 1.0000x reference)
#include <cuda_runtime.h>
#include <cstdint>

#define NN 50000
#define NE 600000
#define DD 128
#define NG 64

// ---------------- scratch (static __device__, allocation-free) ----------------
static __device__ float    g_dis[5 * NN];          // rsqrt degrees: k=0..3 weighted, 4 = unweighted
static __device__ float    g_z[4 * NN * DD];       // z_k = S_k x
static __device__ float    g_H[NN * 4 * DD];       // concat relu(z_k W_k + b_k)
static __device__ float    g_M2[NN * 2 * DD];      // H @ W2
static __device__ float    g_Y2[NN * 2 * DD];      // S_u M2
static __device__ float    g_M3[NN * DD];          // relu(Y2+b2) @ W3
static __device__ float    g_Y3[NN * DD];          // S_u M3
static __device__ float    g_psum[NG * DD];
static __device__ unsigned g_pmax[NG * DD];
static __device__ float    g_pcnt[NG];

// ---------------- helpers ----------------
__device__ __forceinline__ void red_add_v4(float* p, float a, float b, float c, float d) {
    asm volatile("red.global.add.v4.f32 [%0], {%1,%2,%3,%4};"
                 :: "l"(p), "f"(a), "f"(b), "f"(c), "f"(d) : "memory");
}

__device__ __forceinline__ unsigned fenc(float f) {
    unsigned b = __float_as_uint(f);
    return (b & 0x80000000u) ? ~b : (b | 0x80000000u);
}
__device__ __forceinline__ float fdec(unsigned u) {
    return (u & 0x80000000u) ? __uint_as_float(u & 0x7fffffffu) : __uint_as_float(~u);
}

// ---------------- degree kernels ----------------
__global__ void k_deg_init(float* dis) {
    int i = blockIdx.x * blockDim.x + threadIdx.x;
    if (i < 5 * NN) dis[i] = 1.0f;  // self-loop weight 1 in every variant
}

__global__ void k_deg_edges(const int* __restrict__ ei, const float* __restrict__ ea, float* dis) {
    int e = blockIdx.x * blockDim.x + threadIdx.x;
    if (e >= NE) return;
    int d = ei[NE + e];
    float4 w = *reinterpret_cast<const float4*>(&ea[e * 4]);
    atomicAdd(&dis[0 * NN + d], w.x);
    atomicAdd(&dis[1 * NN + d], w.y);
    atomicAdd(&dis[2 * NN + d], w.z);
    atomicAdd(&dis[3 * NN + d], w.w);
    atomicAdd(&dis[4 * NN + d], 1.0f);
}

__global__ void k_rsqrt(float* dis) {
    int i = blockIdx.x * blockDim.x + threadIdx.x;
    if (i < 5 * NN) dis[i] = rsqrtf(dis[i]);
}

// ---------------- conv1 aggregation of x: z_k = S_k x ----------------
__global__ void k_z_init(const float* __restrict__ x, const float* __restrict__ dis, float* z) {
    int t = blockIdx.x * blockDim.x + threadIdx.x;   // over NN*32 float4 slots
    if (t >= NN * 32) return;
    int i = t >> 5, j = t & 31;
    float4 xv = reinterpret_cast<const float4*>(x)[i * 32 + j];
    #pragma unroll
    for (int k = 0; k < 4; k++) {
        float dk = dis[k * NN + i];
        float s = dk * dk;
        float4 o = make_float4(xv.x * s, xv.y * s, xv.z * s, xv.w * s);
        reinterpret_cast<float4*>(z)[(size_t)k * NN * 32 + i * 32 + j] = o;
    }
}

__global__ void k_z_edges(const int* __restrict__ ei, const float* __restrict__ ea,
                          const float* __restrict__ x, const float* __restrict__ dis, float* z) {
    int warp = (blockIdx.x * blockDim.x + threadIdx.x) >> 5;
    int lane = threadIdx.x & 31;
    if (warp >= NE) return;
    int s = ei[warp], d = ei[NE + warp];
    float4 w = *reinterpret_cast<const float4*>(&ea[warp * 4]);
    float n0 = dis[0 * NN + s] * w.x * dis[0 * NN + d];
    float n1 = dis[1 * NN + s] * w.y * dis[1 * NN + d];
    float n2 = dis[2 * NN + s] * w.z * dis[2 * NN + d];
    float n3 = dis[3 * NN + s] * w.w * dis[3 * NN + d];
    float4 xv = reinterpret_cast<const float4*>(x)[s * 32 + lane];
    float* p0 = &z[0 * (size_t)NN * DD + d * DD + lane * 4];
    red_add_v4(p0, n0 * xv.x, n0 * xv.y, n0 * xv.z, n0 * xv.w);
    float* p1 = &z[1 * (size_t)NN * DD + d * DD + lane * 4];
    red_add_v4(p1, n1 * xv.x, n1 * xv.y, n1 * xv.z, n1 * xv.w);
    float* p2 = &z[2 * (size_t)NN * DD + d * DD + lane * 4];
    red_add_v4(p2, n2 * xv.x, n2 * xv.y, n2 * xv.z, n2 * xv.w);
    float* p3 = &z[3 * (size_t)NN * DD + d * DD + lane * 4];
    red_add_v4(p3, n3 * xv.x, n3 * xv.y, n3 * xv.z, n3 * xv.w);
}

// ---------------- generic unweighted aggregation: Y = S_u M (F floats/row) ----------------
template<int F>
__global__ void k_agg_init(const float* __restrict__ M, const float* __restrict__ dis, float* Y) {
    int t = blockIdx.x * blockDim.x + threadIdx.x;   // over NN*(F/4)
    if (t >= NN * (F / 4)) return;
    int i = t / (F / 4), j = t % (F / 4);
    float du = dis[4 * NN + i];
    float s = du * du;
    float4 v = reinterpret_cast<const float4*>(M)[(size_t)i * (F / 4) + j];
    reinterpret_cast<float4*>(Y)[(size_t)i * (F / 4) + j] =
        make_float4(v.x * s, v.y * s, v.z * s, v.w * s);
}

template<int F>
__global__ void k_agg_edges(const int* __restrict__ ei, const float* __restrict__ M,
                            const float* __restrict__ dis, float* Y) {
    int warp = (blockIdx.x * blockDim.x + threadIdx.x) >> 5;
    int lane = threadIdx.x & 31;
    if (warp >= NE) return;
    int s = ei[warp], d = ei[NE + warp];
    float nn = dis[4 * NN + s] * dis[4 * NN + d];
    const float4* srow = reinterpret_cast<const float4*>(&M[(size_t)s * F]);
    float* drow = &Y[(size_t)d * F];
    #pragma unroll
    for (int t = 0; t < F / 128; t++) {
        int j = lane + 32 * t;
        float4 v = srow[j];
        red_add_v4(drow + j * 4, nn * v.x, nn * v.y, nn * v.z, nn * v.w);
    }
}

// ---------------- tiled fp32 GEMM: C[M,N] = op(A)[M,K] @ B[K,N] (+bias,relu) ----------------
// op(A): if Abias != null, a = relu(a + Abias[col])
#define BM 64
#define BN 64
#define BKK 16
__global__ void k_gemm(const float* __restrict__ A, int lda, const float* __restrict__ Abias,
                       const float* __restrict__ B, int ldb,
                       float* __restrict__ C, int ldc,
                       int M, int K,
                       const float* __restrict__ Cbias, int crelu) {
    __shared__ __align__(16) float As[BKK][BM];
    __shared__ __align__(16) float Bs[BKK][BN];
    int tid = threadIdx.x;
    int tx = tid & 15, ty = tid >> 4;
    int row0 = blockIdx.y * BM;
    int col0 = blockIdx.x * BN;
    float acc[4][4];
    #pragma unroll
    for (int i = 0; i < 4; i++)
        #pragma unroll
        for (int j = 0; j < 4; j++) acc[i][j] = 0.0f;

    for (int k0 = 0; k0 < K; k0 += BKK) {
        #pragma unroll
        for (int t = tid; t < BM * BKK; t += 256) {
            int r = t / BKK, c = t % BKK;
            int gr = row0 + r;
            float v = 0.0f;
            if (gr < M) {
                v = A[(size_t)gr * lda + k0 + c];
                if (Abias) v = fmaxf(v + Abias[k0 + c], 0.0f);
            }
            As[c][r] = v;
        }
        #pragma unroll
        for (int t = tid; t < BKK * BN; t += 256) {
            int r = t / BN, c = t % BN;
            Bs[r][c] = B[(size_t)(k0 + r) * ldb + col0 + c];
        }
        __syncthreads();
        #pragma unroll
        for (int kk = 0; kk < BKK; kk++) {
            float4 av = *reinterpret_cast<const float4*>(&As[kk][ty * 4]);
            float4 bv = *reinterpret_cast<const float4*>(&Bs[kk][tx * 4]);
            float a[4] = {av.x, av.y, av.z, av.w};
            float b[4] = {bv.x, bv.y, bv.z, bv.w};
            #pragma unroll
            for (int i = 0; i < 4; i++)
                #pragma unroll
                for (int j = 0; j < 4; j++) acc[i][j] += a[i] * b[j];
        }
        __syncthreads();
    }
    #pragma unroll
    for (int i = 0; i < 4; i++) {
        int r = row0 + ty * 4 + i;
        if (r >= M) continue;
        int c = col0 + tx * 4;
        float4 v = make_float4(acc[i][0], acc[i][1], acc[i][2], acc[i][3]);
        if (Cbias) {
            v.x += Cbias[c]; v.y += Cbias[c + 1]; v.z += Cbias[c + 2]; v.w += Cbias[c + 3];
        }
        if (crelu) {
            v.x = fmaxf(v.x, 0.f); v.y = fmaxf(v.y, 0.f);
            v.z = fmaxf(v.z, 0.f); v.w = fmaxf(v.w, 0.f);
        }
        *reinterpret_cast<float4*>(&C[(size_t)r * ldc + c]) = v;
    }
}

// ---------------- pooling ----------------
__global__ void k_pool_init(float* psum, unsigned* pmax, float* pcnt) {
    int i = blockIdx.x * blockDim.x + threadIdx.x;
    if (i < NG * DD) { psum[i] = 0.0f; pmax[i] = 0x007fffffu; }  // enc(-inf)
    if (i < NG) pcnt[i] = 0.0f;
}

#define POOL_CHUNK 256
__global__ void k_pool(const float* __restrict__ Y3, const float* __restrict__ b3,
                       const int* __restrict__ batch,
                       float* psum, unsigned* pmax, float* pcnt) {
    int j = threadIdx.x;  // 0..127 feature
    int i0 = blockIdx.x * POOL_CHUNK;
    int iend = min(i0 + POOL_CHUNK, NN);
    float bj = b3[j];
    int cur = -1;
    float s = 0.0f, m = __int_as_float(0xff800000), cnt = 0.0f;
    for (int i = i0; i < iend; i++) {
        int g = batch[i];
        if (g != cur) {
            if (cur >= 0) {
                atomicAdd(&psum[cur * DD + j], s);
                atomicMax(&pmax[cur * DD + j], fenc(m));
                if (j == 0) atomicAdd(&pcnt[cur], cnt);
            }
            cur = g; s = 0.0f; m = __int_as_float(0xff800000); cnt = 0.0f;
        }
        float y = Y3[(size_t)i * DD + j] + bj;
        s += y;
        m = fmaxf(m, y);
        cnt += 1.0f;
    }
    if (cur >= 0) {
        atomicAdd(&psum[cur * DD + j], s);
        atomicMax(&pmax[cur * DD + j], fenc(m));
        if (j == 0) atomicAdd(&pcnt[cur], cnt);
    }
}

// ---------------- MLP head ----------------
__global__ void k_mlp(const float* __restrict__ Wm1, const float* __restrict__ bm1,
                      const float* __restrict__ Wm2, const float* __restrict__ bm2,
                      const float* __restrict__ psum, const unsigned* __restrict__ pmax,
                      const float* __restrict__ pcnt, float* __restrict__ out) {
    int g = threadIdx.x;
    if (g >= NG) return;
    float cnt = pcnt[g];
    float inv = 1.0f / fmaxf(cnt, 1.0f);
    float hid[8];
    #pragma unroll
    for (int h = 0; h < 8; h++) hid[h] = bm1[h];
    for (int j = 0; j < DD; j++) {
        float mean = psum[g * DD + j] * inv;
        #pragma unroll
        for (int h = 0; h < 8; h++) hid[h] += mean * Wm1[j * 8 + h];
    }
    for (int j = 0; j < DD; j++) {
        float mx = (cnt > 0.0f) ? fdec(pmax[g * DD + j]) : 0.0f;
        #pragma unroll
        for (int h = 0; h < 8; h++) hid[h] += mx * Wm1[(DD + j) * 8 + h];
    }
    #pragma unroll
    for (int h = 0; h < 8; h++) hid[h] = fmaxf(hid[h], 0.0f);
    #pragma unroll
    for (int c = 0; c < 2; c++) {
        float o = bm2[c];
        #pragma unroll
        for (int h = 0; h < 8; h++) o += hid[h] * Wm2[h * 2 + c];
        out[g * 2 + c] = o;
    }
}

// ---------------- driver ----------------
extern "C" void kernel_launch(void* const* d_in, const int* in_sizes, int n_in,
                              void* d_out, int out_size) {
    const float* x     = (const float*)d_in[0];
    const int*   ei    = (const int*)d_in[1];
    const float* ea    = (const float*)d_in[2];
    const int*   batch = (const int*)d_in[3];
    const float* W1[4] = {(const float*)d_in[4], (const float*)d_in[6],
                          (const float*)d_in[8], (const float*)d_in[10]};
    const float* b1[4] = {(const float*)d_in[5], (const float*)d_in[7],
                          (const float*)d_in[9], (const float*)d_in[11]};
    const float* W2  = (const float*)d_in[12];
    const float* b2  = (const float*)d_in[13];
    const float* W3  = (const float*)d_in[14];
    const float* b3  = (const float*)d_in[15];
    const float* Wm1 = (const float*)d_in[16];
    const float* bm1 = (const float*)d_in[17];
    const float* Wm2 = (const float*)d_in[18];
    const float* bm2 = (const float*)d_in[19];
    float* out = (float*)d_out;

    float *dis, *z, *H, *M2, *Y2, *M3, *Y3, *psum, *pcnt;
    unsigned* pmax;
    cudaGetSymbolAddress((void**)&dis,  g_dis);
    cudaGetSymbolAddress((void**)&z,    g_z);
    cudaGetSymbolAddress((void**)&H,    g_H);
    cudaGetSymbolAddress((void**)&M2,   g_M2);
    cudaGetSymbolAddress((void**)&Y2,   g_Y2);
    cudaGetSymbolAddress((void**)&M3,   g_M3);
    cudaGetSymbolAddress((void**)&Y3,   g_Y3);
    cudaGetSymbolAddress((void**)&psum, g_psum);
    cudaGetSymbolAddress((void**)&pmax, g_pmax);
    cudaGetSymbolAddress((void**)&pcnt, g_pcnt);

    // 1. degrees
    k_deg_init<<<(5 * NN + 255) / 256, 256>>>(dis);
    k_deg_edges<<<(NE + 255) / 256, 256>>>(ei, ea, dis);
    k_rsqrt<<<(5 * NN + 255) / 256, 256>>>(dis);

    // 2. conv1 aggregation of x (aggregate-then-GEMM: S(xW) = (Sx)W)
    k_z_init<<<(NN * 32 + 255) / 256, 256>>>(x, dis, z);
    k_z_edges<<<(NE * 32 + 255) / 256, 256>>>(ei, ea, x, dis, z);

    // 3. conv1 GEMMs: H[:, k*128:(k+1)*128] = relu(z_k @ W1k + b1k)
    for (int k = 0; k < 4; k++) {
        dim3 grid(128 / BN, (NN + BM - 1) / BM);
        k_gemm<<<grid, 256>>>(z + (size_t)k * NN * DD, DD, nullptr,
                              W1[k], DD,
                              H + k * DD, 4 * DD,
                              NN, DD, b1[k], 1);
    }

    // 4. conv2: M2 = H @ W2 (GEMM-then-aggregate: output narrower)
    {
        dim3 grid(256 / BN, (NN + BM - 1) / BM);
        k_gemm<<<grid, 256>>>(H, 4 * DD, nullptr, W2, 2 * DD, M2, 2 * DD,
                              NN, 4 * DD, nullptr, 0);
    }
    k_agg_init<256><<<(NN * 64 + 255) / 256, 256>>>(M2, dis, Y2);
    k_agg_edges<256><<<(NE * 32 + 255) / 256, 256>>>(ei, M2, dis, Y2);

    // 5. conv3: M3 = relu(Y2 + b2) @ W3   (bias+relu of conv2 folded into A-load)
    {
        dim3 grid(128 / BN, (NN + BM - 1) / BM);
        k_gemm<<<grid, 256>>>(Y2, 2 * DD, b2, W3, DD, M3, DD,
                              NN, 2 * DD, nullptr, 0);
    }
    k_agg_init<128><<<(NN * 32 + 255) / 256, 256>>>(M3, dis, Y3);
    k_agg_edges<128><<<(NE * 32 + 255) / 256, 256>>>(ei, M3, dis, Y3);

    // 6. pooling (b3 folded in here) + MLP head
    k_pool_init<<<(NG * DD + 255) / 256, 256>>>(psum, pmax, pcnt);
    k_pool<<<(NN + POOL_CHUNK - 1) / POOL_CHUNK, DD>>>(Y3, b3, batch, psum, pmax, pcnt);
    k_mlp<<<1, 64>>>(Wm1, bm1, Wm2, bm2, psum, pmax, pcnt, out);
}

// round 4
// speedup vs baseline: 1.8464x; 1.8464x over previous
#include <cuda_runtime.h>
#include <cstdint>

#define NN 50000
#define NE 600000
#define DD 128
#define NG 64

// ---------------- scratch (static __device__, allocation-free) ----------------
static __device__ float    g_dis[5 * NN];        // rsqrt degrees: k=0..3 weighted, 4 unweighted
static __device__ int      g_cnt[NN];            // in-degree (no self loop)
static __device__ int      g_cursor[NN];
static __device__ int      g_rowstart[NN + 1];
static __device__ int      g_bsum[64];
static __device__ int      g_csr_src[NE];
static __device__ float4   g_csr_n4[NE];
static __device__ float    g_csr_nu[NE];
static __device__ float    g_z[4 * NN * DD];     // z_k = S_k x
static __device__ float    g_H[NN * 4 * DD];     // concat relu(z_k W_k + b_k)
static __device__ float    g_M2[NN * 2 * DD];    // H @ W2
static __device__ float    g_Y2[NN * 2 * DD];    // S_u M2
static __device__ float    g_M3[NN * DD];        // relu(Y2+b2) @ W3
static __device__ float    g_Y3[NN * DD];        // S_u M3
static __device__ float    g_psum[NG * DD];
static __device__ unsigned g_pmax[NG * DD];
static __device__ float    g_pcnt[NG];

// ---------------- f32x2 packed math helpers (sm_103a FFMA2) ----------------
__device__ __forceinline__ unsigned long long pk2(float lo, float hi) {
    unsigned long long d;
    asm("mov.b64 %0, {%1, %2};" : "=l"(d) : "f"(lo), "f"(hi));
    return d;
}
__device__ __forceinline__ unsigned long long f2fma(unsigned long long a,
                                                    unsigned long long b,
                                                    unsigned long long c) {
    unsigned long long d;
    asm("fma.rn.f32x2 %0, %1, %2, %3;" : "=l"(d) : "l"(a), "l"(b), "l"(c));
    return d;
}
__device__ __forceinline__ float2 upk2(unsigned long long d) {
    float2 v;
    asm("mov.b64 {%0, %1}, %2;" : "=f"(v.x), "=f"(v.y) : "l"(d));
    return v;
}

__device__ __forceinline__ unsigned fenc(float f) {
    unsigned b = __float_as_uint(f);
    return (b & 0x80000000u) ? ~b : (b | 0x80000000u);
}
__device__ __forceinline__ float fdec(unsigned u) {
    return (u & 0x80000000u) ? __uint_as_float(u & 0x7fffffffu) : __uint_as_float(~u);
}

// ---------------- degree + CSR build ----------------
__global__ void k_init(float* dis, int* cnt, int* cursor) {
    int i = blockIdx.x * blockDim.x + threadIdx.x;
    if (i < 5 * NN) dis[i] = 1.0f;   // self-loop weight 1
    if (i < NN) { cnt[i] = 0; cursor[i] = 0; }
}

__global__ void k_deg_edges(const int* __restrict__ ei, const float* __restrict__ ea,
                            float* dis, int* cnt) {
    int e = blockIdx.x * blockDim.x + threadIdx.x;
    if (e >= NE) return;
    int d = ei[NE + e];
    float4 w = *reinterpret_cast<const float4*>(&ea[e * 4]);
    atomicAdd(&dis[0 * NN + d], w.x);
    atomicAdd(&dis[1 * NN + d], w.y);
    atomicAdd(&dis[2 * NN + d], w.z);
    atomicAdd(&dis[3 * NN + d], w.w);
    atomicAdd(&dis[4 * NN + d], 1.0f);
    atomicAdd(&cnt[d], 1);
}

__global__ void k_rsqrt(float* dis) {
    int i = blockIdx.x * blockDim.x + threadIdx.x;
    if (i < 5 * NN) dis[i] = rsqrtf(dis[i]);
}

__global__ void k_scan_block(const int* __restrict__ cnt, int* __restrict__ rowstart,
                             int* __restrict__ bsum) {
    __shared__ int sh[1024];
    int i = blockIdx.x * 1024 + threadIdx.x;
    int v = (i < NN) ? cnt[i] : 0;
    sh[threadIdx.x] = v;
    __syncthreads();
    #pragma unroll
    for (int off = 1; off < 1024; off <<= 1) {
        int t = (threadIdx.x >= off) ? sh[threadIdx.x - off] : 0;
        __syncthreads();
        sh[threadIdx.x] += t;
        __syncthreads();
    }
    if (i < NN) rowstart[i] = sh[threadIdx.x] - v;  // exclusive within block
    if (threadIdx.x == 1023) bsum[blockIdx.x] = sh[1023];
}

__global__ void k_scan_top(int* bsum, int nb) {
    if (threadIdx.x == 0) {
        int run = 0;
        for (int b = 0; b < nb; b++) { int t = bsum[b]; bsum[b] = run; run += t; }
    }
}

__global__ void k_scan_add(int* rowstart, const int* __restrict__ bsum) {
    int i = blockIdx.x * 1024 + threadIdx.x;
    if (i < NN) rowstart[i] += bsum[blockIdx.x];
    if (blockIdx.x == 0 && threadIdx.x == 0) rowstart[NN] = NE;
}

__global__ void k_csr_fill(const int* __restrict__ ei, const float* __restrict__ ea,
                           const float* __restrict__ dis, const int* __restrict__ rowstart,
                           int* cursor, int* __restrict__ csr_src,
                           float4* __restrict__ csr_n4, float* __restrict__ csr_nu) {
    int e = blockIdx.x * blockDim.x + threadIdx.x;
    if (e >= NE) return;
    int s = ei[e], d = ei[NE + e];
    int pos = rowstart[d] + atomicAdd(&cursor[d], 1);
    csr_src[pos] = s;
    float4 w = *reinterpret_cast<const float4*>(&ea[e * 4]);
    float4 n;
    n.x = dis[0 * NN + s] * w.x * dis[0 * NN + d];
    n.y = dis[1 * NN + s] * w.y * dis[1 * NN + d];
    n.z = dis[2 * NN + s] * w.z * dis[2 * NN + d];
    n.w = dis[3 * NN + s] * w.w * dis[3 * NN + d];
    csr_n4[pos] = n;
    csr_nu[pos] = dis[4 * NN + s] * dis[4 * NN + d];
}

// ---------------- gather aggregations (no atomics) ----------------
// z_k[i] = dis_k[i]^2 * x[i] + sum_e n_k(e) * x[src(e)]
__global__ void k_gather_z(const float4* __restrict__ x4, const float* __restrict__ dis,
                           const int* __restrict__ rowstart, const int* __restrict__ csr_src,
                           const float4* __restrict__ csr_n4, float4* __restrict__ z4) {
    int warp = (blockIdx.x * blockDim.x + threadIdx.x) >> 5;
    int lane = threadIdx.x & 31;
    if (warp >= NN) return;
    int i = warp;
    float4 xv = x4[i * 32 + lane];
    float d0 = dis[i], d1 = dis[NN + i], d2 = dis[2 * NN + i], d3 = dis[3 * NN + i];
    float s0 = d0 * d0, s1 = d1 * d1, s2 = d2 * d2, s3 = d3 * d3;
    float4 a0 = make_float4(xv.x * s0, xv.y * s0, xv.z * s0, xv.w * s0);
    float4 a1 = make_float4(xv.x * s1, xv.y * s1, xv.z * s1, xv.w * s1);
    float4 a2 = make_float4(xv.x * s2, xv.y * s2, xv.z * s2, xv.w * s2);
    float4 a3 = make_float4(xv.x * s3, xv.y * s3, xv.z * s3, xv.w * s3);
    int e0 = rowstart[i], e1 = rowstart[i + 1];
    for (int e = e0; e < e1; e++) {
        int s = csr_src[e];
        float4 n = csr_n4[e];
        float4 xs = x4[s * 32 + lane];
        a0.x += n.x * xs.x; a0.y += n.x * xs.y; a0.z += n.x * xs.z; a0.w += n.x * xs.w;
        a1.x += n.y * xs.x; a1.y += n.y * xs.y; a1.z += n.y * xs.z; a1.w += n.y * xs.w;
        a2.x += n.z * xs.x; a2.y += n.z * xs.y; a2.z += n.z * xs.z; a2.w += n.z * xs.w;
        a3.x += n.w * xs.x; a3.y += n.w * xs.y; a3.z += n.w * xs.z; a3.w += n.w * xs.w;
    }
    int base = i * 32 + lane;
    z4[0 * NN * 32 + base] = a0;
    z4[1 * NN * 32 + base] = a1;
    z4[2 * NN * 32 + base] = a2;
    z4[3 * NN * 32 + base] = a3;
}

// Y[i] = dis_u[i]^2 * M[i] + sum_e nu(e) * M[src(e)]   (F floats per row)
template<int F>
__global__ void k_gather_u(const float4* __restrict__ M4, const float* __restrict__ dis,
                           const int* __restrict__ rowstart, const int* __restrict__ csr_src,
                           const float* __restrict__ csr_nu, float4* __restrict__ Y4) {
    constexpr int V = F / 128;  // float4 per lane
    int warp = (blockIdx.x * blockDim.x + threadIdx.x) >> 5;
    int lane = threadIdx.x & 31;
    if (warp >= NN) return;
    int i = warp;
    float du = dis[4 * NN + i];
    float s0 = du * du;
    float4 acc[V];
    #pragma unroll
    for (int v = 0; v < V; v++) {
        float4 m = M4[i * (F / 4) + lane + 32 * v];
        acc[v] = make_float4(m.x * s0, m.y * s0, m.z * s0, m.w * s0);
    }
    int e0 = rowstart[i], e1 = rowstart[i + 1];
    for (int e = e0; e < e1; e++) {
        int s = csr_src[e];
        float nu = csr_nu[e];
        #pragma unroll
        for (int v = 0; v < V; v++) {
            float4 m = M4[s * (F / 4) + lane + 32 * v];
            acc[v].x += nu * m.x; acc[v].y += nu * m.y;
            acc[v].z += nu * m.z; acc[v].w += nu * m.w;
        }
    }
    #pragma unroll
    for (int v = 0; v < V; v++) Y4[i * (F / 4) + lane + 32 * v] = acc[v];
}

// ---------------- FFMA2 SGEMM: C[M,N] = op(A)[M,K] @ B[K,N] (+bias, relu) ----------------
// op(A): if Abias != null, a = relu(a + Abias[k])
#define GBM 128
#define GBN 128
#define GBK 8
__global__ __launch_bounds__(256, 2)
void k_gemm2(const float* __restrict__ A, int lda, const float* __restrict__ Abias,
             const float* __restrict__ B, int ldb,
             float* __restrict__ C, int ldc, int M, int K,
             const float* __restrict__ Cbias, int crelu) {
    __shared__ __align__(16) float As[2][GBK][GBM];
    __shared__ __align__(16) float Bs[2][GBK][GBN];
    int tid = threadIdx.x;
    int row0 = blockIdx.y * GBM;
    int col0 = blockIdx.x * GBN;

    int ar = tid >> 1;           // A-load row within tile (0..127)
    int ac = (tid & 1) * 4;      // A-load k offset (0 or 4)
    int br = tid >> 5;           // B-load k row (0..7)
    int bc = (tid & 31) * 4;     // B-load col
    int tx = tid & 15, ty = tid >> 4;

    unsigned long long acc[8][4];
    #pragma unroll
    for (int i = 0; i < 8; i++)
        #pragma unroll
        for (int j = 0; j < 4; j++) acc[i][j] = 0ull;

    // prefetch tile 0
    float4 av, bv;
    {
        int gr = row0 + ar;
        av = make_float4(0.f, 0.f, 0.f, 0.f);
        if (gr < M) {
            av = *reinterpret_cast<const float4*>(&A[(size_t)gr * lda + ac]);
            if (Abias) {
                float4 bb = *reinterpret_cast<const float4*>(&Abias[ac]);
                av.x = fmaxf(av.x + bb.x, 0.f); av.y = fmaxf(av.y + bb.y, 0.f);
                av.z = fmaxf(av.z + bb.z, 0.f); av.w = fmaxf(av.w + bb.w, 0.f);
            }
        }
        bv = *reinterpret_cast<const float4*>(&B[(size_t)br * ldb + col0 + bc]);
    }
    As[0][ac + 0][ar] = av.x; As[0][ac + 1][ar] = av.y;
    As[0][ac + 2][ar] = av.z; As[0][ac + 3][ar] = av.w;
    *reinterpret_cast<float4*>(&Bs[0][br][bc]) = bv;
    __syncthreads();

    int nk = K >> 3;
    for (int kt = 0; kt < nk; kt++) {
        int cur = kt & 1;
        bool has = (kt + 1 < nk);
        float4 an, bn;
        if (has) {
            int k0 = (kt + 1) * GBK;
            int gr = row0 + ar;
            an = make_float4(0.f, 0.f, 0.f, 0.f);
            if (gr < M) {
                an = *reinterpret_cast<const float4*>(&A[(size_t)gr * lda + k0 + ac]);
                if (Abias) {
                    float4 bb = *reinterpret_cast<const float4*>(&Abias[k0 + ac]);
                    an.x = fmaxf(an.x + bb.x, 0.f); an.y = fmaxf(an.y + bb.y, 0.f);
                    an.z = fmaxf(an.z + bb.z, 0.f); an.w = fmaxf(an.w + bb.w, 0.f);
                }
            }
            bn = *reinterpret_cast<const float4*>(&B[(size_t)(k0 + br) * ldb + col0 + bc]);
        }

        #pragma unroll
        for (int kk = 0; kk < GBK; kk++) {
            float4 a0 = *reinterpret_cast<const float4*>(&As[cur][kk][ty * 8]);
            float4 a1 = *reinterpret_cast<const float4*>(&As[cur][kk][ty * 8 + 4]);
            float4 b0 = *reinterpret_cast<const float4*>(&Bs[cur][kk][tx * 8]);
            float4 b1 = *reinterpret_cast<const float4*>(&Bs[cur][kk][tx * 8 + 4]);
            unsigned long long bb[4] = { pk2(b0.x, b0.y), pk2(b0.z, b0.w),
                                         pk2(b1.x, b1.y), pk2(b1.z, b1.w) };
            float aa[8] = { a0.x, a0.y, a0.z, a0.w, a1.x, a1.y, a1.z, a1.w };
            #pragma unroll
            for (int i = 0; i < 8; i++) {
                unsigned long long ai = pk2(aa[i], aa[i]);
                #pragma unroll
                for (int j = 0; j < 4; j++) acc[i][j] = f2fma(ai, bb[j], acc[i][j]);
            }
        }

        if (has) {
            int nb = cur ^ 1;
            As[nb][ac + 0][ar] = an.x; As[nb][ac + 1][ar] = an.y;
            As[nb][ac + 2][ar] = an.z; As[nb][ac + 3][ar] = an.w;
            *reinterpret_cast<float4*>(&Bs[nb][br][bc]) = bn;
        }
        __syncthreads();
    }

    // epilogue
    float cb[8] = {0, 0, 0, 0, 0, 0, 0, 0};
    if (Cbias) {
        float4 c0 = *reinterpret_cast<const float4*>(&Cbias[col0 + tx * 8]);
        float4 c1 = *reinterpret_cast<const float4*>(&Cbias[col0 + tx * 8 + 4]);
        cb[0] = c0.x; cb[1] = c0.y; cb[2] = c0.z; cb[3] = c0.w;
        cb[4] = c1.x; cb[5] = c1.y; cb[6] = c1.z; cb[7] = c1.w;
    }
    #pragma unroll
    for (int i = 0; i < 8; i++) {
        int r = row0 + ty * 8 + i;
        if (r >= M) continue;
        float v[8];
        #pragma unroll
        for (int j = 0; j < 4; j++) {
            float2 p = upk2(acc[i][j]);
            v[2 * j] = p.x + cb[2 * j];
            v[2 * j + 1] = p.y + cb[2 * j + 1];
        }
        if (crelu) {
            #pragma unroll
            for (int j = 0; j < 8; j++) v[j] = fmaxf(v[j], 0.f);
        }
        float* cp = &C[(size_t)r * ldc + col0 + tx * 8];
        *reinterpret_cast<float4*>(cp) = make_float4(v[0], v[1], v[2], v[3]);
        *reinterpret_cast<float4*>(cp + 4) = make_float4(v[4], v[5], v[6], v[7]);
    }
}

// ---------------- pooling ----------------
__global__ void k_pool_init(float* psum, unsigned* pmax, float* pcnt) {
    int i = blockIdx.x * blockDim.x + threadIdx.x;
    if (i < NG * DD) { psum[i] = 0.0f; pmax[i] = 0x007fffffu; }  // enc(-inf)
    if (i < NG) pcnt[i] = 0.0f;
}

#define POOL_CHUNK 256
__global__ void k_pool(const float* __restrict__ Y3, const float* __restrict__ b3,
                       const int* __restrict__ batch,
                       float* psum, unsigned* pmax, float* pcnt) {
    int j = threadIdx.x;  // 0..127 feature
    int i0 = blockIdx.x * POOL_CHUNK;
    int iend = min(i0 + POOL_CHUNK, NN);
    float bj = b3[j];
    int cur = -1;
    float s = 0.0f, m = __int_as_float(0xff800000), cnt = 0.0f;
    for (int i = i0; i < iend; i++) {
        int g = batch[i];
        if (g != cur) {
            if (cur >= 0) {
                atomicAdd(&psum[cur * DD + j], s);
                atomicMax(&pmax[cur * DD + j], fenc(m));
                if (j == 0) atomicAdd(&pcnt[cur], cnt);
            }
            cur = g; s = 0.0f; m = __int_as_float(0xff800000); cnt = 0.0f;
        }
        float y = Y3[(size_t)i * DD + j] + bj;
        s += y;
        m = fmaxf(m, y);
        cnt += 1.0f;
    }
    if (cur >= 0) {
        atomicAdd(&psum[cur * DD + j], s);
        atomicMax(&pmax[cur * DD + j], fenc(m));
        if (j == 0) atomicAdd(&pcnt[cur], cnt);
    }
}

// ---------------- MLP head ----------------
__global__ void k_mlp(const float* __restrict__ Wm1, const float* __restrict__ bm1,
                      const float* __restrict__ Wm2, const float* __restrict__ bm2,
                      const float* __restrict__ psum, const unsigned* __restrict__ pmax,
                      const float* __restrict__ pcnt, float* __restrict__ out) {
    int g = threadIdx.x;
    if (g >= NG) return;
    float cnt = pcnt[g];
    float inv = 1.0f / fmaxf(cnt, 1.0f);
    float hid[8];
    #pragma unroll
    for (int h = 0; h < 8; h++) hid[h] = bm1[h];
    for (int j = 0; j < DD; j++) {
        float mean = psum[g * DD + j] * inv;
        #pragma unroll
        for (int h = 0; h < 8; h++) hid[h] += mean * Wm1[j * 8 + h];
    }
    for (int j = 0; j < DD; j++) {
        float mx = (cnt > 0.0f) ? fdec(pmax[g * DD + j]) : 0.0f;
        #pragma unroll
        for (int h = 0; h < 8; h++) hid[h] += mx * Wm1[(DD + j) * 8 + h];
    }
    #pragma unroll
    for (int h = 0; h < 8; h++) hid[h] = fmaxf(hid[h], 0.0f);
    #pragma unroll
    for (int c = 0; c < 2; c++) {
        float o = bm2[c];
        #pragma unroll
        for (int h = 0; h < 8; h++) o += hid[h] * Wm2[h * 2 + c];
        out[g * 2 + c] = o;
    }
}

// ---------------- driver ----------------
extern "C" void kernel_launch(void* const* d_in, const int* in_sizes, int n_in,
                              void* d_out, int out_size) {
    const float* x     = (const float*)d_in[0];
    const int*   ei    = (const int*)d_in[1];
    const float* ea    = (const float*)d_in[2];
    const int*   batch = (const int*)d_in[3];
    const float* W1[4] = {(const float*)d_in[4], (const float*)d_in[6],
                          (const float*)d_in[8], (const float*)d_in[10]};
    const float* b1[4] = {(const float*)d_in[5], (const float*)d_in[7],
                          (const float*)d_in[9], (const float*)d_in[11]};
    const float* W2  = (const float*)d_in[12];
    const float* b2  = (const float*)d_in[13];
    const float* W3  = (const float*)d_in[14];
    const float* b3  = (const float*)d_in[15];
    const float* Wm1 = (const float*)d_in[16];
    const float* bm1 = (const float*)d_in[17];
    const float* Wm2 = (const float*)d_in[18];
    const float* bm2 = (const float*)d_in[19];
    float* out = (float*)d_out;

    float *dis, *z, *H, *M2, *Y2, *M3, *Y3, *psum, *pcnt, *csr_nu;
    int *cnt, *cursor, *rowstart, *bsum, *csr_src;
    float4* csr_n4;
    unsigned* pmax;
    cudaGetSymbolAddress((void**)&dis,      g_dis);
    cudaGetSymbolAddress((void**)&cnt,      g_cnt);
    cudaGetSymbolAddress((void**)&cursor,   g_cursor);
    cudaGetSymbolAddress((void**)&rowstart, g_rowstart);
    cudaGetSymbolAddress((void**)&bsum,     g_bsum);
    cudaGetSymbolAddress((void**)&csr_src,  g_csr_src);
    cudaGetSymbolAddress((void**)&csr_n4,   g_csr_n4);
    cudaGetSymbolAddress((void**)&csr_nu,   g_csr_nu);
    cudaGetSymbolAddress((void**)&z,        g_z);
    cudaGetSymbolAddress((void**)&H,        g_H);
    cudaGetSymbolAddress((void**)&M2,       g_M2);
    cudaGetSymbolAddress((void**)&Y2,       g_Y2);
    cudaGetSymbolAddress((void**)&M3,       g_M3);
    cudaGetSymbolAddress((void**)&Y3,       g_Y3);
    cudaGetSymbolAddress((void**)&psum,     g_psum);
    cudaGetSymbolAddress((void**)&pmax,     g_pmax);
    cudaGetSymbolAddress((void**)&pcnt,     g_pcnt);

    const int NB = (NN + 1023) / 1024;  // 49 scan blocks

    // 1. degrees + CSR
    k_init<<<(5 * NN + 255) / 256, 256>>>(dis, cnt, cursor);
    k_deg_edges<<<(NE + 255) / 256, 256>>>(ei, ea, dis, cnt);
    k_rsqrt<<<(5 * NN + 255) / 256, 256>>>(dis);
    k_scan_block<<<NB, 1024>>>(cnt, rowstart, bsum);
    k_scan_top<<<1, 32>>>(bsum, NB);
    k_scan_add<<<NB, 1024>>>(rowstart, bsum);
    k_csr_fill<<<(NE + 255) / 256, 256>>>(ei, ea, dis, rowstart, cursor,
                                          csr_src, csr_n4, csr_nu);

    // 2. conv1 aggregation of x (aggregate-then-GEMM: S(xW) = (Sx)W)
    k_gather_z<<<(NN * 32 + 255) / 256, 256>>>(
        (const float4*)x, dis, rowstart, csr_src, csr_n4, (float4*)z);

    // 3. conv1 GEMMs: H[:, k*128:(k+1)*128] = relu(z_k @ W1k + b1k)
    for (int k = 0; k < 4; k++) {
        dim3 grid(1, (NN + GBM - 1) / GBM);
        k_gemm2<<<grid, 256>>>(z + (size_t)k * NN * DD, DD, nullptr,
                               W1[k], DD, H + k * DD, 4 * DD, NN, DD, b1[k], 1);
    }

    // 4. conv2: M2 = H @ W2, then aggregate
    {
        dim3 grid(2, (NN + GBM - 1) / GBM);
        k_gemm2<<<grid, 256>>>(H, 4 * DD, nullptr, W2, 2 * DD, M2, 2 * DD,
                               NN, 4 * DD, nullptr, 0);
    }
    k_gather_u<256><<<(NN * 32 + 255) / 256, 256>>>(
        (const float4*)M2, dis, rowstart, csr_src, csr_nu, (float4*)Y2);

    // 5. conv3: M3 = relu(Y2 + b2) @ W3, then aggregate
    {
        dim3 grid(1, (NN + GBM - 1) / GBM);
        k_gemm2<<<grid, 256>>>(Y2, 2 * DD, b2, W3, DD, M3, DD, NN, 2 * DD, nullptr, 0);
    }
    k_gather_u<128><<<(NN * 32 + 255) / 256, 256>>>(
        (const float4*)M3, dis, rowstart, csr_src, csr_nu, (float4*)Y3);

    // 6. pooling (b3 folded in) + MLP head
    k_pool_init<<<(NG * DD + 255) / 256, 256>>>(psum, pmax, pcnt);
    k_pool<<<(NN + POOL_CHUNK - 1) / POOL_CHUNK, DD>>>(Y3, b3, batch, psum, pmax, pcnt);
    k_mlp<<<1, 64>>>(Wm1, bm1, Wm2, bm2, psum, pmax, pcnt, out);
}

// round 10
// speedup vs baseline: 2.4305x; 1.3164x over previous
#include <cuda_runtime.h>
#include <cuda_bf16.h>
#include <cstdint>

#define NN 50000
#define NE 600000
#define DD 128
#define NG 64

// ---------------- scratch (static __device__, allocation-free) ----------------
static __device__ float    g_dis[5 * NN];        // rsqrt degrees: k=0..3 weighted, 4 unweighted
static __device__ int      g_cnt[NN];
static __device__ int      g_cursor[NN];
static __device__ int      g_rowstart[NN + 1];
static __device__ int      g_bsum[64];
static __device__ int      g_csr_src[NE];
static __device__ float4   g_csr_n4[NE];
static __device__ float    g_csr_nu[NE];
static __device__ float    g_z[4 * NN * DD];     // z_k = S_k x
static __device__ float    g_H[NN * 4 * DD];     // concat relu(z_k W_k + b_k)
static __device__ float    g_M2[NN * 2 * DD];    // H @ W2
static __device__ float    g_Y2[NN * 2 * DD];    // S_u M2
static __device__ float    g_M3[NN * DD];        // relu(Y2+b2) @ W3
static __device__ float    g_Y3[NN * DD];        // S_u M3
static __device__ float    g_Wt1[4 * DD * DD];   // W1k^T  [128,128] each (N-major, K contig)
static __device__ float    g_Wt2[2 * DD * 4 * DD];  // W2^T [256,512]
static __device__ float    g_Wt3[DD * 2 * DD];   // W3^T [128,256]
static __device__ float    g_psum[NG * DD];
static __device__ unsigned g_pmax[NG * DD];
static __device__ float    g_pcnt[NG];

// ---------------- small helpers ----------------
__device__ __forceinline__ unsigned fenc(float f) {
    unsigned b = __float_as_uint(f);
    return (b & 0x80000000u) ? ~b : (b | 0x80000000u);
}
__device__ __forceinline__ float fdec(unsigned u) {
    return (u & 0x80000000u) ? __uint_as_float(u & 0x7fffffffu) : __uint_as_float(~u);
}
__device__ __forceinline__ uint32_t smem_u32(const void* p) {
    uint32_t a;
    asm("{ .reg .u64 t; cvta.to.shared.u64 t, %1; cvt.u32.u64 %0, t; }" : "=r"(a) : "l"(p));
    return a;
}

__device__ __forceinline__ void ldsm4(uint32_t& r0, uint32_t& r1, uint32_t& r2, uint32_t& r3,
                                      uint32_t addr) {
    asm volatile("ldmatrix.sync.aligned.m8n8.x4.shared.b16 {%0,%1,%2,%3}, [%4];"
                 : "=r"(r0), "=r"(r1), "=r"(r2), "=r"(r3) : "r"(addr));
}

__device__ __forceinline__ void mma_bf16(float* c, const uint32_t* a, uint32_t b0, uint32_t b1) {
    asm volatile(
        "mma.sync.aligned.m16n8k16.row.col.f32.bf16.bf16.f32 "
        "{%0,%1,%2,%3}, {%4,%5,%6,%7}, {%8,%9}, {%0,%1,%2,%3};"
        : "+f"(c[0]), "+f"(c[1]), "+f"(c[2]), "+f"(c[3])
        : "r"(a[0]), "r"(a[1]), "r"(a[2]), "r"(a[3]), "r"(b0), "r"(b1));
}

// ---------------- degree + CSR build ----------------
__global__ void k_init(float* dis, int* cnt, int* cursor) {
    int i = blockIdx.x * blockDim.x + threadIdx.x;
    if (i < 5 * NN) dis[i] = 1.0f;
    if (i < NN) { cnt[i] = 0; cursor[i] = 0; }
}

__global__ void k_deg_edges(const int* __restrict__ ei, const float* __restrict__ ea,
                            float* dis, int* cnt) {
    int e = blockIdx.x * blockDim.x + threadIdx.x;
    if (e >= NE) return;
    int d = ei[NE + e];
    float4 w = *reinterpret_cast<const float4*>(&ea[e * 4]);
    atomicAdd(&dis[0 * NN + d], w.x);
    atomicAdd(&dis[1 * NN + d], w.y);
    atomicAdd(&dis[2 * NN + d], w.z);
    atomicAdd(&dis[3 * NN + d], w.w);
    atomicAdd(&dis[4 * NN + d], 1.0f);
    atomicAdd(&cnt[d], 1);
}

__global__ void k_rsqrt(float* dis) {
    int i = blockIdx.x * blockDim.x + threadIdx.x;
    if (i < 5 * NN) dis[i] = rsqrtf(dis[i]);
}

__global__ void k_scan_block(const int* __restrict__ cnt, int* __restrict__ rowstart,
                             int* __restrict__ bsum) {
    __shared__ int sh[1024];
    int i = blockIdx.x * 1024 + threadIdx.x;
    int v = (i < NN) ? cnt[i] : 0;
    sh[threadIdx.x] = v;
    __syncthreads();
    #pragma unroll
    for (int off = 1; off < 1024; off <<= 1) {
        int t = (threadIdx.x >= off) ? sh[threadIdx.x - off] : 0;
        __syncthreads();
        sh[threadIdx.x] += t;
        __syncthreads();
    }
    if (i < NN) rowstart[i] = sh[threadIdx.x] - v;
    if (threadIdx.x == 1023) bsum[blockIdx.x] = sh[1023];
}

__global__ void k_scan_top(int* bsum, int nb) {
    if (threadIdx.x == 0) {
        int run = 0;
        for (int b = 0; b < nb; b++) { int t = bsum[b]; bsum[b] = run; run += t; }
    }
}

__global__ void k_scan_add(int* rowstart, const int* __restrict__ bsum) {
    int i = blockIdx.x * 1024 + threadIdx.x;
    if (i < NN) rowstart[i] += bsum[blockIdx.x];
    if (blockIdx.x == 0 && threadIdx.x == 0) rowstart[NN] = NE;
}

__global__ void k_csr_fill(const int* __restrict__ ei, const float* __restrict__ ea,
                           const float* __restrict__ dis, const int* __restrict__ rowstart,
                           int* cursor, int* __restrict__ csr_src,
                           float4* __restrict__ csr_n4, float* __restrict__ csr_nu) {
    int e = blockIdx.x * blockDim.x + threadIdx.x;
    if (e >= NE) return;
    int s = ei[e], d = ei[NE + e];
    int pos = rowstart[d] + atomicAdd(&cursor[d], 1);
    csr_src[pos] = s;
    float4 w = *reinterpret_cast<const float4*>(&ea[e * 4]);
    float4 n;
    n.x = dis[0 * NN + s] * w.x * dis[0 * NN + d];
    n.y = dis[1 * NN + s] * w.y * dis[1 * NN + d];
    n.z = dis[2 * NN + s] * w.z * dis[2 * NN + d];
    n.w = dis[3 * NN + s] * w.w * dis[3 * NN + d];
    csr_n4[pos] = n;
    csr_nu[pos] = dis[4 * NN + s] * dis[4 * NN + d];
}

// ---------------- weight transpose: Wt[n*K + k] = W[k*N + n] ----------------
__global__ void k_tr(const float* __restrict__ W, float* __restrict__ Wt, int K, int N) {
    int i = blockIdx.x * blockDim.x + threadIdx.x;
    if (i >= K * N) return;
    int k = i / N, n = i % N;
    Wt[(size_t)n * K + k] = W[i];
}

// ---------------- gather aggregations (no atomics) ----------------
__global__ void k_gather_z(const float4* __restrict__ x4, const float* __restrict__ dis,
                           const int* __restrict__ rowstart, const int* __restrict__ csr_src,
                           const float4* __restrict__ csr_n4, float4* __restrict__ z4) {
    int warp = (blockIdx.x * blockDim.x + threadIdx.x) >> 5;
    int lane = threadIdx.x & 31;
    if (warp >= NN) return;
    int i = warp;
    float4 xv = x4[i * 32 + lane];
    float d0 = dis[i], d1 = dis[NN + i], d2 = dis[2 * NN + i], d3 = dis[3 * NN + i];
    float s0 = d0 * d0, s1 = d1 * d1, s2 = d2 * d2, s3 = d3 * d3;
    float4 a0 = make_float4(xv.x * s0, xv.y * s0, xv.z * s0, xv.w * s0);
    float4 a1 = make_float4(xv.x * s1, xv.y * s1, xv.z * s1, xv.w * s1);
    float4 a2 = make_float4(xv.x * s2, xv.y * s2, xv.z * s2, xv.w * s2);
    float4 a3 = make_float4(xv.x * s3, xv.y * s3, xv.z * s3, xv.w * s3);
    int e0 = rowstart[i], e1 = rowstart[i + 1];
    for (int e = e0; e < e1; e++) {
        int s = csr_src[e];
        float4 n = csr_n4[e];
        float4 xs = x4[s * 32 + lane];
        a0.x += n.x * xs.x; a0.y += n.x * xs.y; a0.z += n.x * xs.z; a0.w += n.x * xs.w;
        a1.x += n.y * xs.x; a1.y += n.y * xs.y; a1.z += n.y * xs.z; a1.w += n.y * xs.w;
        a2.x += n.z * xs.x; a2.y += n.z * xs.y; a2.z += n.z * xs.z; a2.w += n.z * xs.w;
        a3.x += n.w * xs.x; a3.y += n.w * xs.y; a3.z += n.w * xs.z; a3.w += n.w * xs.w;
    }
    int base = i * 32 + lane;
    z4[0 * NN * 32 + base] = a0;
    z4[1 * NN * 32 + base] = a1;
    z4[2 * NN * 32 + base] = a2;
    z4[3 * NN * 32 + base] = a3;
}

template<int F>
__global__ void k_gather_u(const float4* __restrict__ M4, const float* __restrict__ dis,
                           const int* __restrict__ rowstart, const int* __restrict__ csr_src,
                           const float* __restrict__ csr_nu, float4* __restrict__ Y4) {
    constexpr int V = F / 128;
    int warp = (blockIdx.x * blockDim.x + threadIdx.x) >> 5;
    int lane = threadIdx.x & 31;
    if (warp >= NN) return;
    int i = warp;
    float du = dis[4 * NN + i];
    float s0 = du * du;
    float4 acc[V];
    #pragma unroll
    for (int v = 0; v < V; v++) {
        float4 m = M4[i * (F / 4) + lane + 32 * v];
        acc[v] = make_float4(m.x * s0, m.y * s0, m.z * s0, m.w * s0);
    }
    int e0 = rowstart[i], e1 = rowstart[i + 1];
    for (int e = e0; e < e1; e++) {
        int s = csr_src[e];
        float nu = csr_nu[e];
        #pragma unroll
        for (int v = 0; v < V; v++) {
            float4 m = M4[s * (F / 4) + lane + 32 * v];
            acc[v].x += nu * m.x; acc[v].y += nu * m.y;
            acc[v].z += nu * m.z; acc[v].w += nu * m.w;
        }
    }
    #pragma unroll
    for (int v = 0; v < V; v++) Y4[i * (F / 4) + lane + 32 * v] = acc[v];
}

// ============ bf16 split-limb mma.sync GEMM ============
// C[M, col0+bx*128 .. +127] = op(A)[M,K] @ Bt[bx*128.., K]^T (+Cbias, relu)
// 2-limb split: a = a1 + a2 (bf16 each). Smem K-expanded triples:
//   A rows: [A1 | A1 | A2], B rows: [B1 | B2 | B1]  ->  A1B1 + A1B2 + A2B1.
// Smem rows padded to 56 bf16 (112 B): conflict-free ldmatrix.
#define ROWP 56
#define STG  14336                 // bytes per 128-row operand stage (128*56*2)
#define SMT  (4 * STG)             // 2 stages x (A,B)

__device__ __forceinline__ float4 ldg_tile(const float* __restrict__ G, int ld, int rows_valid,
                                           int k0, const float* __restrict__ bias,
                                           int r, int q) {
    float4 v = make_float4(0.f, 0.f, 0.f, 0.f);
    if (r < rows_valid) {
        v = *reinterpret_cast<const float4*>(&G[(size_t)r * ld + k0 + q * 4]);
        if (bias) {
            float4 bb = *reinterpret_cast<const float4*>(&bias[k0 + q * 4]);
            v.x = fmaxf(v.x + bb.x, 0.f); v.y = fmaxf(v.y + bb.y, 0.f);
            v.z = fmaxf(v.z + bb.z, 0.f); v.w = fmaxf(v.w + bb.w, 0.f);
        }
    }
    return v;
}

__device__ __forceinline__ void st_limbs(char* smbase, int r, int q, float4 v, bool isA) {
    __nv_bfloat162 h1a = __floats2bfloat162_rn(v.x, v.y);
    __nv_bfloat162 h1b = __floats2bfloat162_rn(v.z, v.w);
    float rx = v.x - __bfloat162float(h1a.x);
    float ry = v.y - __bfloat162float(h1a.y);
    float rz = v.z - __bfloat162float(h1b.x);
    float rw = v.w - __bfloat162float(h1b.y);
    __nv_bfloat162 h2a = __floats2bfloat162_rn(rx, ry);
    __nv_bfloat162 h2b = __floats2bfloat162_rn(rz, rw);
    uint32_t u1a = *reinterpret_cast<uint32_t*>(&h1a);
    uint32_t u1b = *reinterpret_cast<uint32_t*>(&h1b);
    uint32_t u2a = *reinterpret_cast<uint32_t*>(&h2a);
    uint32_t u2b = *reinterpret_cast<uint32_t*>(&h2b);
    char* pr = smbase + (size_t)r * (ROWP * 2) + q * 8;
    // region 0 (k 0-15)
    *reinterpret_cast<uint32_t*>(pr)      = u1a;
    *reinterpret_cast<uint32_t*>(pr + 4)  = u1b;
    // region 1 (k 16-31): A1 or B2
    *reinterpret_cast<uint32_t*>(pr + 32) = isA ? u1a : u2a;
    *reinterpret_cast<uint32_t*>(pr + 36) = isA ? u1b : u2b;
    // region 2 (k 32-47): A2 or B1
    *reinterpret_cast<uint32_t*>(pr + 64) = isA ? u2a : u1a;
    *reinterpret_cast<uint32_t*>(pr + 68) = isA ? u2b : u1b;
}

__global__ __launch_bounds__(256, 2)
void k_mmagemm(const float* __restrict__ A, int lda, const float* __restrict__ Abias,
               const float* __restrict__ Bt, const float* __restrict__ Cbias,
               float* __restrict__ C, int ldc, int col0, int M, int K, int crelu)
{
    extern __shared__ __align__(128) char sm[];
    uint32_t smu = smem_u32(sm);
    int tid = threadIdx.x;
    int row0 = blockIdx.y * 128;
    int n0 = blockIdx.x * 128;

    const float* Arow = A + (size_t)row0 * lda;
    const float* Bt0 = Bt + (size_t)n0 * K;
    int rowsA = M - row0;
    int nc = K >> 4;

    int w = tid >> 5, lane = tid & 31;
    int wm = w & 1, wn = w >> 1;      // warp tile: rows wm*64+0..63, cols wn*32+0..31
    int j = lane >> 3, rr = lane & 7;
    uint32_t a_off[4], b_off[2];
    #pragma unroll
    for (int mb = 0; mb < 4; mb++)
        a_off[mb] = 2u * ((wm * 64 + mb * 16 + (j & 1) * 8 + rr) * ROWP + (j >> 1) * 8);
    #pragma unroll
    for (int nbp = 0; nbp < 2; nbp++)
        b_off[nbp] = 2u * ((wn * 32 + nbp * 16 + (j & 1) * 8 + rr) * ROWP + (j >> 1) * 8);

    int lr = tid >> 2, lq = tid & 3;          // loader slot 0: rows 0..63
    int lr2 = lr + 64;                        // loader slot 1: rows 64..127

    float acc[4][4][4];
    #pragma unroll
    for (int a = 0; a < 4; a++)
        #pragma unroll
        for (int b = 0; b < 4; b++)
            #pragma unroll
            for (int c = 0; c < 4; c++) acc[a][b][c] = 0.f;

    // prologue: chunk 0 -> stage 0
    {
        float4 va0 = ldg_tile(Arow, lda, rowsA, 0, Abias, lr, lq);
        float4 va1 = ldg_tile(Arow, lda, rowsA, 0, Abias, lr2, lq);
        float4 vb0 = ldg_tile(Bt0, K, 128, 0, nullptr, lr, lq);
        float4 vb1 = ldg_tile(Bt0, K, 128, 0, nullptr, lr2, lq);
        st_limbs(sm, lr, lq, va0, true);
        st_limbs(sm, lr2, lq, va1, true);
        st_limbs(sm + STG, lr, lq, vb0, false);
        st_limbs(sm + STG, lr2, lq, vb1, false);
    }
    __syncthreads();

    for (int c = 0; c < nc; c++) {
        int cur = c & 1;
        bool has = (c + 1 < nc);
        float4 va0, va1, vb0, vb1;
        if (has) {
            int k0 = (c + 1) << 4;
            va0 = ldg_tile(Arow, lda, rowsA, k0, Abias, lr, lq);
            va1 = ldg_tile(Arow, lda, rowsA, k0, Abias, lr2, lq);
            vb0 = ldg_tile(Bt0, K, 128, k0, nullptr, lr, lq);
            vb1 = ldg_tile(Bt0, K, 128, k0, nullptr, lr2, lq);
        }

        uint32_t smA = smu + cur * 2 * STG;
        uint32_t smB = smA + STG;
        #pragma unroll
        for (int ks = 0; ks < 3; ks++) {
            uint32_t ko = ks * 32;   // 16 bf16 = 32 bytes
            uint32_t af[4][4], bf[2][4];
            #pragma unroll
            for (int mb = 0; mb < 4; mb++)
                ldsm4(af[mb][0], af[mb][1], af[mb][2], af[mb][3], smA + a_off[mb] + ko);
            #pragma unroll
            for (int nbp = 0; nbp < 2; nbp++)
                ldsm4(bf[nbp][0], bf[nbp][1], bf[nbp][2], bf[nbp][3], smB + b_off[nbp] + ko);
            #pragma unroll
            for (int mb = 0; mb < 4; mb++)
                #pragma unroll
                for (int nb = 0; nb < 4; nb++)
                    mma_bf16(acc[mb][nb], af[mb], bf[nb >> 1][nb & 1], bf[nb >> 1][2 + (nb & 1)]);
        }
        __syncthreads();
        if (has) {
            int nxt = cur ^ 1;
            char* dA = sm + nxt * 2 * STG;
            st_limbs(dA, lr, lq, va0, true);
            st_limbs(dA, lr2, lq, va1, true);
            st_limbs(dA + STG, lr, lq, vb0, false);
            st_limbs(dA + STG, lr2, lq, vb1, false);
        }
        __syncthreads();
    }

    // epilogue
    int g = lane >> 2, cq = lane & 3;
    #pragma unroll
    for (int mb = 0; mb < 4; mb++) {
        #pragma unroll
        for (int nb = 0; nb < 4; nb++) {
            int bcol = n0 + wn * 32 + nb * 8 + 2 * cq;
            int ccol = col0 + bcol;
            float bx = 0.f, by = 0.f;
            if (Cbias) { bx = Cbias[bcol]; by = Cbias[bcol + 1]; }
            float v0 = acc[mb][nb][0] + bx, v1 = acc[mb][nb][1] + by;
            float v2 = acc[mb][nb][2] + bx, v3 = acc[mb][nb][3] + by;
            if (crelu) {
                v0 = fmaxf(v0, 0.f); v1 = fmaxf(v1, 0.f);
                v2 = fmaxf(v2, 0.f); v3 = fmaxf(v3, 0.f);
            }
            int r0 = row0 + wm * 64 + mb * 16 + g;
            if (r0 < M)
                *reinterpret_cast<float2*>(&C[(size_t)r0 * ldc + ccol]) = make_float2(v0, v1);
            if (r0 + 8 < M)
                *reinterpret_cast<float2*>(&C[(size_t)(r0 + 8) * ldc + ccol]) = make_float2(v2, v3);
        }
    }
}

// ---------------- pooling ----------------
__global__ void k_pool_init(float* psum, unsigned* pmax, float* pcnt) {
    int i = blockIdx.x * blockDim.x + threadIdx.x;
    if (i < NG * DD) { psum[i] = 0.0f; pmax[i] = 0x007fffffu; }
    if (i < NG) pcnt[i] = 0.0f;
}

#define POOL_CHUNK 256
__global__ void k_pool(const float* __restrict__ Y3, const float* __restrict__ b3,
                       const int* __restrict__ batch,
                       float* psum, unsigned* pmax, float* pcnt) {
    int j = threadIdx.x;
    int i0 = blockIdx.x * POOL_CHUNK;
    int iend = min(i0 + POOL_CHUNK, NN);
    float bj = b3[j];
    int cur = -1;
    float s = 0.0f, m = __int_as_float(0xff800000), cnt = 0.0f;
    for (int i = i0; i < iend; i++) {
        int g = batch[i];
        if (g != cur) {
            if (cur >= 0) {
                atomicAdd(&psum[cur * DD + j], s);
                atomicMax(&pmax[cur * DD + j], fenc(m));
                if (j == 0) atomicAdd(&pcnt[cur], cnt);
            }
            cur = g; s = 0.0f; m = __int_as_float(0xff800000); cnt = 0.0f;
        }
        float y = Y3[(size_t)i * DD + j] + bj;
        s += y;
        m = fmaxf(m, y);
        cnt += 1.0f;
    }
    if (cur >= 0) {
        atomicAdd(&psum[cur * DD + j], s);
        atomicMax(&pmax[cur * DD + j], fenc(m));
        if (j == 0) atomicAdd(&pcnt[cur], cnt);
    }
}

// ---------------- MLP head ----------------
__global__ void k_mlp(const float* __restrict__ Wm1, const float* __restrict__ bm1,
                      const float* __restrict__ Wm2, const float* __restrict__ bm2,
                      const float* __restrict__ psum, const unsigned* __restrict__ pmax,
                      const float* __restrict__ pcnt, float* __restrict__ out) {
    int g = threadIdx.x;
    if (g >= NG) return;
    float cnt = pcnt[g];
    float inv = 1.0f / fmaxf(cnt, 1.0f);
    float hid[8];
    #pragma unroll
    for (int h = 0; h < 8; h++) hid[h] = bm1[h];
    for (int j = 0; j < DD; j++) {
        float mean = psum[g * DD + j] * inv;
        #pragma unroll
        for (int h = 0; h < 8; h++) hid[h] += mean * Wm1[j * 8 + h];
    }
    for (int j = 0; j < DD; j++) {
        float mx = (cnt > 0.0f) ? fdec(pmax[g * DD + j]) : 0.0f;
        #pragma unroll
        for (int h = 0; h < 8; h++) hid[h] += mx * Wm1[(DD + j) * 8 + h];
    }
    #pragma unroll
    for (int h = 0; h < 8; h++) hid[h] = fmaxf(hid[h], 0.0f);
    #pragma unroll
    for (int c = 0; c < 2; c++) {
        float o = bm2[c];
        #pragma unroll
        for (int h = 0; h < 8; h++) o += hid[h] * Wm2[h * 2 + c];
        out[g * 2 + c] = o;
    }
}

// ---------------- driver ----------------
extern "C" void kernel_launch(void* const* d_in, const int* in_sizes, int n_in,
                              void* d_out, int out_size) {
    const float* x     = (const float*)d_in[0];
    const int*   ei    = (const int*)d_in[1];
    const float* ea    = (const float*)d_in[2];
    const int*   batch = (const int*)d_in[3];
    const float* W1[4] = {(const float*)d_in[4], (const float*)d_in[6],
                          (const float*)d_in[8], (const float*)d_in[10]};
    const float* b1[4] = {(const float*)d_in[5], (const float*)d_in[7],
                          (const float*)d_in[9], (const float*)d_in[11]};
    const float* W2  = (const float*)d_in[12];
    const float* b2  = (const float*)d_in[13];
    const float* W3  = (const float*)d_in[14];
    const float* b3  = (const float*)d_in[15];
    const float* Wm1 = (const float*)d_in[16];
    const float* bm1 = (const float*)d_in[17];
    const float* Wm2 = (const float*)d_in[18];
    const float* bm2 = (const float*)d_in[19];
    float* out = (float*)d_out;

    float *dis, *z, *H, *M2, *Y2, *M3, *Y3, *psum, *pcnt, *csr_nu;
    float *Wt1, *Wt2, *Wt3;
    int *cnt, *cursor, *rowstart, *bsum, *csr_src;
    float4* csr_n4;
    unsigned* pmax;
    cudaGetSymbolAddress((void**)&dis,      g_dis);
    cudaGetSymbolAddress((void**)&cnt,      g_cnt);
    cudaGetSymbolAddress((void**)&cursor,   g_cursor);
    cudaGetSymbolAddress((void**)&rowstart, g_rowstart);
    cudaGetSymbolAddress((void**)&bsum,     g_bsum);
    cudaGetSymbolAddress((void**)&csr_src,  g_csr_src);
    cudaGetSymbolAddress((void**)&csr_n4,   g_csr_n4);
    cudaGetSymbolAddress((void**)&csr_nu,   g_csr_nu);
    cudaGetSymbolAddress((void**)&z,        g_z);
    cudaGetSymbolAddress((void**)&H,        g_H);
    cudaGetSymbolAddress((void**)&M2,       g_M2);
    cudaGetSymbolAddress((void**)&Y2,       g_Y2);
    cudaGetSymbolAddress((void**)&M3,       g_M3);
    cudaGetSymbolAddress((void**)&Y3,       g_Y3);
    cudaGetSymbolAddress((void**)&Wt1,      g_Wt1);
    cudaGetSymbolAddress((void**)&Wt2,      g_Wt2);
    cudaGetSymbolAddress((void**)&Wt3,      g_Wt3);
    cudaGetSymbolAddress((void**)&psum,     g_psum);
    cudaGetSymbolAddress((void**)&pmax,     g_pmax);
    cudaGetSymbolAddress((void**)&pcnt,     g_pcnt);

    cudaFuncSetAttribute(k_mmagemm, cudaFuncAttributeMaxDynamicSharedMemorySize, SMT);

    const int NB = (NN + 1023) / 1024;
    const int MT = (NN + 127) / 128;   // 391

    // 0. weight transposes
    for (int k = 0; k < 4; k++)
        k_tr<<<(DD * DD + 255) / 256, 256>>>(W1[k], Wt1 + k * DD * DD, DD, DD);
    k_tr<<<(4 * DD * 2 * DD + 255) / 256, 256>>>(W2, Wt2, 4 * DD, 2 * DD);
    k_tr<<<(2 * DD * DD + 255) / 256, 256>>>(W3, Wt3, 2 * DD, DD);

    // 1. degrees + CSR
    k_init<<<(5 * NN + 255) / 256, 256>>>(dis, cnt, cursor);
    k_deg_edges<<<(NE + 255) / 256, 256>>>(ei, ea, dis, cnt);
    k_rsqrt<<<(5 * NN + 255) / 256, 256>>>(dis);
    k_scan_block<<<NB, 1024>>>(cnt, rowstart, bsum);
    k_scan_top<<<1, 32>>>(bsum, NB);
    k_scan_add<<<NB, 1024>>>(rowstart, bsum);
    k_csr_fill<<<(NE + 255) / 256, 256>>>(ei, ea, dis, rowstart, cursor,
                                          csr_src, csr_n4, csr_nu);

    // 2. conv1 aggregation of x:  z_k = S_k x
    k_gather_z<<<(NN * 32 + 255) / 256, 256>>>(
        (const float4*)x, dis, rowstart, csr_src, csr_n4, (float4*)z);

    // 3. conv1 GEMMs: H[:, k*128:(k+1)*128] = relu(z_k @ W1k + b1k)
    for (int k = 0; k < 4; k++) {
        k_mmagemm<<<dim3(1, MT), 256, SMT>>>(
            z + (size_t)k * NN * DD, DD, nullptr, Wt1 + k * DD * DD,
            b1[k], H, 4 * DD, k * DD, NN, DD, 1);
    }

    // 4. conv2: M2 = H @ W2, then aggregate
    k_mmagemm<<<dim3(2, MT), 256, SMT>>>(
        H, 4 * DD, nullptr, Wt2, nullptr, M2, 2 * DD, 0, NN, 4 * DD, 0);
    k_gather_u<256><<<(NN * 32 + 255) / 256, 256>>>(
        (const float4*)M2, dis, rowstart, csr_src, csr_nu, (float4*)Y2);

    // 5. conv3: M3 = relu(Y2 + b2) @ W3, then aggregate
    k_mmagemm<<<dim3(1, MT), 256, SMT>>>(
        Y2, 2 * DD, b2, Wt3, nullptr, M3, DD, 0, NN, 2 * DD, 0);
    k_gather_u<128><<<(NN * 32 + 255) / 256, 256>>>(
        (const float4*)M3, dis, rowstart, csr_src, csr_nu, (float4*)Y3);

    // 6. pooling (b3 folded in) + MLP head
    k_pool_init<<<(NG * DD + 255) / 256, 256>>>(psum, pmax, pcnt);
    k_pool<<<(NN + POOL_CHUNK - 1) / POOL_CHUNK, DD>>>(Y3, b3, batch, psum, pmax, pcnt);
    k_mlp<<<1, 64>>>(Wm1, bm1, Wm2, bm2, psum, pmax, pcnt, out);
}

// round 12
// speedup vs baseline: 2.8828x; 1.1861x over previous
#include <cuda_runtime.h>
#include <cuda_bf16.h>
#include <cuda_fp16.h>
#include <cstdint>

#define NN 50000
#define NE 600000
#define DD 128
#define NG 64

// ---------------- scratch (static __device__, allocation-free) ----------------
static __device__ float    g_dis[5 * NN];        // rsqrt degrees: k=0..3 weighted, 4 unweighted
static __device__ int      g_cursor[NN];
static __device__ int      g_rowstart[NN + 1];
static __device__ int      g_bsum[64];
static __device__ int      g_csr_src[NE];
static __device__ float4   g_csr_n4[NE];
static __device__ float    g_csr_nu[NE];
static __device__ __align__(16) __half g_xh[NN * DD];        // fp16 x
static __device__ __align__(16) __half g_zh[4 * NN * DD];    // fp16 z_k = S_k x
static __device__ __align__(16) __half g_Hh[NN * 4 * DD];    // fp16 concat relu(z W + b)
static __device__ __align__(16) __half g_M2h[NN * 2 * DD];   // fp16 H @ W2
static __device__ __align__(16) __half g_Y2h[NN * 2 * DD];   // fp16 S_u M2
static __device__ __align__(16) __half g_M3h[NN * DD];       // fp16 relu(Y2+b2) @ W3
static __device__ float    g_Y3[NN * DD];                    // fp32 S_u M3 (pool input)
static __device__ float    g_Wt1[4 * DD * DD];
static __device__ float    g_Wt2[2 * DD * 4 * DD];
static __device__ float    g_Wt3[DD * 2 * DD];
static __device__ float    g_psum[NG * DD];
static __device__ unsigned g_pmax[NG * DD];
static __device__ float    g_pcnt[NG];

// ---------------- small helpers ----------------
__device__ __forceinline__ unsigned fenc(float f) {
    unsigned b = __float_as_uint(f);
    return (b & 0x80000000u) ? ~b : (b | 0x80000000u);
}
__device__ __forceinline__ float fdec(unsigned u) {
    return (u & 0x80000000u) ? __uint_as_float(u & 0x7fffffffu) : __uint_as_float(~u);
}
__device__ __forceinline__ uint32_t smem_u32(const void* p) {
    uint32_t a;
    asm("{ .reg .u64 t; cvta.to.shared.u64 t, %1; cvt.u32.u64 %0, t; }" : "=r"(a) : "l"(p));
    return a;
}
__device__ __forceinline__ void ldsm4(uint32_t& r0, uint32_t& r1, uint32_t& r2, uint32_t& r3,
                                      uint32_t addr) {
    asm volatile("ldmatrix.sync.aligned.m8n8.x4.shared.b16 {%0,%1,%2,%3}, [%4];"
                 : "=r"(r0), "=r"(r1), "=r"(r2), "=r"(r3) : "r"(addr));
}
__device__ __forceinline__ void mma_bf16(float* c, const uint32_t* a, uint32_t b0, uint32_t b1) {
    asm volatile(
        "mma.sync.aligned.m16n8k16.row.col.f32.bf16.bf16.f32 "
        "{%0,%1,%2,%3}, {%4,%5,%6,%7}, {%8,%9}, {%0,%1,%2,%3};"
        : "+f"(c[0]), "+f"(c[1]), "+f"(c[2]), "+f"(c[3])
        : "r"(a[0]), "r"(a[1]), "r"(a[2]), "r"(a[3]), "r"(b0), "r"(b1));
}

// ---------------- prep: x -> fp16, weight transposes ----------------
__global__ void k_x2h(const float4* __restrict__ x4, uint4* __restrict__ xh4) {
    int i = blockIdx.x * blockDim.x + threadIdx.x;
    if (i >= NN * 16) return;
    float4 a = x4[2 * i], b = x4[2 * i + 1];
    __half2 h0 = __floats2half2_rn(a.x, a.y), h1 = __floats2half2_rn(a.z, a.w);
    __half2 h2 = __floats2half2_rn(b.x, b.y), h3 = __floats2half2_rn(b.z, b.w);
    uint4 u;
    u.x = *reinterpret_cast<uint32_t*>(&h0); u.y = *reinterpret_cast<uint32_t*>(&h1);
    u.z = *reinterpret_cast<uint32_t*>(&h2); u.w = *reinterpret_cast<uint32_t*>(&h3);
    xh4[i] = u;
}

__global__ void k_tr_all(const float* __restrict__ W1A, const float* __restrict__ W1B,
                         const float* __restrict__ W1C, const float* __restrict__ W1D,
                         const float* __restrict__ W2, const float* __restrict__ W3,
                         float* __restrict__ Wt1, float* __restrict__ Wt2,
                         float* __restrict__ Wt3) {
    int i = blockIdx.x * blockDim.x + threadIdx.x;
    if (i < 4 * DD * DD) {
        int wsel = i >> 14, rem = i & 16383;
        int k = rem >> 7, n = rem & 127;
        const float* W = (wsel == 0) ? W1A : (wsel == 1) ? W1B : (wsel == 2) ? W1C : W1D;
        Wt1[wsel * DD * DD + n * DD + k] = W[rem];
    } else if (i < 4 * DD * DD + 4 * DD * 2 * DD) {
        int rem = i - 4 * DD * DD;           // K=512, N=256
        int k = rem >> 8, n = rem & 255;
        Wt2[n * 512 + k] = W2[rem];
    } else if (i < 4 * DD * DD + 4 * DD * 2 * DD + 2 * DD * DD) {
        int rem = i - 4 * DD * DD - 4 * DD * 2 * DD;  // K=256, N=128
        int k = rem >> 7, n = rem & 127;
        Wt3[n * 256 + k] = W3[rem];
    }
}

// ---------------- degree + CSR build ----------------
__global__ void k_init(float* dis, int* cursor) {
    int i = blockIdx.x * blockDim.x + threadIdx.x;
    if (i < 5 * NN) dis[i] = 1.0f;
    if (i < NN) cursor[i] = 0;
}

__global__ void k_deg_edges(const int* __restrict__ ei, const float* __restrict__ ea,
                            float* dis) {
    int e = blockIdx.x * blockDim.x + threadIdx.x;
    if (e >= NE) return;
    int d = ei[NE + e];
    float4 w = *reinterpret_cast<const float4*>(&ea[e * 4]);
    atomicAdd(&dis[0 * NN + d], w.x);
    atomicAdd(&dis[1 * NN + d], w.y);
    atomicAdd(&dis[2 * NN + d], w.z);
    atomicAdd(&dis[3 * NN + d], w.w);
    atomicAdd(&dis[4 * NN + d], 1.0f);
}

__global__ void k_rsqrt(float* dis) {
    int i = blockIdx.x * blockDim.x + threadIdx.x;
    if (i < 5 * NN) dis[i] = rsqrtf(dis[i]);
}

// in-degree derived from unweighted degree (init 1 + 1 per edge) -> no cnt atomics
__global__ void k_scan_block(const float* __restrict__ deg, int* __restrict__ rowstart,
                             int* __restrict__ bsum) {
    __shared__ int sh[1024];
    int i = blockIdx.x * 1024 + threadIdx.x;
    int v = (i < NN) ? (__float2int_rn(deg[4 * NN + i]) - 1) : 0;
    sh[threadIdx.x] = v;
    __syncthreads();
    #pragma unroll
    for (int off = 1; off < 1024; off <<= 1) {
        int t = (threadIdx.x >= off) ? sh[threadIdx.x - off] : 0;
        __syncthreads();
        sh[threadIdx.x] += t;
        __syncthreads();
    }
    if (i < NN) rowstart[i] = sh[threadIdx.x] - v;
    if (threadIdx.x == 1023) bsum[blockIdx.x] = sh[1023];
}

__global__ void k_scan_top(int* bsum, int nb) {
    if (threadIdx.x == 0) {
        int run = 0;
        for (int b = 0; b < nb; b++) { int t = bsum[b]; bsum[b] = run; run += t; }
    }
}

__global__ void k_scan_add(int* rowstart, const int* __restrict__ bsum) {
    int i = blockIdx.x * 1024 + threadIdx.x;
    if (i < NN) rowstart[i] += bsum[blockIdx.x];
    if (blockIdx.x == 0 && threadIdx.x == 0) rowstart[NN] = NE;
}

__global__ void k_csr_fill(const int* __restrict__ ei, const float* __restrict__ ea,
                           const float* __restrict__ dis, const int* __restrict__ rowstart,
                           int* cursor, int* __restrict__ csr_src,
                           float4* __restrict__ csr_n4, float* __restrict__ csr_nu) {
    int e = blockIdx.x * blockDim.x + threadIdx.x;
    if (e >= NE) return;
    int s = ei[e], d = ei[NE + e];
    int pos = rowstart[d] + atomicAdd(&cursor[d], 1);
    csr_src[pos] = s;
    float4 w = *reinterpret_cast<const float4*>(&ea[e * 4]);
    float4 n;
    n.x = dis[0 * NN + s] * w.x * dis[0 * NN + d];
    n.y = dis[1 * NN + s] * w.y * dis[1 * NN + d];
    n.z = dis[2 * NN + s] * w.z * dis[2 * NN + d];
    n.w = dis[3 * NN + s] * w.w * dis[3 * NN + d];
    csr_n4[pos] = n;
    csr_nu[pos] = dis[4 * NN + s] * dis[4 * NN + d];
}

// ---------------- gather aggregations (fp16 in, no atomics) ----------------
__global__ void k_gather_z_h(const uint2* __restrict__ xh2, const float* __restrict__ dis,
                             const int* __restrict__ rowstart, const int* __restrict__ csr_src,
                             const float4* __restrict__ csr_n4, uint2* __restrict__ zh2) {
    int warp = (blockIdx.x * blockDim.x + threadIdx.x) >> 5;
    int lane = threadIdx.x & 31;
    if (warp >= NN) return;
    int i = warp;
    uint2 u = xh2[i * 32 + lane];
    float2 f0 = __half22float2(*reinterpret_cast<__half2*>(&u.x));
    float2 f1 = __half22float2(*reinterpret_cast<__half2*>(&u.y));
    float4 xv = make_float4(f0.x, f0.y, f1.x, f1.y);
    float d0 = dis[i], d1 = dis[NN + i], d2 = dis[2 * NN + i], d3 = dis[3 * NN + i];
    float s0 = d0 * d0, s1 = d1 * d1, s2 = d2 * d2, s3 = d3 * d3;
    float4 a0 = make_float4(xv.x * s0, xv.y * s0, xv.z * s0, xv.w * s0);
    float4 a1 = make_float4(xv.x * s1, xv.y * s1, xv.z * s1, xv.w * s1);
    float4 a2 = make_float4(xv.x * s2, xv.y * s2, xv.z * s2, xv.w * s2);
    float4 a3 = make_float4(xv.x * s3, xv.y * s3, xv.z * s3, xv.w * s3);
    int e0 = rowstart[i], e1 = rowstart[i + 1];
    for (int e = e0; e < e1; e++) {
        int s = csr_src[e];
        float4 n = csr_n4[e];
        uint2 us = xh2[s * 32 + lane];
        float2 g0 = __half22float2(*reinterpret_cast<__half2*>(&us.x));
        float2 g1 = __half22float2(*reinterpret_cast<__half2*>(&us.y));
        float4 xs = make_float4(g0.x, g0.y, g1.x, g1.y);
        a0.x += n.x * xs.x; a0.y += n.x * xs.y; a0.z += n.x * xs.z; a0.w += n.x * xs.w;
        a1.x += n.y * xs.x; a1.y += n.y * xs.y; a1.z += n.y * xs.z; a1.w += n.y * xs.w;
        a2.x += n.z * xs.x; a2.y += n.z * xs.y; a2.z += n.z * xs.z; a2.w += n.z * xs.w;
        a3.x += n.w * xs.x; a3.y += n.w * xs.y; a3.z += n.w * xs.z; a3.w += n.w * xs.w;
    }
    int base = i * 32 + lane;
    float4 aa[4] = {a0, a1, a2, a3};
    #pragma unroll
    for (int k = 0; k < 4; k++) {
        __half2 h0 = __floats2half2_rn(aa[k].x, aa[k].y);
        __half2 h1 = __floats2half2_rn(aa[k].z, aa[k].w);
        uint2 o;
        o.x = *reinterpret_cast<uint32_t*>(&h0);
        o.y = *reinterpret_cast<uint32_t*>(&h1);
        zh2[(size_t)k * NN * 32 + base] = o;
    }
}

template<int HL>
__device__ __forceinline__ void ldhalf(const __half* p, float* v) {
    if (HL == 4) {
        uint2 u = *reinterpret_cast<const uint2*>(p);
        float2 a = __half22float2(*reinterpret_cast<__half2*>(&u.x));
        float2 b = __half22float2(*reinterpret_cast<__half2*>(&u.y));
        v[0] = a.x; v[1] = a.y; v[2] = b.x; v[3] = b.y;
    } else {
        uint4 u = *reinterpret_cast<const uint4*>(p);
        const __half2* h = reinterpret_cast<const __half2*>(&u);
        #pragma unroll
        for (int t = 0; t < 4; t++) {
            float2 f = __half22float2(h[t]);
            v[2 * t] = f.x; v[2 * t + 1] = f.y;
        }
    }
}

// Y[i] = dis_u[i]^2 * M[i] + sum_e nu(e) * M[src(e)]; M fp16, acc fp32.
// OUTF32: 1 -> fp32 output (Y3 for pooling), 0 -> fp16 output.
template<int F, int OUTF32>
__global__ void k_gather_u_h(const __half* __restrict__ Mh, const float* __restrict__ dis,
                             const int* __restrict__ rowstart, const int* __restrict__ csr_src,
                             const float* __restrict__ csr_nu, void* __restrict__ Yout) {
    constexpr int HL = F / 32;
    int warp = (blockIdx.x * blockDim.x + threadIdx.x) >> 5;
    int lane = threadIdx.x & 31;
    if (warp >= NN) return;
    int i = warp;
    float du = dis[4 * NN + i];
    float s0 = du * du;
    float acc[HL], v[HL];
    ldhalf<HL>(Mh + (size_t)i * F + lane * HL, v);
    #pragma unroll
    for (int t = 0; t < HL; t++) acc[t] = v[t] * s0;
    int e0 = rowstart[i], e1 = rowstart[i + 1];
    for (int e = e0; e < e1; e++) {
        int s = csr_src[e];
        float nu = csr_nu[e];
        ldhalf<HL>(Mh + (size_t)s * F + lane * HL, v);
        #pragma unroll
        for (int t = 0; t < HL; t++) acc[t] += nu * v[t];
    }
    if (OUTF32) {
        float* Y = (float*)Yout;
        #pragma unroll
        for (int q = 0; q < HL / 4; q++)
            *reinterpret_cast<float4*>(&Y[(size_t)i * F + lane * HL + 4 * q]) =
                make_float4(acc[4 * q], acc[4 * q + 1], acc[4 * q + 2], acc[4 * q + 3]);
    } else {
        __half* Yh = (__half*)Yout;
        uint32_t pk[HL / 2];
        #pragma unroll
        for (int t = 0; t < HL / 2; t++) {
            __half2 h = __floats2half2_rn(acc[2 * t], acc[2 * t + 1]);
            pk[t] = *reinterpret_cast<uint32_t*>(&h);
        }
        if (HL == 4)
            *reinterpret_cast<uint2*>(Yh + (size_t)i * F + lane * HL) = make_uint2(pk[0], pk[1]);
        else
            *reinterpret_cast<uint4*>(Yh + (size_t)i * F + lane * HL) =
                make_uint4(pk[0], pk[1], pk[2], pk[3]);
    }
}

// ============ bf16 split-limb mma.sync GEMM, fp16 activations ============
// C = op(A)@Bt^T; A fp16 (exactly representable as bf16hi+bf16lo limbs), B fp32.
// K-expanded smem triples: A rows [A1|A1|A2], B rows [B1|B2|B1].
#define ROWP 56
#define STG  14336
#define SMT  (4 * STG)

__device__ __forceinline__ void ldA8(const __half* __restrict__ Arow, int lda, int rowsA,
                                     int k0, const float* __restrict__ Abias,
                                     int lr, int lq, float* f) {
    if (lr < rowsA) {
        uint4 u = *reinterpret_cast<const uint4*>(Arow + (size_t)lr * lda + k0 + lq * 8);
        const __half2* h = reinterpret_cast<const __half2*>(&u);
        #pragma unroll
        for (int t = 0; t < 4; t++) {
            float2 p = __half22float2(h[t]);
            f[2 * t] = p.x; f[2 * t + 1] = p.y;
        }
        if (Abias) {
            float4 b0 = *reinterpret_cast<const float4*>(Abias + k0 + lq * 8);
            float4 b1 = *reinterpret_cast<const float4*>(Abias + k0 + lq * 8 + 4);
            f[0] = fmaxf(f[0] + b0.x, 0.f); f[1] = fmaxf(f[1] + b0.y, 0.f);
            f[2] = fmaxf(f[2] + b0.z, 0.f); f[3] = fmaxf(f[3] + b0.w, 0.f);
            f[4] = fmaxf(f[4] + b1.x, 0.f); f[5] = fmaxf(f[5] + b1.y, 0.f);
            f[6] = fmaxf(f[6] + b1.z, 0.f); f[7] = fmaxf(f[7] + b1.w, 0.f);
        }
    } else {
        #pragma unroll
        for (int t = 0; t < 8; t++) f[t] = 0.f;
    }
}

__device__ __forceinline__ void ldB8(const float* __restrict__ Bt0, int K, int k0,
                                     int lr, int lq, float* f) {
    float4 v0 = *reinterpret_cast<const float4*>(Bt0 + (size_t)lr * K + k0 + lq * 8);
    float4 v1 = *reinterpret_cast<const float4*>(Bt0 + (size_t)lr * K + k0 + lq * 8 + 4);
    f[0] = v0.x; f[1] = v0.y; f[2] = v0.z; f[3] = v0.w;
    f[4] = v1.x; f[5] = v1.y; f[6] = v1.z; f[7] = v1.w;
}

__device__ __forceinline__ void split8(const float* f, uint4& hi, uint4& lo) {
    uint32_t hw[4], lw[4];
    #pragma unroll
    for (int t = 0; t < 4; t++) {
        __nv_bfloat162 h2 = __floats2bfloat162_rn(f[2 * t], f[2 * t + 1]);
        hw[t] = *reinterpret_cast<uint32_t*>(&h2);
        float lx = f[2 * t] - __bfloat162float(h2.x);
        float ly = f[2 * t + 1] - __bfloat162float(h2.y);
        __nv_bfloat162 l2 = __floats2bfloat162_rn(lx, ly);
        lw[t] = *reinterpret_cast<uint32_t*>(&l2);
    }
    hi = make_uint4(hw[0], hw[1], hw[2], hw[3]);
    lo = make_uint4(lw[0], lw[1], lw[2], lw[3]);
}

__device__ __forceinline__ void stA8(char* smbase, int lr, int lq, const float* f) {
    uint4 hi, lo; split8(f, hi, lo);
    char* pr = smbase + (size_t)lr * (ROWP * 2) + lq * 16;
    *reinterpret_cast<uint4*>(pr)      = hi;
    *reinterpret_cast<uint4*>(pr + 32) = hi;
    *reinterpret_cast<uint4*>(pr + 64) = lo;
}
__device__ __forceinline__ void stB8(char* smbase, int lr, int lq, const float* f) {
    uint4 hi, lo; split8(f, hi, lo);
    char* pr = smbase + (size_t)lr * (ROWP * 2) + lq * 16;
    *reinterpret_cast<uint4*>(pr)      = hi;
    *reinterpret_cast<uint4*>(pr + 32) = lo;
    *reinterpret_cast<uint4*>(pr + 64) = hi;
}

__device__ __forceinline__ void gemm_body(
    const __half* __restrict__ Ah, int lda, const float* __restrict__ Abias,
    const float* __restrict__ Bt0, const float* __restrict__ Cbias,
    __half* __restrict__ Ch, int ldc, int ccol0, int M, int K, int crelu, int row0)
{
    extern __shared__ __align__(128) char sm[];
    uint32_t smu = smem_u32(sm);
    int tid = threadIdx.x;
    const __half* Arow = Ah + (size_t)row0 * lda;
    int rowsA = M - row0;
    int nc = K >> 4;

    int w = tid >> 5, lane = tid & 31;
    int wm = w & 1, wn = w >> 1;
    int j = lane >> 3, rr = lane & 7;
    uint32_t a_off[4], b_off[2];
    #pragma unroll
    for (int mb = 0; mb < 4; mb++)
        a_off[mb] = 2u * ((wm * 64 + mb * 16 + (j & 1) * 8 + rr) * ROWP + (j >> 1) * 8);
    #pragma unroll
    for (int nbp = 0; nbp < 2; nbp++)
        b_off[nbp] = 2u * ((wn * 32 + nbp * 16 + (j & 1) * 8 + rr) * ROWP + (j >> 1) * 8);

    int lr = tid >> 1, lq = tid & 1;
    float acc[4][4][4];
    #pragma unroll
    for (int a = 0; a < 4; a++)
        #pragma unroll
        for (int b = 0; b < 4; b++)
            #pragma unroll
            for (int c = 0; c < 4; c++) acc[a][b][c] = 0.f;

    float fa[8], fb[8];
    ldA8(Arow, lda, rowsA, 0, Abias, lr, lq, fa);
    ldB8(Bt0, K, 0, lr, lq, fb);
    stA8(sm, lr, lq, fa);
    stB8(sm + STG, lr, lq, fb);
    __syncthreads();

    for (int c = 0; c < nc; c++) {
        int cur = c & 1;
        bool has = (c + 1 < nc);
        if (has) {
            int k0 = (c + 1) << 4;
            ldA8(Arow, lda, rowsA, k0, Abias, lr, lq, fa);
            ldB8(Bt0, K, k0, lr, lq, fb);
        }
        uint32_t smA = smu + cur * 2 * STG;
        uint32_t smB = smA + STG;
        #pragma unroll
        for (int ks = 0; ks < 3; ks++) {
            uint32_t ko = ks * 32;
            uint32_t af[4][4], bf2[2][4];
            #pragma unroll
            for (int mb = 0; mb < 4; mb++)
                ldsm4(af[mb][0], af[mb][1], af[mb][2], af[mb][3], smA + a_off[mb] + ko);
            #pragma unroll
            for (int nbp = 0; nbp < 2; nbp++)
                ldsm4(bf2[nbp][0], bf2[nbp][1], bf2[nbp][2], bf2[nbp][3], smB + b_off[nbp] + ko);
            #pragma unroll
            for (int mb = 0; mb < 4; mb++)
                #pragma unroll
                for (int nb = 0; nb < 4; nb++)
                    mma_bf16(acc[mb][nb], af[mb], bf2[nb >> 1][nb & 1], bf2[nb >> 1][2 + (nb & 1)]);
        }
        __syncthreads();
        if (has) {
            char* d = sm + (cur ^ 1) * 2 * STG;
            stA8(d, lr, lq, fa);
            stB8(d + STG, lr, lq, fb);
        }
        __syncthreads();
    }

    int g = lane >> 2, cq = lane & 3;
    #pragma unroll
    for (int mb = 0; mb < 4; mb++) {
        #pragma unroll
        for (int nb = 0; nb < 4; nb++) {
            int l = wn * 32 + nb * 8 + 2 * cq;
            float bx = 0.f, by = 0.f;
            if (Cbias) { bx = Cbias[l]; by = Cbias[l + 1]; }
            float v0 = acc[mb][nb][0] + bx, v1 = acc[mb][nb][1] + by;
            float v2 = acc[mb][nb][2] + bx, v3 = acc[mb][nb][3] + by;
            if (crelu) {
                v0 = fmaxf(v0, 0.f); v1 = fmaxf(v1, 0.f);
                v2 = fmaxf(v2, 0.f); v3 = fmaxf(v3, 0.f);
            }
            int r0 = row0 + wm * 64 + mb * 16 + g;
            int ccol = ccol0 + l;
            if (r0 < M)
                *reinterpret_cast<__half2*>(Ch + (size_t)r0 * ldc + ccol) =
                    __floats2half2_rn(v0, v1);
            if (r0 + 8 < M)
                *reinterpret_cast<__half2*>(Ch + (size_t)(r0 + 8) * ldc + ccol) =
                    __floats2half2_rn(v2, v3);
        }
    }
}

__global__ __launch_bounds__(256, 2)
void k_gemm_g(const __half* __restrict__ Ah, int lda, const float* __restrict__ Abias,
              const float* __restrict__ Bt, __half* __restrict__ Ch, int ldc,
              int M, int K, int crelu) {
    int n0 = blockIdx.x * 128;
    gemm_body(Ah, lda, Abias, Bt + (size_t)n0 * K, nullptr, Ch, ldc, n0, M, K, crelu,
              blockIdx.y * 128);
}

__global__ __launch_bounds__(256, 2)
void k_gemm_c1(const __half* __restrict__ zh, const float* __restrict__ Wt1,
               const float* __restrict__ bA, const float* __restrict__ bB,
               const float* __restrict__ bC, const float* __restrict__ bD,
               __half* __restrict__ Hh, int M) {
    int k = blockIdx.x;
    const float* bias = (k == 0) ? bA : (k == 1) ? bB : (k == 2) ? bC : bD;
    gemm_body(zh + (size_t)k * NN * DD, DD, nullptr, Wt1 + (size_t)k * DD * DD, bias,
              Hh, 4 * DD, k * DD, M, DD, 1, blockIdx.y * 128);
}

// ---------------- pooling ----------------
__global__ void k_pool_init(float* psum, unsigned* pmax, float* pcnt) {
    int i = blockIdx.x * blockDim.x + threadIdx.x;
    if (i < NG * DD) { psum[i] = 0.0f; pmax[i] = 0x007fffffu; }
    if (i < NG) pcnt[i] = 0.0f;
}

#define POOL_CHUNK 256
__global__ void k_pool(const float* __restrict__ Y3, const float* __restrict__ b3,
                       const int* __restrict__ batch,
                       float* psum, unsigned* pmax, float* pcnt) {
    int j = threadIdx.x;
    int i0 = blockIdx.x * POOL_CHUNK;
    int iend = min(i0 + POOL_CHUNK, NN);
    float bj = b3[j];
    int cur = -1;
    float s = 0.0f, m = __int_as_float(0xff800000), cnt = 0.0f;
    for (int i = i0; i < iend; i++) {
        int g = batch[i];
        if (g != cur) {
            if (cur >= 0) {
                atomicAdd(&psum[cur * DD + j], s);
                atomicMax(&pmax[cur * DD + j], fenc(m));
                if (j == 0) atomicAdd(&pcnt[cur], cnt);
            }
            cur = g; s = 0.0f; m = __int_as_float(0xff800000); cnt = 0.0f;
        }
        float y = Y3[(size_t)i * DD + j] + bj;
        s += y;
        m = fmaxf(m, y);
        cnt += 1.0f;
    }
    if (cur >= 0) {
        atomicAdd(&psum[cur * DD + j], s);
        atomicMax(&pmax[cur * DD + j], fenc(m));
        if (j == 0) atomicAdd(&pcnt[cur], cnt);
    }
}

// ---------------- MLP head ----------------
__global__ void k_mlp(const float* __restrict__ Wm1, const float* __restrict__ bm1,
                      const float* __restrict__ Wm2, const float* __restrict__ bm2,
                      const float* __restrict__ psum, const unsigned* __restrict__ pmax,
                      const float* __restrict__ pcnt, float* __restrict__ out) {
    int g = threadIdx.x;
    if (g >= NG) return;
    float cnt = pcnt[g];
    float inv = 1.0f / fmaxf(cnt, 1.0f);
    float hid[8];
    #pragma unroll
    for (int h = 0; h < 8; h++) hid[h] = bm1[h];
    for (int j = 0; j < DD; j++) {
        float mean = psum[g * DD + j] * inv;
        #pragma unroll
        for (int h = 0; h < 8; h++) hid[h] += mean * Wm1[j * 8 + h];
    }
    for (int j = 0; j < DD; j++) {
        float mx = (cnt > 0.0f) ? fdec(pmax[g * DD + j]) : 0.0f;
        #pragma unroll
        for (int h = 0; h < 8; h++) hid[h] += mx * Wm1[(DD + j) * 8 + h];
    }
    #pragma unroll
    for (int h = 0; h < 8; h++) hid[h] = fmaxf(hid[h], 0.0f);
    #pragma unroll
    for (int c = 0; c < 2; c++) {
        float o = bm2[c];
        #pragma unroll
        for (int h = 0; h < 8; h++) o += hid[h] * Wm2[h * 2 + c];
        out[g * 2 + c] = o;
    }
}

// ---------------- driver ----------------
extern "C" void kernel_launch(void* const* d_in, const int* in_sizes, int n_in,
                              void* d_out, int out_size) {
    const float* x     = (const float*)d_in[0];
    const int*   ei    = (const int*)d_in[1];
    const float* ea    = (const float*)d_in[2];
    const int*   batch = (const int*)d_in[3];
    const float* W1A = (const float*)d_in[4];
    const float* b1A = (const float*)d_in[5];
    const float* W1B = (const float*)d_in[6];
    const float* b1B = (const float*)d_in[7];
    const float* W1C = (const float*)d_in[8];
    const float* b1C = (const float*)d_in[9];
    const float* W1D = (const float*)d_in[10];
    const float* b1D = (const float*)d_in[11];
    const float* W2  = (const float*)d_in[12];
    const float* b2  = (const float*)d_in[13];
    const float* W3  = (const float*)d_in[14];
    const float* b3  = (const float*)d_in[15];
    const float* Wm1 = (const float*)d_in[16];
    const float* bm1 = (const float*)d_in[17];
    const float* Wm2 = (const float*)d_in[18];
    const float* bm2 = (const float*)d_in[19];
    float* out = (float*)d_out;

    float *dis, *csr_nu, *Y3, *Wt1, *Wt2, *Wt3, *psum, *pcnt;
    int *cursor, *rowstart, *bsum, *csr_src;
    float4* csr_n4;
    unsigned* pmax;
    __half *xh, *zh, *Hh, *M2h, *Y2h, *M3h;
    cudaGetSymbolAddress((void**)&dis,      g_dis);
    cudaGetSymbolAddress((void**)&cursor,   g_cursor);
    cudaGetSymbolAddress((void**)&rowstart, g_rowstart);
    cudaGetSymbolAddress((void**)&bsum,     g_bsum);
    cudaGetSymbolAddress((void**)&csr_src,  g_csr_src);
    cudaGetSymbolAddress((void**)&csr_n4,   g_csr_n4);
    cudaGetSymbolAddress((void**)&csr_nu,   g_csr_nu);
    cudaGetSymbolAddress((void**)&xh,       g_xh);
    cudaGetSymbolAddress((void**)&zh,       g_zh);
    cudaGetSymbolAddress((void**)&Hh,       g_Hh);
    cudaGetSymbolAddress((void**)&M2h,      g_M2h);
    cudaGetSymbolAddress((void**)&Y2h,      g_Y2h);
    cudaGetSymbolAddress((void**)&M3h,      g_M3h);
    cudaGetSymbolAddress((void**)&Y3,       g_Y3);
    cudaGetSymbolAddress((void**)&Wt1,      g_Wt1);
    cudaGetSymbolAddress((void**)&Wt2,      g_Wt2);
    cudaGetSymbolAddress((void**)&Wt3,      g_Wt3);
    cudaGetSymbolAddress((void**)&psum,     g_psum);
    cudaGetSymbolAddress((void**)&pmax,     g_pmax);
    cudaGetSymbolAddress((void**)&pcnt,     g_pcnt);

    cudaFuncSetAttribute(k_gemm_g, cudaFuncAttributeMaxDynamicSharedMemorySize, SMT);
    cudaFuncSetAttribute(k_gemm_c1, cudaFuncAttributeMaxDynamicSharedMemorySize, SMT);

    const int NB = (NN + 1023) / 1024;
    const int MT = (NN + 127) / 128;   // 391
    const int TRN = 4 * DD * DD + 4 * DD * 2 * DD + 2 * DD * DD;  // 229376

    // 0. prep: transposes + x->fp16
    k_tr_all<<<(TRN + 255) / 256, 256>>>(W1A, W1B, W1C, W1D, W2, W3, Wt1, Wt2, Wt3);
    k_x2h<<<(NN * 16 + 255) / 256, 256>>>((const float4*)x, (uint4*)xh);

    // 1. degrees + CSR (in-degree derived from float degree; no cnt atomics)
    k_init<<<(5 * NN + 255) / 256, 256>>>(dis, cursor);
    k_deg_edges<<<(NE + 255) / 256, 256>>>(ei, ea, dis);
    k_scan_block<<<NB, 1024>>>(dis, rowstart, bsum);
    k_scan_top<<<1, 32>>>(bsum, NB);
    k_scan_add<<<NB, 1024>>>(rowstart, bsum);
    k_rsqrt<<<(5 * NN + 255) / 256, 256>>>(dis);
    k_csr_fill<<<(NE + 255) / 256, 256>>>(ei, ea, dis, rowstart, cursor,
                                          csr_src, csr_n4, csr_nu);

    // 2. conv1 aggregation of x:  z_k = S_k x  (fp16 in/out, fp32 accum)
    k_gather_z_h<<<(NN * 32 + 255) / 256, 256>>>(
        (const uint2*)xh, dis, rowstart, csr_src, csr_n4, (uint2*)zh);

    // 3. conv1 fused GEMMs: H[:, k*128:(k+1)*128] = relu(z_k @ W1k + b1k)
    k_gemm_c1<<<dim3(4, MT), 256, SMT>>>(zh, Wt1, b1A, b1B, b1C, b1D, Hh, NN);

    // 4. conv2: M2 = H @ W2, then aggregate
    k_gemm_g<<<dim3(2, MT), 256, SMT>>>(Hh, 4 * DD, nullptr, Wt2, M2h, 2 * DD, NN, 4 * DD, 0);
    k_gather_u_h<256, 0><<<(NN * 32 + 255) / 256, 256>>>(
        M2h, dis, rowstart, csr_src, csr_nu, (void*)Y2h);

    // 5. conv3: M3 = relu(Y2 + b2) @ W3, then aggregate (fp32 out for pooling)
    k_gemm_g<<<dim3(1, MT), 256, SMT>>>(Y2h, 2 * DD, b2, Wt3, M3h, DD, NN, 2 * DD, 0);
    k_gather_u_h<128, 1><<<(NN * 32 + 255) / 256, 256>>>(
        M3h, dis, rowstart, csr_src, csr_nu, (void*)Y3);

    // 6. pooling (b3 folded in) + MLP head
    k_pool_init<<<(NG * DD + 255) / 256, 256>>>(psum, pmax, pcnt);
    k_pool<<<(NN + POOL_CHUNK - 1) / POOL_CHUNK, DD>>>(Y3, b3, batch, psum, pmax, pcnt);
    k_mlp<<<1, 64>>>(Wm1, bm1, Wm2, bm2, psum, pmax, pcnt, out);
}

// round 13
// speedup vs baseline: 3.8424x; 1.3329x over previous
#include <cuda_runtime.h>
#include <cuda_bf16.h>
#include <cuda_fp16.h>
#include <cstdint>

#define NN 50000
#define NE 600000
#define DD 128
#define NG 64

// ---------------- scratch (static __device__, allocation-free) ----------------
static __device__ float    g_dis[5 * NN];        // rsqrt degrees: k=0..3 weighted, 4 unweighted
static __device__ int      g_cursor[NN];
static __device__ int      g_rowstart[NN + 1];
static __device__ int      g_bsum[64];
static __device__ int      g_csr_src[NE];
static __device__ float4   g_csr_n4[NE];
static __device__ float    g_csr_nu[NE];
static __device__ __align__(16) __half g_xh[NN * DD];        // fp16 x
static __device__ __align__(16) __half g_zh[4 * NN * DD];    // fp16 z_k = S_k x
static __device__ __align__(16) __half g_Hh[NN * 4 * DD];    // fp16 concat relu(z W + b)
static __device__ __align__(16) __half g_M2h[NN * 2 * DD];   // fp16 H @ W2
static __device__ __align__(16) __half g_Y2h[NN * 2 * DD];   // fp16 S_u M2
static __device__ __align__(16) __half g_M3h[NN * DD];       // fp16 relu(Y2+b2) @ W3
static __device__ float    g_Y3[NN * DD];                    // fp32 S_u M3 (pool input)
static __device__ float    g_Wt1[4 * DD * DD];
static __device__ float    g_Wt2[2 * DD * 4 * DD];
static __device__ float    g_Wt3[DD * 2 * DD];
static __device__ float    g_psum[NG * DD];
static __device__ unsigned g_pmax[NG * DD];
static __device__ float    g_pcnt[NG];

// ---------------- small helpers ----------------
__device__ __forceinline__ unsigned fenc(float f) {
    unsigned b = __float_as_uint(f);
    return (b & 0x80000000u) ? ~b : (b | 0x80000000u);
}
__device__ __forceinline__ float fdec(unsigned u) {
    return (u & 0x80000000u) ? __uint_as_float(u & 0x7fffffffu) : __uint_as_float(~u);
}
__device__ __forceinline__ uint32_t smem_u32(const void* p) {
    uint32_t a;
    asm("{ .reg .u64 t; cvta.to.shared.u64 t, %1; cvt.u32.u64 %0, t; }" : "=r"(a) : "l"(p));
    return a;
}
__device__ __forceinline__ void ldsm4(uint32_t& r0, uint32_t& r1, uint32_t& r2, uint32_t& r3,
                                      uint32_t addr) {
    asm volatile("ldmatrix.sync.aligned.m8n8.x4.shared.b16 {%0,%1,%2,%3}, [%4];"
                 : "=r"(r0), "=r"(r1), "=r"(r2), "=r"(r3) : "r"(addr));
}
__device__ __forceinline__ void mma_f16(float* c, const uint32_t* a, uint32_t b0, uint32_t b1) {
    asm volatile(
        "mma.sync.aligned.m16n8k16.row.col.f32.f16.f16.f32 "
        "{%0,%1,%2,%3}, {%4,%5,%6,%7}, {%8,%9}, {%0,%1,%2,%3};"
        : "+f"(c[0]), "+f"(c[1]), "+f"(c[2]), "+f"(c[3])
        : "r"(a[0]), "r"(a[1]), "r"(a[2]), "r"(a[3]), "r"(b0), "r"(b1));
}

// ---------------- prep: x -> fp16, weight transposes ----------------
__global__ void k_x2h(const float4* __restrict__ x4, uint4* __restrict__ xh4) {
    int i = blockIdx.x * blockDim.x + threadIdx.x;
    if (i >= NN * 16) return;
    float4 a = x4[2 * i], b = x4[2 * i + 1];
    __half2 h0 = __floats2half2_rn(a.x, a.y), h1 = __floats2half2_rn(a.z, a.w);
    __half2 h2 = __floats2half2_rn(b.x, b.y), h3 = __floats2half2_rn(b.z, b.w);
    uint4 u;
    u.x = *reinterpret_cast<uint32_t*>(&h0); u.y = *reinterpret_cast<uint32_t*>(&h1);
    u.z = *reinterpret_cast<uint32_t*>(&h2); u.w = *reinterpret_cast<uint32_t*>(&h3);
    xh4[i] = u;
}

__global__ void k_tr_all(const float* __restrict__ W1A, const float* __restrict__ W1B,
                         const float* __restrict__ W1C, const float* __restrict__ W1D,
                         const float* __restrict__ W2, const float* __restrict__ W3,
                         float* __restrict__ Wt1, float* __restrict__ Wt2,
                         float* __restrict__ Wt3) {
    int i = blockIdx.x * blockDim.x + threadIdx.x;
    if (i < 4 * DD * DD) {
        int wsel = i >> 14, rem = i & 16383;
        int k = rem >> 7, n = rem & 127;
        const float* W = (wsel == 0) ? W1A : (wsel == 1) ? W1B : (wsel == 2) ? W1C : W1D;
        Wt1[wsel * DD * DD + n * DD + k] = W[rem];
    } else if (i < 4 * DD * DD + 4 * DD * 2 * DD) {
        int rem = i - 4 * DD * DD;           // K=512, N=256
        int k = rem >> 8, n = rem & 255;
        Wt2[n * 512 + k] = W2[rem];
    } else if (i < 4 * DD * DD + 4 * DD * 2 * DD + 2 * DD * DD) {
        int rem = i - 4 * DD * DD - 4 * DD * 2 * DD;  // K=256, N=128
        int k = rem >> 7, n = rem & 127;
        Wt3[n * 256 + k] = W3[rem];
    }
}

// ---------------- degree + CSR build ----------------
__global__ void k_init(float* dis, int* cursor) {
    int i = blockIdx.x * blockDim.x + threadIdx.x;
    if (i < 5 * NN) dis[i] = 1.0f;
    if (i < NN) cursor[i] = 0;
}

__global__ void k_deg_edges(const int* __restrict__ ei, const float* __restrict__ ea,
                            float* dis) {
    int e = blockIdx.x * blockDim.x + threadIdx.x;
    if (e >= NE) return;
    int d = ei[NE + e];
    float4 w = *reinterpret_cast<const float4*>(&ea[e * 4]);
    atomicAdd(&dis[0 * NN + d], w.x);
    atomicAdd(&dis[1 * NN + d], w.y);
    atomicAdd(&dis[2 * NN + d], w.z);
    atomicAdd(&dis[3 * NN + d], w.w);
    atomicAdd(&dis[4 * NN + d], 1.0f);
}

__global__ void k_rsqrt(float* dis) {
    int i = blockIdx.x * blockDim.x + threadIdx.x;
    if (i < 5 * NN) dis[i] = rsqrtf(dis[i]);
}

// in-degree derived from unweighted degree (init 1 + 1 per edge) -> no cnt atomics
__global__ void k_scan_block(const float* __restrict__ deg, int* __restrict__ rowstart,
                             int* __restrict__ bsum) {
    __shared__ int sh[1024];
    int i = blockIdx.x * 1024 + threadIdx.x;
    int v = (i < NN) ? (__float2int_rn(deg[4 * NN + i]) - 1) : 0;
    sh[threadIdx.x] = v;
    __syncthreads();
    #pragma unroll
    for (int off = 1; off < 1024; off <<= 1) {
        int t = (threadIdx.x >= off) ? sh[threadIdx.x - off] : 0;
        __syncthreads();
        sh[threadIdx.x] += t;
        __syncthreads();
    }
    if (i < NN) rowstart[i] = sh[threadIdx.x] - v;
    if (threadIdx.x == 1023) bsum[blockIdx.x] = sh[1023];
}

__global__ void k_scan_top(int* bsum, int nb) {
    if (threadIdx.x == 0) {
        int run = 0;
        for (int b = 0; b < nb; b++) { int t = bsum[b]; bsum[b] = run; run += t; }
    }
}

__global__ void k_scan_add(int* rowstart, const int* __restrict__ bsum) {
    int i = blockIdx.x * 1024 + threadIdx.x;
    if (i < NN) rowstart[i] += bsum[blockIdx.x];
    if (blockIdx.x == 0 && threadIdx.x == 0) rowstart[NN] = NE;
}

__global__ void k_csr_fill(const int* __restrict__ ei, const float* __restrict__ ea,
                           const float* __restrict__ dis, const int* __restrict__ rowstart,
                           int* cursor, int* __restrict__ csr_src,
                           float4* __restrict__ csr_n4, float* __restrict__ csr_nu) {
    int e = blockIdx.x * blockDim.x + threadIdx.x;
    if (e >= NE) return;
    int s = ei[e], d = ei[NE + e];
    int pos = rowstart[d] + atomicAdd(&cursor[d], 1);
    csr_src[pos] = s;
    float4 w = *reinterpret_cast<const float4*>(&ea[e * 4]);
    float4 n;
    n.x = dis[0 * NN + s] * w.x * dis[0 * NN + d];
    n.y = dis[1 * NN + s] * w.y * dis[1 * NN + d];
    n.z = dis[2 * NN + s] * w.z * dis[2 * NN + d];
    n.w = dis[3 * NN + s] * w.w * dis[3 * NN + d];
    csr_n4[pos] = n;
    csr_nu[pos] = dis[4 * NN + s] * dis[4 * NN + d];
}

// ---------------- gather aggregations (fp16 in, no atomics) ----------------
__global__ void k_gather_z_h(const uint2* __restrict__ xh2, const float* __restrict__ dis,
                             const int* __restrict__ rowstart, const int* __restrict__ csr_src,
                             const float4* __restrict__ csr_n4, uint2* __restrict__ zh2) {
    int warp = (blockIdx.x * blockDim.x + threadIdx.x) >> 5;
    int lane = threadIdx.x & 31;
    if (warp >= NN) return;
    int i = warp;
    uint2 u = xh2[i * 32 + lane];
    float2 f0 = __half22float2(*reinterpret_cast<__half2*>(&u.x));
    float2 f1 = __half22float2(*reinterpret_cast<__half2*>(&u.y));
    float4 xv = make_float4(f0.x, f0.y, f1.x, f1.y);
    float d0 = dis[i], d1 = dis[NN + i], d2 = dis[2 * NN + i], d3 = dis[3 * NN + i];
    float s0 = d0 * d0, s1 = d1 * d1, s2 = d2 * d2, s3 = d3 * d3;
    float4 a0 = make_float4(xv.x * s0, xv.y * s0, xv.z * s0, xv.w * s0);
    float4 a1 = make_float4(xv.x * s1, xv.y * s1, xv.z * s1, xv.w * s1);
    float4 a2 = make_float4(xv.x * s2, xv.y * s2, xv.z * s2, xv.w * s2);
    float4 a3 = make_float4(xv.x * s3, xv.y * s3, xv.z * s3, xv.w * s3);
    int e0 = rowstart[i], e1 = rowstart[i + 1];
    for (int e = e0; e < e1; e++) {
        int s = csr_src[e];
        float4 n = csr_n4[e];
        uint2 us = xh2[s * 32 + lane];
        float2 g0 = __half22float2(*reinterpret_cast<__half2*>(&us.x));
        float2 g1 = __half22float2(*reinterpret_cast<__half2*>(&us.y));
        float4 xs = make_float4(g0.x, g0.y, g1.x, g1.y);
        a0.x += n.x * xs.x; a0.y += n.x * xs.y; a0.z += n.x * xs.z; a0.w += n.x * xs.w;
        a1.x += n.y * xs.x; a1.y += n.y * xs.y; a1.z += n.y * xs.z; a1.w += n.y * xs.w;
        a2.x += n.z * xs.x; a2.y += n.z * xs.y; a2.z += n.z * xs.z; a2.w += n.z * xs.w;
        a3.x += n.w * xs.x; a3.y += n.w * xs.y; a3.z += n.w * xs.z; a3.w += n.w * xs.w;
    }
    int base = i * 32 + lane;
    float4 aa[4] = {a0, a1, a2, a3};
    #pragma unroll
    for (int k = 0; k < 4; k++) {
        __half2 h0 = __floats2half2_rn(aa[k].x, aa[k].y);
        __half2 h1 = __floats2half2_rn(aa[k].z, aa[k].w);
        uint2 o;
        o.x = *reinterpret_cast<uint32_t*>(&h0);
        o.y = *reinterpret_cast<uint32_t*>(&h1);
        zh2[(size_t)k * NN * 32 + base] = o;
    }
}

template<int HL>
__device__ __forceinline__ void ldhalf(const __half* p, float* v) {
    if (HL == 4) {
        uint2 u = *reinterpret_cast<const uint2*>(p);
        float2 a = __half22float2(*reinterpret_cast<__half2*>(&u.x));
        float2 b = __half22float2(*reinterpret_cast<__half2*>(&u.y));
        v[0] = a.x; v[1] = a.y; v[2] = b.x; v[3] = b.y;
    } else {
        uint4 u = *reinterpret_cast<const uint4*>(p);
        const __half2* h = reinterpret_cast<const __half2*>(&u);
        #pragma unroll
        for (int t = 0; t < 4; t++) {
            float2 f = __half22float2(h[t]);
            v[2 * t] = f.x; v[2 * t + 1] = f.y;
        }
    }
}

// Y[i] = dis_u[i]^2 * M[i] + sum_e nu(e) * M[src(e)]; M fp16, acc fp32.
template<int F, int OUTF32>
__global__ void k_gather_u_h(const __half* __restrict__ Mh, const float* __restrict__ dis,
                             const int* __restrict__ rowstart, const int* __restrict__ csr_src,
                             const float* __restrict__ csr_nu, void* __restrict__ Yout) {
    constexpr int HL = F / 32;
    int warp = (blockIdx.x * blockDim.x + threadIdx.x) >> 5;
    int lane = threadIdx.x & 31;
    if (warp >= NN) return;
    int i = warp;
    float du = dis[4 * NN + i];
    float s0 = du * du;
    float acc[HL], v[HL];
    ldhalf<HL>(Mh + (size_t)i * F + lane * HL, v);
    #pragma unroll
    for (int t = 0; t < HL; t++) acc[t] = v[t] * s0;
    int e0 = rowstart[i], e1 = rowstart[i + 1];
    for (int e = e0; e < e1; e++) {
        int s = csr_src[e];
        float nu = csr_nu[e];
        ldhalf<HL>(Mh + (size_t)s * F + lane * HL, v);
        #pragma unroll
        for (int t = 0; t < HL; t++) acc[t] += nu * v[t];
    }
    if (OUTF32) {
        float* Y = (float*)Yout;
        #pragma unroll
        for (int q = 0; q < HL / 4; q++)
            *reinterpret_cast<float4*>(&Y[(size_t)i * F + lane * HL + 4 * q]) =
                make_float4(acc[4 * q], acc[4 * q + 1], acc[4 * q + 2], acc[4 * q + 3]);
    } else {
        __half* Yh = (__half*)Yout;
        uint32_t pk[HL / 2];
        #pragma unroll
        for (int t = 0; t < HL / 2; t++) {
            __half2 h = __floats2half2_rn(acc[2 * t], acc[2 * t + 1]);
            pk[t] = *reinterpret_cast<uint32_t*>(&h);
        }
        if (HL == 4)
            *reinterpret_cast<uint2*>(Yh + (size_t)i * F + lane * HL) = make_uint2(pk[0], pk[1]);
        else
            *reinterpret_cast<uint4*>(Yh + (size_t)i * F + lane * HL) =
                make_uint4(pk[0], pk[1], pk[2], pk[3]);
    }
}

// ============ fp16 x fp16-limb mma.sync GEMM ============
// C = op(A)@Bt^T; A fp16 exact, B fp32 split into 2 fp16 limbs (B1 + B2, err 2^-22).
// Per 16-K chunk: A smem [128 x 16h] rows padded to 24h (48B, conflict-free),
//                 B smem [128 x (B1 16h | B2 16h)] rows padded to 40h (80B).
#define ROWPA 24
#define ROWPB 40
#define ASTG  6144                  // 128*48
#define BSTG  10240                 // 128*80
#define STAGE (ASTG + BSTG)         // 16384
#define SMT   (2 * STAGE)           // 32768

__device__ __forceinline__ uint4 ldA16(const __half* __restrict__ Arow, int lda, int rowsA,
                                       int k0, const float* __restrict__ Abias,
                                       int lr, int lq) {
    uint4 u = make_uint4(0, 0, 0, 0);
    if (lr < rowsA) {
        u = *reinterpret_cast<const uint4*>(Arow + (size_t)lr * lda + k0 + lq * 8);
        if (Abias) {
            const __half2* h = reinterpret_cast<const __half2*>(&u);
            float4 b0 = *reinterpret_cast<const float4*>(Abias + k0 + lq * 8);
            float4 b1 = *reinterpret_cast<const float4*>(Abias + k0 + lq * 8 + 4);
            float bb[8] = {b0.x, b0.y, b0.z, b0.w, b1.x, b1.y, b1.z, b1.w};
            uint32_t w[4];
            #pragma unroll
            for (int t = 0; t < 4; t++) {
                float2 f = __half22float2(h[t]);
                __half2 r = __floats2half2_rn(fmaxf(f.x + bb[2 * t], 0.f),
                                              fmaxf(f.y + bb[2 * t + 1], 0.f));
                w[t] = *reinterpret_cast<uint32_t*>(&r);
            }
            u = make_uint4(w[0], w[1], w[2], w[3]);
        }
    }
    return u;
}

__device__ __forceinline__ void ldB16(const float* __restrict__ Bt0, int K, int k0,
                                      int lr, int lq, float* f) {
    float4 v0 = *reinterpret_cast<const float4*>(Bt0 + (size_t)lr * K + k0 + lq * 8);
    float4 v1 = *reinterpret_cast<const float4*>(Bt0 + (size_t)lr * K + k0 + lq * 8 + 4);
    f[0] = v0.x; f[1] = v0.y; f[2] = v0.z; f[3] = v0.w;
    f[4] = v1.x; f[5] = v1.y; f[6] = v1.z; f[7] = v1.w;
}

__device__ __forceinline__ void stB16(char* smB, int lr, int lq, const float* f) {
    uint32_t hw[4], lw[4];
    #pragma unroll
    for (int t = 0; t < 4; t++) {
        __half2 h2 = __floats2half2_rn(f[2 * t], f[2 * t + 1]);
        hw[t] = *reinterpret_cast<uint32_t*>(&h2);
        float lx = f[2 * t] - __half2float(h2.x);
        float ly = f[2 * t + 1] - __half2float(h2.y);
        __half2 l2 = __floats2half2_rn(lx, ly);
        lw[t] = *reinterpret_cast<uint32_t*>(&l2);
    }
    char* pr = smB + (size_t)lr * (ROWPB * 2) + lq * 16;
    *reinterpret_cast<uint4*>(pr)      = make_uint4(hw[0], hw[1], hw[2], hw[3]);
    *reinterpret_cast<uint4*>(pr + 32) = make_uint4(lw[0], lw[1], lw[2], lw[3]);
}

__device__ __forceinline__ void gemm_body(
    const __half* __restrict__ Ah, int lda, const float* __restrict__ Abias,
    const float* __restrict__ Bt0, const float* __restrict__ Cbias,
    __half* __restrict__ Ch, int ldc, int ccol0, int M, int K, int crelu, int row0)
{
    extern __shared__ __align__(128) char sm[];
    uint32_t smu = smem_u32(sm);
    int tid = threadIdx.x;
    const __half* Arow = Ah + (size_t)row0 * lda;
    int rowsA = M - row0;
    int nc = K >> 4;

    int w = tid >> 5, lane = tid & 31;
    int wm = w & 1, wn = w >> 1;
    int j = lane >> 3, rr = lane & 7;
    uint32_t a_off[4], b_off[2];
    #pragma unroll
    for (int mb = 0; mb < 4; mb++)
        a_off[mb] = 2u * ((wm * 64 + mb * 16 + (j & 1) * 8 + rr) * ROWPA + (j >> 1) * 8);
    #pragma unroll
    for (int nbp = 0; nbp < 2; nbp++)
        b_off[nbp] = 2u * ((wn * 32 + nbp * 16 + (j & 1) * 8 + rr) * ROWPB + (j >> 1) * 8);

    int lr = tid >> 1, lq = tid & 1;
    float acc[4][4][4];
    #pragma unroll
    for (int a = 0; a < 4; a++)
        #pragma unroll
        for (int b = 0; b < 4; b++)
            #pragma unroll
            for (int c = 0; c < 4; c++) acc[a][b][c] = 0.f;

    uint4 ua;
    float fb[8];
    ua = ldA16(Arow, lda, rowsA, 0, Abias, lr, lq);
    ldB16(Bt0, K, 0, lr, lq, fb);
    *reinterpret_cast<uint4*>(sm + (size_t)lr * 48 + lq * 16) = ua;
    stB16(sm + ASTG, lr, lq, fb);
    __syncthreads();

    for (int c = 0; c < nc; c++) {
        int cur = c & 1;
        bool has = (c + 1 < nc);
        if (has) {
            int k0 = (c + 1) << 4;
            ua = ldA16(Arow, lda, rowsA, k0, Abias, lr, lq);
            ldB16(Bt0, K, k0, lr, lq, fb);
        }
        uint32_t smA = smu + cur * STAGE;
        uint32_t smB = smA + ASTG;
        uint32_t af[4][4], b1[2][4], b2[2][4];
        #pragma unroll
        for (int mb = 0; mb < 4; mb++)
            ldsm4(af[mb][0], af[mb][1], af[mb][2], af[mb][3], smA + a_off[mb]);
        #pragma unroll
        for (int nbp = 0; nbp < 2; nbp++) {
            ldsm4(b1[nbp][0], b1[nbp][1], b1[nbp][2], b1[nbp][3], smB + b_off[nbp]);
            ldsm4(b2[nbp][0], b2[nbp][1], b2[nbp][2], b2[nbp][3], smB + b_off[nbp] + 32);
        }
        #pragma unroll
        for (int mb = 0; mb < 4; mb++)
            #pragma unroll
            for (int nb = 0; nb < 4; nb++) {
                mma_f16(acc[mb][nb], af[mb], b1[nb >> 1][nb & 1], b1[nb >> 1][2 + (nb & 1)]);
                mma_f16(acc[mb][nb], af[mb], b2[nb >> 1][nb & 1], b2[nb >> 1][2 + (nb & 1)]);
            }
        __syncthreads();
        if (has) {
            char* d = sm + (cur ^ 1) * STAGE;
            *reinterpret_cast<uint4*>(d + (size_t)lr * 48 + lq * 16) = ua;
            stB16(d + ASTG, lr, lq, fb);
        }
        __syncthreads();
    }

    int g = lane >> 2, cq = lane & 3;
    #pragma unroll
    for (int mb = 0; mb < 4; mb++) {
        #pragma unroll
        for (int nb = 0; nb < 4; nb++) {
            int l = wn * 32 + nb * 8 + 2 * cq;
            float bx = 0.f, by = 0.f;
            if (Cbias) { bx = Cbias[l]; by = Cbias[l + 1]; }
            float v0 = acc[mb][nb][0] + bx, v1 = acc[mb][nb][1] + by;
            float v2 = acc[mb][nb][2] + bx, v3 = acc[mb][nb][3] + by;
            if (crelu) {
                v0 = fmaxf(v0, 0.f); v1 = fmaxf(v1, 0.f);
                v2 = fmaxf(v2, 0.f); v3 = fmaxf(v3, 0.f);
            }
            int r0 = row0 + wm * 64 + mb * 16 + g;
            int ccol = ccol0 + l;
            if (r0 < M)
                *reinterpret_cast<__half2*>(Ch + (size_t)r0 * ldc + ccol) =
                    __floats2half2_rn(v0, v1);
            if (r0 + 8 < M)
                *reinterpret_cast<__half2*>(Ch + (size_t)(r0 + 8) * ldc + ccol) =
                    __floats2half2_rn(v2, v3);
        }
    }
}

__global__ __launch_bounds__(256, 2)
void k_gemm_g(const __half* __restrict__ Ah, int lda, const float* __restrict__ Abias,
              const float* __restrict__ Bt, __half* __restrict__ Ch, int ldc,
              int M, int K, int crelu) {
    int n0 = blockIdx.x * 128;
    gemm_body(Ah, lda, Abias, Bt + (size_t)n0 * K, nullptr, Ch, ldc, n0, M, K, crelu,
              blockIdx.y * 128);
}

__global__ __launch_bounds__(256, 2)
void k_gemm_c1(const __half* __restrict__ zh, const float* __restrict__ Wt1,
               const float* __restrict__ bA, const float* __restrict__ bB,
               const float* __restrict__ bC, const float* __restrict__ bD,
               __half* __restrict__ Hh, int M) {
    int k = blockIdx.x;
    const float* bias = (k == 0) ? bA : (k == 1) ? bB : (k == 2) ? bC : bD;
    gemm_body(zh + (size_t)k * NN * DD, DD, nullptr, Wt1 + (size_t)k * DD * DD, bias,
              Hh, 4 * DD, k * DD, M, DD, 1, blockIdx.y * 128);
}

// ---------------- pooling ----------------
__global__ void k_pool_init(float* psum, unsigned* pmax, float* pcnt) {
    int i = blockIdx.x * blockDim.x + threadIdx.x;
    if (i < NG * DD) { psum[i] = 0.0f; pmax[i] = 0x007fffffu; }
    if (i < NG) pcnt[i] = 0.0f;
}

#define POOL_CHUNK 128
__global__ void k_pool(const float* __restrict__ Y3, const float* __restrict__ b3,
                       const int* __restrict__ batch,
                       float* psum, unsigned* pmax, float* pcnt) {
    int j = threadIdx.x;
    int i0 = blockIdx.x * POOL_CHUNK;
    int iend = min(i0 + POOL_CHUNK, NN);
    float bj = b3[j];
    int cur = -1;
    float s = 0.0f, m = __int_as_float(0xff800000), cnt = 0.0f;
    for (int i = i0; i < iend; i++) {
        int g = batch[i];
        if (g != cur) {
            if (cur >= 0) {
                atomicAdd(&psum[cur * DD + j], s);
                atomicMax(&pmax[cur * DD + j], fenc(m));
                if (j == 0) atomicAdd(&pcnt[cur], cnt);
            }
            cur = g; s = 0.0f; m = __int_as_float(0xff800000); cnt = 0.0f;
        }
        float y = Y3[(size_t)i * DD + j] + bj;
        s += y;
        m = fmaxf(m, y);
        cnt += 1.0f;
    }
    if (cur >= 0) {
        atomicAdd(&psum[cur * DD + j], s);
        atomicMax(&pmax[cur * DD + j], fenc(m));
        if (j == 0) atomicAdd(&pcnt[cur], cnt);
    }
}

// ---------------- MLP head ----------------
__global__ void k_mlp(const float* __restrict__ Wm1, const float* __restrict__ bm1,
                      const float* __restrict__ Wm2, const float* __restrict__ bm2,
                      const float* __restrict__ psum, const unsigned* __restrict__ pmax,
                      const float* __restrict__ pcnt, float* __restrict__ out) {
    int g = threadIdx.x;
    if (g >= NG) return;
    float cnt = pcnt[g];
    float inv = 1.0f / fmaxf(cnt, 1.0f);
    float hid[8];
    #pragma unroll
    for (int h = 0; h < 8; h++) hid[h] = bm1[h];
    for (int j = 0; j < DD; j++) {
        float mean = psum[g * DD + j] * inv;
        #pragma unroll
        for (int h = 0; h < 8; h++) hid[h] += mean * Wm1[j * 8 + h];
    }
    for (int j = 0; j < DD; j++) {
        float mx = (cnt > 0.0f) ? fdec(pmax[g * DD + j]) : 0.0f;
        #pragma unroll
        for (int h = 0; h < 8; h++) hid[h] += mx * Wm1[(DD + j) * 8 + h];
    }
    #pragma unroll
    for (int h = 0; h < 8; h++) hid[h] = fmaxf(hid[h], 0.0f);
    #pragma unroll
    for (int c = 0; c < 2; c++) {
        float o = bm2[c];
        #pragma unroll
        for (int h = 0; h < 8; h++) o += hid[h] * Wm2[h * 2 + c];
        out[g * 2 + c] = o;
    }
}

// ---------------- driver ----------------
extern "C" void kernel_launch(void* const* d_in, const int* in_sizes, int n_in,
                              void* d_out, int out_size) {
    const float* x     = (const float*)d_in[0];
    const int*   ei    = (const int*)d_in[1];
    const float* ea    = (const float*)d_in[2];
    const int*   batch = (const int*)d_in[3];
    const float* W1A = (const float*)d_in[4];
    const float* b1A = (const float*)d_in[5];
    const float* W1B = (const float*)d_in[6];
    const float* b1B = (const float*)d_in[7];
    const float* W1C = (const float*)d_in[8];
    const float* b1C = (const float*)d_in[9];
    const float* W1D = (const float*)d_in[10];
    const float* b1D = (const float*)d_in[11];
    const float* W2  = (const float*)d_in[12];
    const float* b2  = (const float*)d_in[13];
    const float* W3  = (const float*)d_in[14];
    const float* b3  = (const float*)d_in[15];
    const float* Wm1 = (const float*)d_in[16];
    const float* bm1 = (const float*)d_in[17];
    const float* Wm2 = (const float*)d_in[18];
    const float* bm2 = (const float*)d_in[19];
    float* out = (float*)d_out;

    float *dis, *csr_nu, *Y3, *Wt1, *Wt2, *Wt3, *psum, *pcnt;
    int *cursor, *rowstart, *bsum, *csr_src;
    float4* csr_n4;
    unsigned* pmax;
    __half *xh, *zh, *Hh, *M2h, *Y2h, *M3h;
    cudaGetSymbolAddress((void**)&dis,      g_dis);
    cudaGetSymbolAddress((void**)&cursor,   g_cursor);
    cudaGetSymbolAddress((void**)&rowstart, g_rowstart);
    cudaGetSymbolAddress((void**)&bsum,     g_bsum);
    cudaGetSymbolAddress((void**)&csr_src,  g_csr_src);
    cudaGetSymbolAddress((void**)&csr_n4,   g_csr_n4);
    cudaGetSymbolAddress((void**)&csr_nu,   g_csr_nu);
    cudaGetSymbolAddress((void**)&xh,       g_xh);
    cudaGetSymbolAddress((void**)&zh,       g_zh);
    cudaGetSymbolAddress((void**)&Hh,       g_Hh);
    cudaGetSymbolAddress((void**)&M2h,      g_M2h);
    cudaGetSymbolAddress((void**)&Y2h,      g_Y2h);
    cudaGetSymbolAddress((void**)&M3h,      g_M3h);
    cudaGetSymbolAddress((void**)&Y3,       g_Y3);
    cudaGetSymbolAddress((void**)&Wt1,      g_Wt1);
    cudaGetSymbolAddress((void**)&Wt2,      g_Wt2);
    cudaGetSymbolAddress((void**)&Wt3,      g_Wt3);
    cudaGetSymbolAddress((void**)&psum,     g_psum);
    cudaGetSymbolAddress((void**)&pmax,     g_pmax);
    cudaGetSymbolAddress((void**)&pcnt,     g_pcnt);

    cudaFuncSetAttribute(k_gemm_g, cudaFuncAttributeMaxDynamicSharedMemorySize, SMT);
    cudaFuncSetAttribute(k_gemm_c1, cudaFuncAttributeMaxDynamicSharedMemorySize, SMT);

    const int NB = (NN + 1023) / 1024;
    const int MT = (NN + 127) / 128;   // 391
    const int TRN = 4 * DD * DD + 4 * DD * 2 * DD + 2 * DD * DD;  // 229376

    // 0. prep: transposes + x->fp16
    k_tr_all<<<(TRN + 255) / 256, 256>>>(W1A, W1B, W1C, W1D, W2, W3, Wt1, Wt2, Wt3);
    k_x2h<<<(NN * 16 + 255) / 256, 256>>>((const float4*)x, (uint4*)xh);

    // 1. degrees + CSR
    k_init<<<(5 * NN + 255) / 256, 256>>>(dis, cursor);
    k_deg_edges<<<(NE + 255) / 256, 256>>>(ei, ea, dis);
    k_scan_block<<<NB, 1024>>>(dis, rowstart, bsum);
    k_scan_top<<<1, 32>>>(bsum, NB);
    k_scan_add<<<NB, 1024>>>(rowstart, bsum);
    k_rsqrt<<<(5 * NN + 255) / 256, 256>>>(dis);
    k_csr_fill<<<(NE + 255) / 256, 256>>>(ei, ea, dis, rowstart, cursor,
                                          csr_src, csr_n4, csr_nu);

    // 2. conv1 aggregation of x:  z_k = S_k x  (fp16 in/out, fp32 accum)
    k_gather_z_h<<<(NN * 32 + 255) / 256, 256>>>(
        (const uint2*)xh, dis, rowstart, csr_src, csr_n4, (uint2*)zh);

    // 3. conv1 fused GEMMs
    k_gemm_c1<<<dim3(4, MT), 256, SMT>>>(zh, Wt1, b1A, b1B, b1C, b1D, Hh, NN);

    // 4. conv2: M2 = H @ W2, then aggregate
    k_gemm_g<<<dim3(2, MT), 256, SMT>>>(Hh, 4 * DD, nullptr, Wt2, M2h, 2 * DD, NN, 4 * DD, 0);
    k_gather_u_h<256, 0><<<(NN * 32 + 255) / 256, 256>>>(
        M2h, dis, rowstart, csr_src, csr_nu, (void*)Y2h);

    // 5. conv3: M3 = relu(Y2 + b2) @ W3, then aggregate (fp32 out for pooling)
    k_gemm_g<<<dim3(1, MT), 256, SMT>>>(Y2h, 2 * DD, b2, Wt3, M3h, DD, NN, 2 * DD, 0);
    k_gather_u_h<128, 1><<<(NN * 32 + 255) / 256, 256>>>(
        M3h, dis, rowstart, csr_src, csr_nu, (void*)Y3);

    // 6. pooling (b3 folded in) + MLP head
    k_pool_init<<<(NG * DD + 255) / 256, 256>>>(psum, pmax, pcnt);
    k_pool<<<(NN + POOL_CHUNK - 1) / POOL_CHUNK, DD>>>(Y3, b3, batch, psum, pmax, pcnt);
    k_mlp<<<1, 64>>>(Wm1, bm1, Wm2, bm2, psum, pmax, pcnt, out);
}

// round 15
// speedup vs baseline: 3.8641x; 1.0056x over previous
#include <cuda_runtime.h>
#include <cuda_bf16.h>
#include <cuda_fp16.h>
#include <cstdint>

#define NN 50000
#define NE 600000
#define DD 128
#define NG 64

// ---------------- scratch (static __device__, allocation-free) ----------------
static __device__ float    g_dis[5 * NN];        // rsqrt degrees: k=0..3 weighted, 4 unweighted
static __device__ int      g_cursor[NN];
static __device__ int      g_rowstart[NN + 1];
static __device__ int      g_bsum[64];
static __device__ int      g_csr_src[NE];
static __device__ float4   g_csr_n4[NE];
static __device__ float    g_csr_nu[NE];
static __device__ __align__(16) __half g_xh[NN * DD];        // fp16 x
static __device__ __align__(16) __half g_zh[4 * NN * DD];    // fp16 z_k = S_k x
static __device__ __align__(16) __half g_Hh[NN * 4 * DD];    // fp16 concat relu(z W + b)
static __device__ __align__(16) __half g_M2h[NN * 2 * DD];   // fp16 H @ W2
static __device__ __align__(16) __half g_Y2h[NN * 2 * DD];   // fp16 S_u M2
static __device__ __align__(16) __half g_M3h[NN * DD];       // fp16 relu(Y2+b2) @ W3
static __device__ float    g_Y3[NN * DD];                    // fp32 S_u M3 (pool input)
static __device__ float    g_Wt1[4 * DD * DD];
static __device__ float    g_Wt2[2 * DD * 4 * DD];
static __device__ float    g_Wt3[DD * 2 * DD];
static __device__ float    g_psum[NG * DD];
static __device__ unsigned g_pmax[NG * DD];
static __device__ float    g_pcnt[NG];

// ---------------- small helpers ----------------
__device__ __forceinline__ unsigned fenc(float f) {
    unsigned b = __float_as_uint(f);
    return (b & 0x80000000u) ? ~b : (b | 0x80000000u);
}
__device__ __forceinline__ float fdec(unsigned u) {
    return (u & 0x80000000u) ? __uint_as_float(u & 0x7fffffffu) : __uint_as_float(~u);
}
__device__ __forceinline__ uint32_t smem_u32(const void* p) {
    uint32_t a;
    asm("{ .reg .u64 t; cvta.to.shared.u64 t, %1; cvt.u32.u64 %0, t; }" : "=r"(a) : "l"(p));
    return a;
}
__device__ __forceinline__ void ldsm4(uint32_t& r0, uint32_t& r1, uint32_t& r2, uint32_t& r3,
                                      uint32_t addr) {
    asm volatile("ldmatrix.sync.aligned.m8n8.x4.shared.b16 {%0,%1,%2,%3}, [%4];"
                 : "=r"(r0), "=r"(r1), "=r"(r2), "=r"(r3) : "r"(addr));
}
__device__ __forceinline__ void mma_f16(float* c, const uint32_t* a, uint32_t b0, uint32_t b1) {
    asm volatile(
        "mma.sync.aligned.m16n8k16.row.col.f32.f16.f16.f32 "
        "{%0,%1,%2,%3}, {%4,%5,%6,%7}, {%8,%9}, {%0,%1,%2,%3};"
        : "+f"(c[0]), "+f"(c[1]), "+f"(c[2]), "+f"(c[3])
        : "r"(a[0]), "r"(a[1]), "r"(a[2]), "r"(a[3]), "r"(b0), "r"(b1));
}

// ---------------- prep: x -> fp16, weight transposes ----------------
__global__ void k_x2h(const float4* __restrict__ x4, uint4* __restrict__ xh4) {
    int i = blockIdx.x * blockDim.x + threadIdx.x;
    if (i >= NN * 16) return;
    float4 a = x4[2 * i], b = x4[2 * i + 1];
    __half2 h0 = __floats2half2_rn(a.x, a.y), h1 = __floats2half2_rn(a.z, a.w);
    __half2 h2 = __floats2half2_rn(b.x, b.y), h3 = __floats2half2_rn(b.z, b.w);
    uint4 u;
    u.x = *reinterpret_cast<uint32_t*>(&h0); u.y = *reinterpret_cast<uint32_t*>(&h1);
    u.z = *reinterpret_cast<uint32_t*>(&h2); u.w = *reinterpret_cast<uint32_t*>(&h3);
    xh4[i] = u;
}

__global__ void k_tr_all(const float* __restrict__ W1A, const float* __restrict__ W1B,
                         const float* __restrict__ W1C, const float* __restrict__ W1D,
                         const float* __restrict__ W2, const float* __restrict__ W3,
                         float* __restrict__ Wt1, float* __restrict__ Wt2,
                         float* __restrict__ Wt3) {
    int i = blockIdx.x * blockDim.x + threadIdx.x;
    if (i < 4 * DD * DD) {
        int wsel = i >> 14, rem = i & 16383;
        int k = rem >> 7, n = rem & 127;
        const float* W = (wsel == 0) ? W1A : (wsel == 1) ? W1B : (wsel == 2) ? W1C : W1D;
        Wt1[wsel * DD * DD + n * DD + k] = W[rem];
    } else if (i < 4 * DD * DD + 4 * DD * 2 * DD) {
        int rem = i - 4 * DD * DD;           // K=512, N=256
        int k = rem >> 8, n = rem & 255;
        Wt2[n * 512 + k] = W2[rem];
    } else if (i < 4 * DD * DD + 4 * DD * 2 * DD + 2 * DD * DD) {
        int rem = i - 4 * DD * DD - 4 * DD * 2 * DD;  // K=256, N=128
        int k = rem >> 7, n = rem & 127;
        Wt3[n * 256 + k] = W3[rem];
    }
}

// ---------------- degree + CSR build ----------------
__global__ void k_init(float* dis, int* cursor) {
    int i = blockIdx.x * blockDim.x + threadIdx.x;
    if (i < 5 * NN) dis[i] = 1.0f;
    if (i < NN) cursor[i] = 0;
}

__global__ void k_deg_edges(const int* __restrict__ ei, const float* __restrict__ ea,
                            float* dis) {
    int e = blockIdx.x * blockDim.x + threadIdx.x;
    if (e >= NE) return;
    int d = ei[NE + e];
    float4 w = *reinterpret_cast<const float4*>(&ea[e * 4]);
    atomicAdd(&dis[0 * NN + d], w.x);
    atomicAdd(&dis[1 * NN + d], w.y);
    atomicAdd(&dis[2 * NN + d], w.z);
    atomicAdd(&dis[3 * NN + d], w.w);
    atomicAdd(&dis[4 * NN + d], 1.0f);
}

__global__ void k_rsqrt(float* dis) {
    int i = blockIdx.x * blockDim.x + threadIdx.x;
    if (i < 5 * NN) dis[i] = rsqrtf(dis[i]);
}

// in-degree derived from unweighted degree (init 1 + 1 per edge) -> no cnt atomics
__global__ void k_scan_block(const float* __restrict__ deg, int* __restrict__ rowstart,
                             int* __restrict__ bsum) {
    __shared__ int sh[1024];
    int i = blockIdx.x * 1024 + threadIdx.x;
    int v = (i < NN) ? (__float2int_rn(deg[4 * NN + i]) - 1) : 0;
    sh[threadIdx.x] = v;
    __syncthreads();
    #pragma unroll
    for (int off = 1; off < 1024; off <<= 1) {
        int t = (threadIdx.x >= off) ? sh[threadIdx.x - off] : 0;
        __syncthreads();
        sh[threadIdx.x] += t;
        __syncthreads();
    }
    if (i < NN) rowstart[i] = sh[threadIdx.x] - v;
    if (threadIdx.x == 1023) bsum[blockIdx.x] = sh[1023];
}

__global__ void k_scan_top(int* bsum, int nb) {
    if (threadIdx.x == 0) {
        int run = 0;
        for (int b = 0; b < nb; b++) { int t = bsum[b]; bsum[b] = run; run += t; }
    }
}

__global__ void k_scan_add(int* rowstart, const int* __restrict__ bsum) {
    int i = blockIdx.x * 1024 + threadIdx.x;
    if (i < NN) rowstart[i] += bsum[blockIdx.x];
    if (blockIdx.x == 0 && threadIdx.x == 0) rowstart[NN] = NE;
}

__global__ void k_csr_fill(const int* __restrict__ ei, const float* __restrict__ ea,
                           const float* __restrict__ dis, const int* __restrict__ rowstart,
                           int* cursor, int* __restrict__ csr_src,
                           float4* __restrict__ csr_n4, float* __restrict__ csr_nu) {
    int e = blockIdx.x * blockDim.x + threadIdx.x;
    if (e >= NE) return;
    int s = ei[e], d = ei[NE + e];
    int pos = rowstart[d] + atomicAdd(&cursor[d], 1);
    csr_src[pos] = s;
    float4 w = *reinterpret_cast<const float4*>(&ea[e * 4]);
    float4 n;
    n.x = dis[0 * NN + s] * w.x * dis[0 * NN + d];
    n.y = dis[1 * NN + s] * w.y * dis[1 * NN + d];
    n.z = dis[2 * NN + s] * w.z * dis[2 * NN + d];
    n.w = dis[3 * NN + s] * w.w * dis[3 * NN + d];
    csr_n4[pos] = n;
    csr_nu[pos] = dis[4 * NN + s] * dis[4 * NN + d];
}

// ---------------- gather aggregations (fp16 in, no atomics, MLP-4 pipelined) --------
__device__ __forceinline__ float4 h2f4(uint2 u) {
    float2 a = __half22float2(*reinterpret_cast<__half2*>(&u.x));
    float2 b = __half22float2(*reinterpret_cast<__half2*>(&u.y));
    return make_float4(a.x, a.y, b.x, b.y);
}

__global__ void k_gather_z_h(const uint2* __restrict__ xh2, const float* __restrict__ dis,
                             const int* __restrict__ rowstart, const int* __restrict__ csr_src,
                             const float4* __restrict__ csr_n4, uint2* __restrict__ zh2) {
    int warp = (blockIdx.x * blockDim.x + threadIdx.x) >> 5;
    int lane = threadIdx.x & 31;
    if (warp >= NN) return;
    int i = warp;
    float4 xv = h2f4(xh2[i * 32 + lane]);
    float d0 = dis[i], d1 = dis[NN + i], d2 = dis[2 * NN + i], d3 = dis[3 * NN + i];
    float s0 = d0 * d0, s1 = d1 * d1, s2 = d2 * d2, s3 = d3 * d3;
    float4 a0 = make_float4(xv.x * s0, xv.y * s0, xv.z * s0, xv.w * s0);
    float4 a1 = make_float4(xv.x * s1, xv.y * s1, xv.z * s1, xv.w * s1);
    float4 a2 = make_float4(xv.x * s2, xv.y * s2, xv.z * s2, xv.w * s2);
    float4 a3 = make_float4(xv.x * s3, xv.y * s3, xv.z * s3, xv.w * s3);
    int e0 = rowstart[i], e1 = rowstart[i + 1];
    int e = e0;
    for (; e + 4 <= e1; e += 4) {
        int sA = csr_src[e], sB = csr_src[e + 1], sC = csr_src[e + 2], sD = csr_src[e + 3];
        float4 nA = csr_n4[e], nB = csr_n4[e + 1], nC = csr_n4[e + 2], nD = csr_n4[e + 3];
        float4 xA = h2f4(xh2[sA * 32 + lane]);
        float4 xB = h2f4(xh2[sB * 32 + lane]);
        float4 xC = h2f4(xh2[sC * 32 + lane]);
        float4 xD = h2f4(xh2[sD * 32 + lane]);
        #define ACC_Z(n, xs) \
            a0.x += n.x * xs.x; a0.y += n.x * xs.y; a0.z += n.x * xs.z; a0.w += n.x * xs.w; \
            a1.x += n.y * xs.x; a1.y += n.y * xs.y; a1.z += n.y * xs.z; a1.w += n.y * xs.w; \
            a2.x += n.z * xs.x; a2.y += n.z * xs.y; a2.z += n.z * xs.z; a2.w += n.z * xs.w; \
            a3.x += n.w * xs.x; a3.y += n.w * xs.y; a3.z += n.w * xs.z; a3.w += n.w * xs.w;
        ACC_Z(nA, xA) ACC_Z(nB, xB) ACC_Z(nC, xC) ACC_Z(nD, xD)
    }
    for (; e < e1; e++) {
        int s = csr_src[e];
        float4 n = csr_n4[e];
        float4 xs = h2f4(xh2[s * 32 + lane]);
        ACC_Z(n, xs)
        #undef ACC_Z
    }
    int base = i * 32 + lane;
    float4 aa[4] = {a0, a1, a2, a3};
    #pragma unroll
    for (int k = 0; k < 4; k++) {
        __half2 h0 = __floats2half2_rn(aa[k].x, aa[k].y);
        __half2 h1 = __floats2half2_rn(aa[k].z, aa[k].w);
        uint2 o;
        o.x = *reinterpret_cast<uint32_t*>(&h0);
        o.y = *reinterpret_cast<uint32_t*>(&h1);
        zh2[(size_t)k * NN * 32 + base] = o;
    }
}

template<int HL>
__device__ __forceinline__ void ldhalf(const __half* p, float* v) {
    if (HL == 4) {
        uint2 u = *reinterpret_cast<const uint2*>(p);
        float2 a = __half22float2(*reinterpret_cast<__half2*>(&u.x));
        float2 b = __half22float2(*reinterpret_cast<__half2*>(&u.y));
        v[0] = a.x; v[1] = a.y; v[2] = b.x; v[3] = b.y;
    } else {
        uint4 u = *reinterpret_cast<const uint4*>(p);
        const __half2* h = reinterpret_cast<const __half2*>(&u);
        #pragma unroll
        for (int t = 0; t < 4; t++) {
            float2 f = __half22float2(h[t]);
            v[2 * t] = f.x; v[2 * t + 1] = f.y;
        }
    }
}

// Y[i] = dis_u[i]^2 * M[i] + sum_e nu(e) * M[src(e)]; M fp16, acc fp32. MLP-4 pipeline.
template<int F, int OUTF32>
__global__ void k_gather_u_h(const __half* __restrict__ Mh, const float* __restrict__ dis,
                             const int* __restrict__ rowstart, const int* __restrict__ csr_src,
                             const float* __restrict__ csr_nu, void* __restrict__ Yout) {
    constexpr int HL = F / 32;
    int warp = (blockIdx.x * blockDim.x + threadIdx.x) >> 5;
    int lane = threadIdx.x & 31;
    if (warp >= NN) return;
    int i = warp;
    float du = dis[4 * NN + i];
    float s0 = du * du;
    float acc[HL];
    {
        float v[HL];
        ldhalf<HL>(Mh + (size_t)i * F + lane * HL, v);
        #pragma unroll
        for (int t = 0; t < HL; t++) acc[t] = v[t] * s0;
    }
    int e0 = rowstart[i], e1 = rowstart[i + 1];
    int e = e0;
    for (; e + 4 <= e1; e += 4) {
        int sA = csr_src[e], sB = csr_src[e + 1], sC = csr_src[e + 2], sD = csr_src[e + 3];
        float nA = csr_nu[e], nB = csr_nu[e + 1], nC = csr_nu[e + 2], nD = csr_nu[e + 3];
        float vA[HL], vB[HL], vC[HL], vD[HL];
        ldhalf<HL>(Mh + (size_t)sA * F + lane * HL, vA);
        ldhalf<HL>(Mh + (size_t)sB * F + lane * HL, vB);
        ldhalf<HL>(Mh + (size_t)sC * F + lane * HL, vC);
        ldhalf<HL>(Mh + (size_t)sD * F + lane * HL, vD);
        #pragma unroll
        for (int t = 0; t < HL; t++)
            acc[t] += nA * vA[t] + nB * vB[t] + nC * vC[t] + nD * vD[t];
    }
    for (; e < e1; e++) {
        int s = csr_src[e];
        float nu = csr_nu[e];
        float v[HL];
        ldhalf<HL>(Mh + (size_t)s * F + lane * HL, v);
        #pragma unroll
        for (int t = 0; t < HL; t++) acc[t] += nu * v[t];
    }
    if (OUTF32) {
        float* Y = (float*)Yout;
        #pragma unroll
        for (int q = 0; q < HL / 4; q++)
            *reinterpret_cast<float4*>(&Y[(size_t)i * F + lane * HL + 4 * q]) =
                make_float4(acc[4 * q], acc[4 * q + 1], acc[4 * q + 2], acc[4 * q + 3]);
    } else {
        __half* Yh = (__half*)Yout;
        uint32_t pk[HL / 2];
        #pragma unroll
        for (int t = 0; t < HL / 2; t++) {
            __half2 h = __floats2half2_rn(acc[2 * t], acc[2 * t + 1]);
            pk[t] = *reinterpret_cast<uint32_t*>(&h);
        }
        if (HL == 4)
            *reinterpret_cast<uint2*>(Yh + (size_t)i * F + lane * HL) = make_uint2(pk[0], pk[1]);
        else
            *reinterpret_cast<uint4*>(Yh + (size_t)i * F + lane * HL) =
                make_uint4(pk[0], pk[1], pk[2], pk[3]);
    }
}

// ============ fp16 x fp16-limb mma.sync GEMM ============
// C = op(A)@Bt^T; A fp16 exact, B fp32 split into 2 fp16 limbs (B1 + B2, err 2^-22).
#define ROWPA 24
#define ROWPB 40
#define ASTG  6144                  // 128*48
#define BSTG  10240                 // 128*80
#define STAGE (ASTG + BSTG)         // 16384
#define SMT   (2 * STAGE)           // 32768

__device__ __forceinline__ uint4 ldA16(const __half* __restrict__ Arow, int lda, int rowsA,
                                       int k0, const float* __restrict__ Abias,
                                       int lr, int lq) {
    uint4 u = make_uint4(0, 0, 0, 0);
    if (lr < rowsA) {
        u = *reinterpret_cast<const uint4*>(Arow + (size_t)lr * lda + k0 + lq * 8);
        if (Abias) {
            const __half2* h = reinterpret_cast<const __half2*>(&u);
            float4 b0 = *reinterpret_cast<const float4*>(Abias + k0 + lq * 8);
            float4 b1 = *reinterpret_cast<const float4*>(Abias + k0 + lq * 8 + 4);
            float bb[8] = {b0.x, b0.y, b0.z, b0.w, b1.x, b1.y, b1.z, b1.w};
            uint32_t w[4];
            #pragma unroll
            for (int t = 0; t < 4; t++) {
                float2 f = __half22float2(h[t]);
                __half2 r = __floats2half2_rn(fmaxf(f.x + bb[2 * t], 0.f),
                                              fmaxf(f.y + bb[2 * t + 1], 0.f));
                w[t] = *reinterpret_cast<uint32_t*>(&r);
            }
            u = make_uint4(w[0], w[1], w[2], w[3]);
        }
    }
    return u;
}

__device__ __forceinline__ void ldB16(const float* __restrict__ Bt0, int K, int k0,
                                      int lr, int lq, float* f) {
    float4 v0 = *reinterpret_cast<const float4*>(Bt0 + (size_t)lr * K + k0 + lq * 8);
    float4 v1 = *reinterpret_cast<const float4*>(Bt0 + (size_t)lr * K + k0 + lq * 8 + 4);
    f[0] = v0.x; f[1] = v0.y; f[2] = v0.z; f[3] = v0.w;
    f[4] = v1.x; f[5] = v1.y; f[6] = v1.z; f[7] = v1.w;
}

__device__ __forceinline__ void stB16(char* smB, int lr, int lq, const float* f) {
    uint32_t hw[4], lw[4];
    #pragma unroll
    for (int t = 0; t < 4; t++) {
        __half2 h2 = __floats2half2_rn(f[2 * t], f[2 * t + 1]);
        hw[t] = *reinterpret_cast<uint32_t*>(&h2);
        float lx = f[2 * t] - __half2float(h2.x);
        float ly = f[2 * t + 1] - __half2float(h2.y);
        __half2 l2 = __floats2half2_rn(lx, ly);
        lw[t] = *reinterpret_cast<uint32_t*>(&l2);
    }
    char* pr = smB + (size_t)lr * (ROWPB * 2) + lq * 16;
    *reinterpret_cast<uint4*>(pr)      = make_uint4(hw[0], hw[1], hw[2], hw[3]);
    *reinterpret_cast<uint4*>(pr + 32) = make_uint4(lw[0], lw[1], lw[2], lw[3]);
}

__device__ __forceinline__ void gemm_body(
    const __half* __restrict__ Ah, int lda, const float* __restrict__ Abias,
    const float* __restrict__ Bt0, const float* __restrict__ Cbias,
    __half* __restrict__ Ch, int ldc, int ccol0, int M, int K, int crelu, int row0)
{
    extern __shared__ __align__(128) char sm[];
    uint32_t smu = smem_u32(sm);
    int tid = threadIdx.x;
    const __half* Arow = Ah + (size_t)row0 * lda;
    int rowsA = M - row0;
    int nc = K >> 4;

    int w = tid >> 5, lane = tid & 31;
    int wm = w & 1, wn = w >> 1;
    int j = lane >> 3, rr = lane & 7;
    uint32_t a_off[4], b_off[2];
    #pragma unroll
    for (int mb = 0; mb < 4; mb++)
        a_off[mb] = 2u * ((wm * 64 + mb * 16 + (j & 1) * 8 + rr) * ROWPA + (j >> 1) * 8);
    #pragma unroll
    for (int nbp = 0; nbp < 2; nbp++)
        b_off[nbp] = 2u * ((wn * 32 + nbp * 16 + (j & 1) * 8 + rr) * ROWPB + (j >> 1) * 8);

    int lr = tid >> 1, lq = tid & 1;
    float acc[4][4][4];
    #pragma unroll
    for (int a = 0; a < 4; a++)
        #pragma unroll
        for (int b = 0; b < 4; b++)
            #pragma unroll
            for (int c = 0; c < 4; c++) acc[a][b][c] = 0.f;

    uint4 ua;
    float fb[8];
    ua = ldA16(Arow, lda, rowsA, 0, Abias, lr, lq);
    ldB16(Bt0, K, 0, lr, lq, fb);
    *reinterpret_cast<uint4*>(sm + (size_t)lr * 48 + lq * 16) = ua;
    stB16(sm + ASTG, lr, lq, fb);
    __syncthreads();

    for (int c = 0; c < nc; c++) {
        int cur = c & 1;
        bool has = (c + 1 < nc);
        if (has) {
            int k0 = (c + 1) << 4;
            ua = ldA16(Arow, lda, rowsA, k0, Abias, lr, lq);
            ldB16(Bt0, K, k0, lr, lq, fb);
        }
        uint32_t smA = smu + cur * STAGE;
        uint32_t smB = smA + ASTG;
        uint32_t af[4][4], b1[2][4], b2[2][4];
        #pragma unroll
        for (int mb = 0; mb < 4; mb++)
            ldsm4(af[mb][0], af[mb][1], af[mb][2], af[mb][3], smA + a_off[mb]);
        #pragma unroll
        for (int nbp = 0; nbp < 2; nbp++) {
            ldsm4(b1[nbp][0], b1[nbp][1], b1[nbp][2], b1[nbp][3], smB + b_off[nbp]);
            ldsm4(b2[nbp][0], b2[nbp][1], b2[nbp][2], b2[nbp][3], smB + b_off[nbp] + 32);
        }
        #pragma unroll
        for (int mb = 0; mb < 4; mb++)
            #pragma unroll
            for (int nb = 0; nb < 4; nb++) {
                mma_f16(acc[mb][nb], af[mb], b1[nb >> 1][nb & 1], b1[nb >> 1][2 + (nb & 1)]);
                mma_f16(acc[mb][nb], af[mb], b2[nb >> 1][nb & 1], b2[nb >> 1][2 + (nb & 1)]);
            }
        __syncthreads();
        if (has) {
            char* d = sm + (cur ^ 1) * STAGE;
            *reinterpret_cast<uint4*>(d + (size_t)lr * 48 + lq * 16) = ua;
            stB16(d + ASTG, lr, lq, fb);
        }
        __syncthreads();
    }

    int g = lane >> 2, cq = lane & 3;
    #pragma unroll
    for (int mb = 0; mb < 4; mb++) {
        #pragma unroll
        for (int nb = 0; nb < 4; nb++) {
            int l = wn * 32 + nb * 8 + 2 * cq;
            float bx = 0.f, by = 0.f;
            if (Cbias) { bx = Cbias[l]; by = Cbias[l + 1]; }
            float v0 = acc[mb][nb][0] + bx, v1 = acc[mb][nb][1] + by;
            float v2 = acc[mb][nb][2] + bx, v3 = acc[mb][nb][3] + by;
            if (crelu) {
                v0 = fmaxf(v0, 0.f); v1 = fmaxf(v1, 0.f);
                v2 = fmaxf(v2, 0.f); v3 = fmaxf(v3, 0.f);
            }
            int r0 = row0 + wm * 64 + mb * 16 + g;
            int ccol = ccol0 + l;
            if (r0 < M)
                *reinterpret_cast<__half2*>(Ch + (size_t)r0 * ldc + ccol) =
                    __floats2half2_rn(v0, v1);
            if (r0 + 8 < M)
                *reinterpret_cast<__half2*>(Ch + (size_t)(r0 + 8) * ldc + ccol) =
                    __floats2half2_rn(v2, v3);
        }
    }
}

__global__ __launch_bounds__(256, 2)
void k_gemm_g(const __half* __restrict__ Ah, int lda, const float* __restrict__ Abias,
              const float* __restrict__ Bt, __half* __restrict__ Ch, int ldc,
              int M, int K, int crelu) {
    int n0 = blockIdx.x * 128;
    gemm_body(Ah, lda, Abias, Bt + (size_t)n0 * K, nullptr, Ch, ldc, n0, M, K, crelu,
              blockIdx.y * 128);
}

__global__ __launch_bounds__(256, 2)
void k_gemm_c1(const __half* __restrict__ zh, const float* __restrict__ Wt1,
               const float* __restrict__ bA, const float* __restrict__ bB,
               const float* __restrict__ bC, const float* __restrict__ bD,
               __half* __restrict__ Hh, int M) {
    int k = blockIdx.x;
    const float* bias = (k == 0) ? bA : (k == 1) ? bB : (k == 2) ? bC : bD;
    gemm_body(zh + (size_t)k * NN * DD, DD, nullptr, Wt1 + (size_t)k * DD * DD, bias,
              Hh, 4 * DD, k * DD, M, DD, 1, blockIdx.y * 128);
}

// ---------------- pooling ----------------
__global__ void k_pool_init(float* psum, unsigned* pmax, float* pcnt) {
    int i = blockIdx.x * blockDim.x + threadIdx.x;
    if (i < NG * DD) { psum[i] = 0.0f; pmax[i] = 0x007fffffu; }
    if (i < NG) pcnt[i] = 0.0f;
}

#define POOL_CHUNK 128
__global__ void k_pool(const float* __restrict__ Y3, const float* __restrict__ b3,
                       const int* __restrict__ batch,
                       float* psum, unsigned* pmax, float* pcnt) {
    int j = threadIdx.x;
    int i0 = blockIdx.x * POOL_CHUNK;
    int iend = min(i0 + POOL_CHUNK, NN);
    float bj = b3[j];
    int cur = -1;
    float s = 0.0f, m = __int_as_float(0xff800000), cnt = 0.0f;
    for (int i = i0; i < iend; i++) {
        int g = batch[i];
        if (g != cur) {
            if (cur >= 0) {
                atomicAdd(&psum[cur * DD + j], s);
                atomicMax(&pmax[cur * DD + j], fenc(m));
                if (j == 0) atomicAdd(&pcnt[cur], cnt);
            }
            cur = g; s = 0.0f; m = __int_as_float(0xff800000); cnt = 0.0f;
        }
        float y = Y3[(size_t)i * DD + j] + bj;
        s += y;
        m = fmaxf(m, y);
        cnt += 1.0f;
    }
    if (cur >= 0) {
        atomicAdd(&psum[cur * DD + j], s);
        atomicMax(&pmax[cur * DD + j], fenc(m));
        if (j == 0) atomicAdd(&pcnt[cur], cnt);
    }
}

// ---------------- MLP head ----------------
__global__ void k_mlp(const float* __restrict__ Wm1, const float* __restrict__ bm1,
                      const float* __restrict__ Wm2, const float* __restrict__ bm2,
                      const float* __restrict__ psum, const unsigned* __restrict__ pmax,
                      const float* __restrict__ pcnt, float* __restrict__ out) {
    int g = threadIdx.x;
    if (g >= NG) return;
    float cnt = pcnt[g];
    float inv = 1.0f / fmaxf(cnt, 1.0f);
    float hid[8];
    #pragma unroll
    for (int h = 0; h < 8; h++) hid[h] = bm1[h];
    for (int j = 0; j < DD; j++) {
        float mean = psum[g * DD + j] * inv;
        #pragma unroll
        for (int h = 0; h < 8; h++) hid[h] += mean * Wm1[j * 8 + h];
    }
    for (int j = 0; j < DD; j++) {
        float mx = (cnt > 0.0f) ? fdec(pmax[g * DD + j]) : 0.0f;
        #pragma unroll
        for (int h = 0; h < 8; h++) hid[h] += mx * Wm1[(DD + j) * 8 + h];
    }
    #pragma unroll
    for (int h = 0; h < 8; h++) hid[h] = fmaxf(hid[h], 0.0f);
    #pragma unroll
    for (int c = 0; c < 2; c++) {
        float o = bm2[c];
        #pragma unroll
        for (int h = 0; h < 8; h++) o += hid[h] * Wm2[h * 2 + c];
        out[g * 2 + c] = o;
    }
}

// ---------------- driver ----------------
extern "C" void kernel_launch(void* const* d_in, const int* in_sizes, int n_in,
                              void* d_out, int out_size) {
    const float* x     = (const float*)d_in[0];
    const int*   ei    = (const int*)d_in[1];
    const float* ea    = (const float*)d_in[2];
    const int*   batch = (const int*)d_in[3];
    const float* W1A = (const float*)d_in[4];
    const float* b1A = (const float*)d_in[5];
    const float* W1B = (const float*)d_in[6];
    const float* b1B = (const float*)d_in[7];
    const float* W1C = (const float*)d_in[8];
    const float* b1C = (const float*)d_in[9];
    const float* W1D = (const float*)d_in[10];
    const float* b1D = (const float*)d_in[11];
    const float* W2  = (const float*)d_in[12];
    const float* b2  = (const float*)d_in[13];
    const float* W3  = (const float*)d_in[14];
    const float* b3  = (const float*)d_in[15];
    const float* Wm1 = (const float*)d_in[16];
    const float* bm1 = (const float*)d_in[17];
    const float* Wm2 = (const float*)d_in[18];
    const float* bm2 = (const float*)d_in[19];
    float* out = (float*)d_out;

    float *dis, *csr_nu, *Y3, *Wt1, *Wt2, *Wt3, *psum, *pcnt;
    int *cursor, *rowstart, *bsum, *csr_src;
    float4* csr_n4;
    unsigned* pmax;
    __half *xh, *zh, *Hh, *M2h, *Y2h, *M3h;
    cudaGetSymbolAddress((void**)&dis,      g_dis);
    cudaGetSymbolAddress((void**)&cursor,   g_cursor);
    cudaGetSymbolAddress((void**)&rowstart, g_rowstart);
    cudaGetSymbolAddress((void**)&bsum,     g_bsum);
    cudaGetSymbolAddress((void**)&csr_src,  g_csr_src);
    cudaGetSymbolAddress((void**)&csr_n4,   g_csr_n4);
    cudaGetSymbolAddress((void**)&csr_nu,   g_csr_nu);
    cudaGetSymbolAddress((void**)&xh,       g_xh);
    cudaGetSymbolAddress((void**)&zh,       g_zh);
    cudaGetSymbolAddress((void**)&Hh,       g_Hh);
    cudaGetSymbolAddress((void**)&M2h,      g_M2h);
    cudaGetSymbolAddress((void**)&Y2h,      g_Y2h);
    cudaGetSymbolAddress((void**)&M3h,      g_M3h);
    cudaGetSymbolAddress((void**)&Y3,       g_Y3);
    cudaGetSymbolAddress((void**)&Wt1,      g_Wt1);
    cudaGetSymbolAddress((void**)&Wt2,      g_Wt2);
    cudaGetSymbolAddress((void**)&Wt3,      g_Wt3);
    cudaGetSymbolAddress((void**)&psum,     g_psum);
    cudaGetSymbolAddress((void**)&pmax,     g_pmax);
    cudaGetSymbolAddress((void**)&pcnt,     g_pcnt);

    cudaFuncSetAttribute(k_gemm_g, cudaFuncAttributeMaxDynamicSharedMemorySize, SMT);
    cudaFuncSetAttribute(k_gemm_c1, cudaFuncAttributeMaxDynamicSharedMemorySize, SMT);

    const int NB = (NN + 1023) / 1024;
    const int MT = (NN + 127) / 128;   // 391
    const int TRN = 4 * DD * DD + 4 * DD * 2 * DD + 2 * DD * DD;  // 229376

    // 0. prep: transposes + x->fp16
    k_tr_all<<<(TRN + 255) / 256, 256>>>(W1A, W1B, W1C, W1D, W2, W3, Wt1, Wt2, Wt3);
    k_x2h<<<(NN * 16 + 255) / 256, 256>>>((const float4*)x, (uint4*)xh);

    // 1. degrees + CSR
    k_init<<<(5 * NN + 255) / 256, 256>>>(dis, cursor);
    k_deg_edges<<<(NE + 255) / 256, 256>>>(ei, ea, dis);
    k_scan_block<<<NB, 1024>>>(dis, rowstart, bsum);
    k_scan_top<<<1, 32>>>(bsum, NB);
    k_scan_add<<<NB, 1024>>>(rowstart, bsum);
    k_rsqrt<<<(5 * NN + 255) / 256, 256>>>(dis);
    k_csr_fill<<<(NE + 255) / 256, 256>>>(ei, ea, dis, rowstart, cursor,
                                          csr_src, csr_n4, csr_nu);

    // 2. conv1 aggregation of x:  z_k = S_k x  (fp16 in/out, fp32 accum)
    k_gather_z_h<<<(NN * 32 + 255) / 256, 256>>>(
        (const uint2*)xh, dis, rowstart, csr_src, csr_n4, (uint2*)zh);

    // 3. conv1 fused GEMMs
    k_gemm_c1<<<dim3(4, MT), 256, SMT>>>(zh, Wt1, b1A, b1B, b1C, b1D, Hh, NN);

    // 4. conv2: M2 = H @ W2, then aggregate
    k_gemm_g<<<dim3(2, MT), 256, SMT>>>(Hh, 4 * DD, nullptr, Wt2, M2h, 2 * DD, NN, 4 * DD, 0);
    k_gather_u_h<256, 0><<<(NN * 32 + 255) / 256, 256>>>(
        M2h, dis, rowstart, csr_src, csr_nu, (void*)Y2h);

    // 5. conv3: M3 = relu(Y2 + b2) @ W3, then aggregate (fp32 out for pooling)
    k_gemm_g<<<dim3(1, MT), 256, SMT>>>(Y2h, 2 * DD, b2, Wt3, M3h, DD, NN, 2 * DD, 0);
    k_gather_u_h<128, 1><<<(NN * 32 + 255) / 256, 256>>>(
        M3h, dis, rowstart, csr_src, csr_nu, (void*)Y3);

    // 6. pooling (b3 folded in) + MLP head
    k_pool_init<<<(NG * DD + 255) / 256, 256>>>(psum, pmax, pcnt);
    k_pool<<<(NN + POOL_CHUNK - 1) / POOL_CHUNK, DD>>>(Y3, b3, batch, psum, pmax, pcnt);
    k_mlp<<<1, 64>>>(Wm1, bm1, Wm2, bm2, psum, pmax, pcnt, out);
}

// round 17
// speedup vs baseline: 4.0797x; 1.0558x over previous
#include <cuda_runtime.h>
#include <cuda_bf16.h>
#include <cuda_fp16.h>
#include <cstdint>

#define NN 50000
#define NE 600000
#define DD 128
#define NG 64

// ---------------- scratch (static __device__, allocation-free) ----------------
static __device__ float    g_dis[5 * NN];        // rsqrt degrees: k=0..3 weighted, 4 unweighted
static __device__ int      g_cursor[NN];
static __device__ int      g_rowstart[NN + 1];
static __device__ int      g_bsum[64];
static __device__ int      g_csr_src[NE];
static __device__ float4   g_csr_n4[NE];
static __device__ float    g_csr_nu[NE];
static __device__ __align__(16) __half g_xh[NN * DD];        // fp16 x
static __device__ __align__(16) __half g_zh[4 * NN * DD];    // fp16 z_k = S_k x
static __device__ __align__(16) __half g_Hh[NN * 4 * DD];    // fp16 concat relu(z W + b)
static __device__ __align__(16) __half g_M2h[NN * 2 * DD];   // fp16 H @ W2
static __device__ __align__(16) __half g_Y2h[NN * 2 * DD];   // fp16 S_u M2
static __device__ __align__(16) __half g_M3h[NN * DD];       // fp16 relu(Y2+b2) @ W3
static __device__ float    g_Y3[NN * DD];                    // fp32 S_u M3 (pool input)
static __device__ float    g_Wt1[4 * DD * DD];
static __device__ float    g_Wt2[2 * DD * 4 * DD];
static __device__ float    g_Wt3[DD * 2 * DD];
static __device__ float    g_psum[NG * DD];
static __device__ unsigned g_pmax[NG * DD];
static __device__ float    g_pcnt[NG];

// ---------------- small helpers ----------------
__device__ __forceinline__ unsigned fenc(float f) {
    unsigned b = __float_as_uint(f);
    return (b & 0x80000000u) ? ~b : (b | 0x80000000u);
}
__device__ __forceinline__ float fdec(unsigned u) {
    return (u & 0x80000000u) ? __uint_as_float(u & 0x7fffffffu) : __uint_as_float(~u);
}
__device__ __forceinline__ uint32_t smem_u32(const void* p) {
    uint32_t a;
    asm("{ .reg .u64 t; cvta.to.shared.u64 t, %1; cvt.u32.u64 %0, t; }" : "=r"(a) : "l"(p));
    return a;
}
__device__ __forceinline__ void ldsm4(uint32_t& r0, uint32_t& r1, uint32_t& r2, uint32_t& r3,
                                      uint32_t addr) {
    asm volatile("ldmatrix.sync.aligned.m8n8.x4.shared.b16 {%0,%1,%2,%3}, [%4];"
                 : "=r"(r0), "=r"(r1), "=r"(r2), "=r"(r3) : "r"(addr));
}
__device__ __forceinline__ void mma_f16(float* c, const uint32_t* a, uint32_t b0, uint32_t b1) {
    asm volatile(
        "mma.sync.aligned.m16n8k16.row.col.f32.f16.f16.f32 "
        "{%0,%1,%2,%3}, {%4,%5,%6,%7}, {%8,%9}, {%0,%1,%2,%3};"
        : "+f"(c[0]), "+f"(c[1]), "+f"(c[2]), "+f"(c[3])
        : "r"(a[0]), "r"(a[1]), "r"(a[2]), "r"(a[3]), "r"(b0), "r"(b1));
}

// ---------------- prep: x -> fp16, weight transposes ----------------
__global__ void k_x2h(const float4* __restrict__ x4, uint4* __restrict__ xh4) {
    int i = blockIdx.x * blockDim.x + threadIdx.x;
    if (i >= NN * 16) return;
    float4 a = x4[2 * i], b = x4[2 * i + 1];
    __half2 h0 = __floats2half2_rn(a.x, a.y), h1 = __floats2half2_rn(a.z, a.w);
    __half2 h2 = __floats2half2_rn(b.x, b.y), h3 = __floats2half2_rn(b.z, b.w);
    uint4 u;
    u.x = *reinterpret_cast<uint32_t*>(&h0); u.y = *reinterpret_cast<uint32_t*>(&h1);
    u.z = *reinterpret_cast<uint32_t*>(&h2); u.w = *reinterpret_cast<uint32_t*>(&h3);
    xh4[i] = u;
}

__global__ void k_tr_all(const float* __restrict__ W1A, const float* __restrict__ W1B,
                         const float* __restrict__ W1C, const float* __restrict__ W1D,
                         const float* __restrict__ W2, const float* __restrict__ W3,
                         float* __restrict__ Wt1, float* __restrict__ Wt2,
                         float* __restrict__ Wt3) {
    int i = blockIdx.x * blockDim.x + threadIdx.x;
    if (i < 4 * DD * DD) {
        int wsel = i >> 14, rem = i & 16383;
        int k = rem >> 7, n = rem & 127;
        const float* W = (wsel == 0) ? W1A : (wsel == 1) ? W1B : (wsel == 2) ? W1C : W1D;
        Wt1[wsel * DD * DD + n * DD + k] = W[rem];
    } else if (i < 4 * DD * DD + 4 * DD * 2 * DD) {
        int rem = i - 4 * DD * DD;           // K=512, N=256
        int k = rem >> 8, n = rem & 255;
        Wt2[n * 512 + k] = W2[rem];
    } else if (i < 4 * DD * DD + 4 * DD * 2 * DD + 2 * DD * DD) {
        int rem = i - 4 * DD * DD - 4 * DD * 2 * DD;  // K=256, N=128
        int k = rem >> 7, n = rem & 127;
        Wt3[n * 256 + k] = W3[rem];
    }
}

// ---------------- degree + CSR build ----------------
__global__ void k_init(float* dis, int* cursor) {
    int i = blockIdx.x * blockDim.x + threadIdx.x;
    if (i < 5 * NN) dis[i] = 1.0f;
    if (i < NN) cursor[i] = 0;
}

__global__ void k_deg_edges(const int* __restrict__ ei, const float* __restrict__ ea,
                            float* dis) {
    int e = blockIdx.x * blockDim.x + threadIdx.x;
    if (e >= NE) return;
    int d = ei[NE + e];
    float4 w = *reinterpret_cast<const float4*>(&ea[e * 4]);
    atomicAdd(&dis[0 * NN + d], w.x);
    atomicAdd(&dis[1 * NN + d], w.y);
    atomicAdd(&dis[2 * NN + d], w.z);
    atomicAdd(&dis[3 * NN + d], w.w);
    atomicAdd(&dis[4 * NN + d], 1.0f);
}

__global__ void k_rsqrt(float* dis) {
    int i = blockIdx.x * blockDim.x + threadIdx.x;
    if (i < 5 * NN) dis[i] = rsqrtf(dis[i]);
}

// in-degree derived from unweighted degree (init 1 + 1 per edge) -> no cnt atomics
__global__ void k_scan_block(const float* __restrict__ deg, int* __restrict__ rowstart,
                             int* __restrict__ bsum) {
    __shared__ int sh[1024];
    int i = blockIdx.x * 1024 + threadIdx.x;
    int v = (i < NN) ? (__float2int_rn(deg[4 * NN + i]) - 1) : 0;
    sh[threadIdx.x] = v;
    __syncthreads();
    #pragma unroll
    for (int off = 1; off < 1024; off <<= 1) {
        int t = (threadIdx.x >= off) ? sh[threadIdx.x - off] : 0;
        __syncthreads();
        sh[threadIdx.x] += t;
        __syncthreads();
    }
    if (i < NN) rowstart[i] = sh[threadIdx.x] - v;
    if (threadIdx.x == 1023) bsum[blockIdx.x] = sh[1023];
}

__global__ void k_scan_top(int* bsum, int nb) {
    if (threadIdx.x == 0) {
        int run = 0;
        for (int b = 0; b < nb; b++) { int t = bsum[b]; bsum[b] = run; run += t; }
    }
}

__global__ void k_scan_add(int* rowstart, const int* __restrict__ bsum) {
    int i = blockIdx.x * 1024 + threadIdx.x;
    if (i < NN) rowstart[i] += bsum[blockIdx.x];
    if (blockIdx.x == 0 && threadIdx.x == 0) rowstart[NN] = NE;
}

__global__ void k_csr_fill(const int* __restrict__ ei, const float* __restrict__ ea,
                           const float* __restrict__ dis, const int* __restrict__ rowstart,
                           int* cursor, int* __restrict__ csr_src,
                           float4* __restrict__ csr_n4, float* __restrict__ csr_nu) {
    int e = blockIdx.x * blockDim.x + threadIdx.x;
    if (e >= NE) return;
    int s = ei[e], d = ei[NE + e];
    int pos = rowstart[d] + atomicAdd(&cursor[d], 1);
    csr_src[pos] = s;
    float4 w = *reinterpret_cast<const float4*>(&ea[e * 4]);
    float4 n;
    n.x = dis[0 * NN + s] * w.x * dis[0 * NN + d];
    n.y = dis[1 * NN + s] * w.y * dis[1 * NN + d];
    n.z = dis[2 * NN + s] * w.z * dis[2 * NN + d];
    n.w = dis[3 * NN + s] * w.w * dis[3 * NN + d];
    csr_n4[pos] = n;
    csr_nu[pos] = dis[4 * NN + s] * dis[4 * NN + d];
}

// ---------------- gather aggregations (fp16 in, no atomics, MLP-4 pipelined) --------
__device__ __forceinline__ float4 h2f4(uint2 u) {
    float2 a = __half22float2(*reinterpret_cast<__half2*>(&u.x));
    float2 b = __half22float2(*reinterpret_cast<__half2*>(&u.y));
    return make_float4(a.x, a.y, b.x, b.y);
}

__global__ void k_gather_z_h(const uint2* __restrict__ xh2, const float* __restrict__ dis,
                             const int* __restrict__ rowstart, const int* __restrict__ csr_src,
                             const float4* __restrict__ csr_n4, uint2* __restrict__ zh2) {
    int warp = (blockIdx.x * blockDim.x + threadIdx.x) >> 5;
    int lane = threadIdx.x & 31;
    if (warp >= NN) return;
    int i = warp;
    float4 xv = h2f4(xh2[i * 32 + lane]);
    float d0 = dis[i], d1 = dis[NN + i], d2 = dis[2 * NN + i], d3 = dis[3 * NN + i];
    float s0 = d0 * d0, s1 = d1 * d1, s2 = d2 * d2, s3 = d3 * d3;
    float4 a0 = make_float4(xv.x * s0, xv.y * s0, xv.z * s0, xv.w * s0);
    float4 a1 = make_float4(xv.x * s1, xv.y * s1, xv.z * s1, xv.w * s1);
    float4 a2 = make_float4(xv.x * s2, xv.y * s2, xv.z * s2, xv.w * s2);
    float4 a3 = make_float4(xv.x * s3, xv.y * s3, xv.z * s3, xv.w * s3);
    int e0 = rowstart[i], e1 = rowstart[i + 1];
    int e = e0;
    for (; e + 4 <= e1; e += 4) {
        int sA = csr_src[e], sB = csr_src[e + 1], sC = csr_src[e + 2], sD = csr_src[e + 3];
        float4 nA = csr_n4[e], nB = csr_n4[e + 1], nC = csr_n4[e + 2], nD = csr_n4[e + 3];
        float4 xA = h2f4(xh2[sA * 32 + lane]);
        float4 xB = h2f4(xh2[sB * 32 + lane]);
        float4 xC = h2f4(xh2[sC * 32 + lane]);
        float4 xD = h2f4(xh2[sD * 32 + lane]);
        #define ACC_Z(n, xs) \
            a0.x += n.x * xs.x; a0.y += n.x * xs.y; a0.z += n.x * xs.z; a0.w += n.x * xs.w; \
            a1.x += n.y * xs.x; a1.y += n.y * xs.y; a1.z += n.y * xs.z; a1.w += n.y * xs.w; \
            a2.x += n.z * xs.x; a2.y += n.z * xs.y; a2.z += n.z * xs.z; a2.w += n.z * xs.w; \
            a3.x += n.w * xs.x; a3.y += n.w * xs.y; a3.z += n.w * xs.z; a3.w += n.w * xs.w;
        ACC_Z(nA, xA) ACC_Z(nB, xB) ACC_Z(nC, xC) ACC_Z(nD, xD)
    }
    for (; e < e1; e++) {
        int s = csr_src[e];
        float4 n = csr_n4[e];
        float4 xs = h2f4(xh2[s * 32 + lane]);
        ACC_Z(n, xs)
        #undef ACC_Z
    }
    int base = i * 32 + lane;
    float4 aa[4] = {a0, a1, a2, a3};
    #pragma unroll
    for (int k = 0; k < 4; k++) {
        __half2 h0 = __floats2half2_rn(aa[k].x, aa[k].y);
        __half2 h1 = __floats2half2_rn(aa[k].z, aa[k].w);
        uint2 o;
        o.x = *reinterpret_cast<uint32_t*>(&h0);
        o.y = *reinterpret_cast<uint32_t*>(&h1);
        zh2[(size_t)k * NN * 32 + base] = o;
    }
}

template<int HL>
__device__ __forceinline__ void ldhalf(const __half* p, float* v) {
    if (HL == 4) {
        uint2 u = *reinterpret_cast<const uint2*>(p);
        float2 a = __half22float2(*reinterpret_cast<__half2*>(&u.x));
        float2 b = __half22float2(*reinterpret_cast<__half2*>(&u.y));
        v[0] = a.x; v[1] = a.y; v[2] = b.x; v[3] = b.y;
    } else {
        uint4 u = *reinterpret_cast<const uint4*>(p);
        const __half2* h = reinterpret_cast<const __half2*>(&u);
        #pragma unroll
        for (int t = 0; t < 4; t++) {
            float2 f = __half22float2(h[t]);
            v[2 * t] = f.x; v[2 * t + 1] = f.y;
        }
    }
}

// Y[i] = dis_u[i]^2 * M[i] + sum_e nu(e) * M[src(e)]; M fp16, acc fp32. MLP-4 pipeline.
template<int F, int OUTF32>
__global__ void k_gather_u_h(const __half* __restrict__ Mh, const float* __restrict__ dis,
                             const int* __restrict__ rowstart, const int* __restrict__ csr_src,
                             const float* __restrict__ csr_nu, void* __restrict__ Yout) {
    constexpr int HL = F / 32;
    int warp = (blockIdx.x * blockDim.x + threadIdx.x) >> 5;
    int lane = threadIdx.x & 31;
    if (warp >= NN) return;
    int i = warp;
    float du = dis[4 * NN + i];
    float s0 = du * du;
    float acc[HL];
    {
        float v[HL];
        ldhalf<HL>(Mh + (size_t)i * F + lane * HL, v);
        #pragma unroll
        for (int t = 0; t < HL; t++) acc[t] = v[t] * s0;
    }
    int e0 = rowstart[i], e1 = rowstart[i + 1];
    int e = e0;
    for (; e + 4 <= e1; e += 4) {
        int sA = csr_src[e], sB = csr_src[e + 1], sC = csr_src[e + 2], sD = csr_src[e + 3];
        float nA = csr_nu[e], nB = csr_nu[e + 1], nC = csr_nu[e + 2], nD = csr_nu[e + 3];
        float vA[HL], vB[HL], vC[HL], vD[HL];
        ldhalf<HL>(Mh + (size_t)sA * F + lane * HL, vA);
        ldhalf<HL>(Mh + (size_t)sB * F + lane * HL, vB);
        ldhalf<HL>(Mh + (size_t)sC * F + lane * HL, vC);
        ldhalf<HL>(Mh + (size_t)sD * F + lane * HL, vD);
        #pragma unroll
        for (int t = 0; t < HL; t++)
            acc[t] += nA * vA[t] + nB * vB[t] + nC * vC[t] + nD * vD[t];
    }
    for (; e < e1; e++) {
        int s = csr_src[e];
        float nu = csr_nu[e];
        float v[HL];
        ldhalf<HL>(Mh + (size_t)s * F + lane * HL, v);
        #pragma unroll
        for (int t = 0; t < HL; t++) acc[t] += nu * v[t];
    }
    if (OUTF32) {
        float* Y = (float*)Yout;
        #pragma unroll
        for (int q = 0; q < HL / 4; q++)
            *reinterpret_cast<float4*>(&Y[(size_t)i * F + lane * HL + 4 * q]) =
                make_float4(acc[4 * q], acc[4 * q + 1], acc[4 * q + 2], acc[4 * q + 3]);
    } else {
        __half* Yh = (__half*)Yout;
        uint32_t pk[HL / 2];
        #pragma unroll
        for (int t = 0; t < HL / 2; t++) {
            __half2 h = __floats2half2_rn(acc[2 * t], acc[2 * t + 1]);
            pk[t] = *reinterpret_cast<uint32_t*>(&h);
        }
        if (HL == 4)
            *reinterpret_cast<uint2*>(Yh + (size_t)i * F + lane * HL) = make_uint2(pk[0], pk[1]);
        else
            *reinterpret_cast<uint4*>(Yh + (size_t)i * F + lane * HL) =
                make_uint4(pk[0], pk[1], pk[2], pk[3]);
    }
}

// ============ fp16 x fp16 mma.sync GEMM (single-limb weights) ============
// C = op(A)@Bt^T; A fp16 exact, B fp32 rounded to fp16 (err ~2^-11 rel, fp32 accum).
// Per 16-K chunk: A and B smem [128 x 16h], rows padded to 24h (48 B, conflict-free).
#define ROWPA 24
#define ROWPB 24
#define ASTG  6144                  // 128*48
#define BSTG  6144                  // 128*48
#define STAGE (ASTG + BSTG)         // 12288
#define SMT   (2 * STAGE)           // 24576

__device__ __forceinline__ uint4 ldA16(const __half* __restrict__ Arow, int lda, int rowsA,
                                       int k0, const float* __restrict__ Abias,
                                       int lr, int lq) {
    uint4 u = make_uint4(0, 0, 0, 0);
    if (lr < rowsA) {
        u = *reinterpret_cast<const uint4*>(Arow + (size_t)lr * lda + k0 + lq * 8);
        if (Abias) {
            const __half2* h = reinterpret_cast<const __half2*>(&u);
            float4 b0 = *reinterpret_cast<const float4*>(Abias + k0 + lq * 8);
            float4 b1 = *reinterpret_cast<const float4*>(Abias + k0 + lq * 8 + 4);
            float bb[8] = {b0.x, b0.y, b0.z, b0.w, b1.x, b1.y, b1.z, b1.w};
            uint32_t w[4];
            #pragma unroll
            for (int t = 0; t < 4; t++) {
                float2 f = __half22float2(h[t]);
                __half2 r = __floats2half2_rn(fmaxf(f.x + bb[2 * t], 0.f),
                                              fmaxf(f.y + bb[2 * t + 1], 0.f));
                w[t] = *reinterpret_cast<uint32_t*>(&r);
            }
            u = make_uint4(w[0], w[1], w[2], w[3]);
        }
    }
    return u;
}

// load 16 fp32 weights (one row-chunk), round to fp16, return packed uint4
__device__ __forceinline__ uint4 ldB16h(const float* __restrict__ Bt0, int K, int k0,
                                        int lr, int lq) {
    float4 v0 = *reinterpret_cast<const float4*>(Bt0 + (size_t)lr * K + k0 + lq * 8);
    float4 v1 = *reinterpret_cast<const float4*>(Bt0 + (size_t)lr * K + k0 + lq * 8 + 4);
    __half2 h0 = __floats2half2_rn(v0.x, v0.y);
    __half2 h1 = __floats2half2_rn(v0.z, v0.w);
    __half2 h2 = __floats2half2_rn(v1.x, v1.y);
    __half2 h3 = __floats2half2_rn(v1.z, v1.w);
    uint4 u;
    u.x = *reinterpret_cast<uint32_t*>(&h0);
    u.y = *reinterpret_cast<uint32_t*>(&h1);
    u.z = *reinterpret_cast<uint32_t*>(&h2);
    u.w = *reinterpret_cast<uint32_t*>(&h3);
    return u;
}

__device__ __forceinline__ void gemm_body(
    const __half* __restrict__ Ah, int lda, const float* __restrict__ Abias,
    const float* __restrict__ Bt0, const float* __restrict__ Cbias,
    __half* __restrict__ Ch, int ldc, int ccol0, int M, int K, int crelu, int row0)
{
    extern __shared__ __align__(128) char sm[];
    uint32_t smu = smem_u32(sm);
    int tid = threadIdx.x;
    const __half* Arow = Ah + (size_t)row0 * lda;
    int rowsA = M - row0;
    int nc = K >> 4;

    int w = tid >> 5, lane = tid & 31;
    int wm = w & 1, wn = w >> 1;
    int j = lane >> 3, rr = lane & 7;
    uint32_t a_off[4], b_off[2];
    #pragma unroll
    for (int mb = 0; mb < 4; mb++)
        a_off[mb] = 2u * ((wm * 64 + mb * 16 + (j & 1) * 8 + rr) * ROWPA + (j >> 1) * 8);
    #pragma unroll
    for (int nbp = 0; nbp < 2; nbp++)
        b_off[nbp] = 2u * ((wn * 32 + nbp * 16 + (j & 1) * 8 + rr) * ROWPB + (j >> 1) * 8);

    int lr = tid >> 1, lq = tid & 1;
    float acc[4][4][4];
    #pragma unroll
    for (int a = 0; a < 4; a++)
        #pragma unroll
        for (int b = 0; b < 4; b++)
            #pragma unroll
            for (int c = 0; c < 4; c++) acc[a][b][c] = 0.f;

    uint4 ua, ub;
    ua = ldA16(Arow, lda, rowsA, 0, Abias, lr, lq);
    ub = ldB16h(Bt0, K, 0, lr, lq);
    *reinterpret_cast<uint4*>(sm + (size_t)lr * 48 + lq * 16) = ua;
    *reinterpret_cast<uint4*>(sm + ASTG + (size_t)lr * 48 + lq * 16) = ub;
    __syncthreads();

    for (int c = 0; c < nc; c++) {
        int cur = c & 1;
        bool has = (c + 1 < nc);
        if (has) {
            int k0 = (c + 1) << 4;
            ua = ldA16(Arow, lda, rowsA, k0, Abias, lr, lq);
            ub = ldB16h(Bt0, K, k0, lr, lq);
        }
        uint32_t smA = smu + cur * STAGE;
        uint32_t smB = smA + ASTG;
        uint32_t af[4][4], b1[2][4];
        #pragma unroll
        for (int mb = 0; mb < 4; mb++)
            ldsm4(af[mb][0], af[mb][1], af[mb][2], af[mb][3], smA + a_off[mb]);
        #pragma unroll
        for (int nbp = 0; nbp < 2; nbp++)
            ldsm4(b1[nbp][0], b1[nbp][1], b1[nbp][2], b1[nbp][3], smB + b_off[nbp]);
        #pragma unroll
        for (int mb = 0; mb < 4; mb++)
            #pragma unroll
            for (int nb = 0; nb < 4; nb++)
                mma_f16(acc[mb][nb], af[mb], b1[nb >> 1][nb & 1], b1[nb >> 1][2 + (nb & 1)]);
        __syncthreads();
        if (has) {
            char* d = sm + (cur ^ 1) * STAGE;
            *reinterpret_cast<uint4*>(d + (size_t)lr * 48 + lq * 16) = ua;
            *reinterpret_cast<uint4*>(d + ASTG + (size_t)lr * 48 + lq * 16) = ub;
        }
        __syncthreads();
    }

    int g = lane >> 2, cq = lane & 3;
    #pragma unroll
    for (int mb = 0; mb < 4; mb++) {
        #pragma unroll
        for (int nb = 0; nb < 4; nb++) {
            int l = wn * 32 + nb * 8 + 2 * cq;
            float bx = 0.f, by = 0.f;
            if (Cbias) { bx = Cbias[l]; by = Cbias[l + 1]; }
            float v0 = acc[mb][nb][0] + bx, v1 = acc[mb][nb][1] + by;
            float v2 = acc[mb][nb][2] + bx, v3 = acc[mb][nb][3] + by;
            if (crelu) {
                v0 = fmaxf(v0, 0.f); v1 = fmaxf(v1, 0.f);
                v2 = fmaxf(v2, 0.f); v3 = fmaxf(v3, 0.f);
            }
            int r0 = row0 + wm * 64 + mb * 16 + g;
            int ccol = ccol0 + l;
            if (r0 < M)
                *reinterpret_cast<__half2*>(Ch + (size_t)r0 * ldc + ccol) =
                    __floats2half2_rn(v0, v1);
            if (r0 + 8 < M)
                *reinterpret_cast<__half2*>(Ch + (size_t)(r0 + 8) * ldc + ccol) =
                    __floats2half2_rn(v2, v3);
        }
    }
}

__global__ __launch_bounds__(256, 2)
void k_gemm_g(const __half* __restrict__ Ah, int lda, const float* __restrict__ Abias,
              const float* __restrict__ Bt, __half* __restrict__ Ch, int ldc,
              int M, int K, int crelu) {
    int n0 = blockIdx.x * 128;
    gemm_body(Ah, lda, Abias, Bt + (size_t)n0 * K, nullptr, Ch, ldc, n0, M, K, crelu,
              blockIdx.y * 128);
}

__global__ __launch_bounds__(256, 2)
void k_gemm_c1(const __half* __restrict__ zh, const float* __restrict__ Wt1,
               const float* __restrict__ bA, const float* __restrict__ bB,
               const float* __restrict__ bC, const float* __restrict__ bD,
               __half* __restrict__ Hh, int M) {
    int k = blockIdx.x;
    const float* bias = (k == 0) ? bA : (k == 1) ? bB : (k == 2) ? bC : bD;
    gemm_body(zh + (size_t)k * NN * DD, DD, nullptr, Wt1 + (size_t)k * DD * DD, bias,
              Hh, 4 * DD, k * DD, M, DD, 1, blockIdx.y * 128);
}

// ---------------- pooling ----------------
__global__ void k_pool_init(float* psum, unsigned* pmax, float* pcnt) {
    int i = blockIdx.x * blockDim.x + threadIdx.x;
    if (i < NG * DD) { psum[i] = 0.0f; pmax[i] = 0x007fffffu; }
    if (i < NG) pcnt[i] = 0.0f;
}

#define POOL_CHUNK 128
__global__ void k_pool(const float* __restrict__ Y3, const float* __restrict__ b3,
                       const int* __restrict__ batch,
                       float* psum, unsigned* pmax, float* pcnt) {
    int j = threadIdx.x;
    int i0 = blockIdx.x * POOL_CHUNK;
    int iend = min(i0 + POOL_CHUNK, NN);
    float bj = b3[j];
    int cur = -1;
    float s = 0.0f, m = __int_as_float(0xff800000), cnt = 0.0f;
    for (int i = i0; i < iend; i++) {
        int g = batch[i];
        if (g != cur) {
            if (cur >= 0) {
                atomicAdd(&psum[cur * DD + j], s);
                atomicMax(&pmax[cur * DD + j], fenc(m));
                if (j == 0) atomicAdd(&pcnt[cur], cnt);
            }
            cur = g; s = 0.0f; m = __int_as_float(0xff800000); cnt = 0.0f;
        }
        float y = Y3[(size_t)i * DD + j] + bj;
        s += y;
        m = fmaxf(m, y);
        cnt += 1.0f;
    }
    if (cur >= 0) {
        atomicAdd(&psum[cur * DD + j], s);
        atomicMax(&pmax[cur * DD + j], fenc(m));
        if (j == 0) atomicAdd(&pcnt[cur], cnt);
    }
}

// ---------------- MLP head ----------------
__global__ void k_mlp(const float* __restrict__ Wm1, const float* __restrict__ bm1,
                      const float* __restrict__ Wm2, const float* __restrict__ bm2,
                      const float* __restrict__ psum, const unsigned* __restrict__ pmax,
                      const float* __restrict__ pcnt, float* __restrict__ out) {
    int g = threadIdx.x;
    if (g >= NG) return;
    float cnt = pcnt[g];
    float inv = 1.0f / fmaxf(cnt, 1.0f);
    float hid[8];
    #pragma unroll
    for (int h = 0; h < 8; h++) hid[h] = bm1[h];
    for (int j = 0; j < DD; j++) {
        float mean = psum[g * DD + j] * inv;
        #pragma unroll
        for (int h = 0; h < 8; h++) hid[h] += mean * Wm1[j * 8 + h];
    }
    for (int j = 0; j < DD; j++) {
        float mx = (cnt > 0.0f) ? fdec(pmax[g * DD + j]) : 0.0f;
        #pragma unroll
        for (int h = 0; h < 8; h++) hid[h] += mx * Wm1[(DD + j) * 8 + h];
    }
    #pragma unroll
    for (int h = 0; h < 8; h++) hid[h] = fmaxf(hid[h], 0.0f);
    #pragma unroll
    for (int c = 0; c < 2; c++) {
        float o = bm2[c];
        #pragma unroll
        for (int h = 0; h < 8; h++) o += hid[h] * Wm2[h * 2 + c];
        out[g * 2 + c] = o;
    }
}

// ---------------- driver ----------------
extern "C" void kernel_launch(void* const* d_in, const int* in_sizes, int n_in,
                              void* d_out, int out_size) {
    const float* x     = (const float*)d_in[0];
    const int*   ei    = (const int*)d_in[1];
    const float* ea    = (const float*)d_in[2];
    const int*   batch = (const int*)d_in[3];
    const float* W1A = (const float*)d_in[4];
    const float* b1A = (const float*)d_in[5];
    const float* W1B = (const float*)d_in[6];
    const float* b1B = (const float*)d_in[7];
    const float* W1C = (const float*)d_in[8];
    const float* b1C = (const float*)d_in[9];
    const float* W1D = (const float*)d_in[10];
    const float* b1D = (const float*)d_in[11];
    const float* W2  = (const float*)d_in[12];
    const float* b2  = (const float*)d_in[13];
    const float* W3  = (const float*)d_in[14];
    const float* b3  = (const float*)d_in[15];
    const float* Wm1 = (const float*)d_in[16];
    const float* bm1 = (const float*)d_in[17];
    const float* Wm2 = (const float*)d_in[18];
    const float* bm2 = (const float*)d_in[19];
    float* out = (float*)d_out;

    float *dis, *csr_nu, *Y3, *Wt1, *Wt2, *Wt3, *psum, *pcnt;
    int *cursor, *rowstart, *bsum, *csr_src;
    float4* csr_n4;
    unsigned* pmax;
    __half *xh, *zh, *Hh, *M2h, *Y2h, *M3h;
    cudaGetSymbolAddress((void**)&dis,      g_dis);
    cudaGetSymbolAddress((void**)&cursor,   g_cursor);
    cudaGetSymbolAddress((void**)&rowstart, g_rowstart);
    cudaGetSymbolAddress((void**)&bsum,     g_bsum);
    cudaGetSymbolAddress((void**)&csr_src,  g_csr_src);
    cudaGetSymbolAddress((void**)&csr_n4,   g_csr_n4);
    cudaGetSymbolAddress((void**)&csr_nu,   g_csr_nu);
    cudaGetSymbolAddress((void**)&xh,       g_xh);
    cudaGetSymbolAddress((void**)&zh,       g_zh);
    cudaGetSymbolAddress((void**)&Hh,       g_Hh);
    cudaGetSymbolAddress((void**)&M2h,      g_M2h);
    cudaGetSymbolAddress((void**)&Y2h,      g_Y2h);
    cudaGetSymbolAddress((void**)&M3h,      g_M3h);
    cudaGetSymbolAddress((void**)&Y3,       g_Y3);
    cudaGetSymbolAddress((void**)&Wt1,      g_Wt1);
    cudaGetSymbolAddress((void**)&Wt2,      g_Wt2);
    cudaGetSymbolAddress((void**)&Wt3,      g_Wt3);
    cudaGetSymbolAddress((void**)&psum,     g_psum);
    cudaGetSymbolAddress((void**)&pmax,     g_pmax);
    cudaGetSymbolAddress((void**)&pcnt,     g_pcnt);

    cudaFuncSetAttribute(k_gemm_g, cudaFuncAttributeMaxDynamicSharedMemorySize, SMT);
    cudaFuncSetAttribute(k_gemm_c1, cudaFuncAttributeMaxDynamicSharedMemorySize, SMT);

    const int NB = (NN + 1023) / 1024;
    const int MT = (NN + 127) / 128;   // 391
    const int TRN = 4 * DD * DD + 4 * DD * 2 * DD + 2 * DD * DD;  // 229376

    // 0. prep: transposes + x->fp16
    k_tr_all<<<(TRN + 255) / 256, 256>>>(W1A, W1B, W1C, W1D, W2, W3, Wt1, Wt2, Wt3);
    k_x2h<<<(NN * 16 + 255) / 256, 256>>>((const float4*)x, (uint4*)xh);

    // 1. degrees + CSR
    k_init<<<(5 * NN + 255) / 256, 256>>>(dis, cursor);
    k_deg_edges<<<(NE + 255) / 256, 256>>>(ei, ea, dis);
    k_scan_block<<<NB, 1024>>>(dis, rowstart, bsum);
    k_scan_top<<<1, 32>>>(bsum, NB);
    k_scan_add<<<NB, 1024>>>(rowstart, bsum);
    k_rsqrt<<<(5 * NN + 255) / 256, 256>>>(dis);
    k_csr_fill<<<(NE + 255) / 256, 256>>>(ei, ea, dis, rowstart, cursor,
                                          csr_src, csr_n4, csr_nu);

    // 2. conv1 aggregation of x:  z_k = S_k x  (fp16 in/out, fp32 accum)
    k_gather_z_h<<<(NN * 32 + 255) / 256, 256>>>(
        (const uint2*)xh, dis, rowstart, csr_src, csr_n4, (uint2*)zh);

    // 3. conv1 fused GEMMs
    k_gemm_c1<<<dim3(4, MT), 256, SMT>>>(zh, Wt1, b1A, b1B, b1C, b1D, Hh, NN);

    // 4. conv2: M2 = H @ W2, then aggregate
    k_gemm_g<<<dim3(2, MT), 256, SMT>>>(Hh, 4 * DD, nullptr, Wt2, M2h, 2 * DD, NN, 4 * DD, 0);
    k_gather_u_h<256, 0><<<(NN * 32 + 255) / 256, 256>>>(
        M2h, dis, rowstart, csr_src, csr_nu, (void*)Y2h);

    // 5. conv3: M3 = relu(Y2 + b2) @ W3, then aggregate (fp32 out for pooling)
    k_gemm_g<<<dim3(1, MT), 256, SMT>>>(Y2h, 2 * DD, b2, Wt3, M3h, DD, NN, 2 * DD, 0);
    k_gather_u_h<128, 1><<<(NN * 32 + 255) / 256, 256>>>(
        M3h, dis, rowstart, csr_src, csr_nu, (void*)Y3);

    // 6. pooling (b3 folded in) + MLP head
    k_pool_init<<<(NG * DD + 255) / 256, 256>>>(psum, pmax, pcnt);
    k_pool<<<(NN + POOL_CHUNK - 1) / POOL_CHUNK, DD>>>(Y3, b3, batch, psum, pmax, pcnt);
    k_mlp<<<1, 64>>>(Wm1, bm1, Wm2, bm2, psum, pmax, pcnt, out);
}